// round 1
// baseline (speedup 1.0000x reference)
#include <cuda_runtime.h>
#include <math.h>

#define Bv 4
#define Lv 8192
#define Dm 1024
#define Hh 16
#define DKv 64
#define Uv 50
#define BLv (Bv*Lv)            // 32768
#define SPLIT 4
#define LSPL (Lv/SPLIT)        // 2048
#define TK 32

typedef unsigned long long u64;

// ---------------- scratch (device globals; no allocations allowed) ----------
__device__ float g_Q[BLv*Dm];          // 128 MB
__device__ float g_K[BLv*Dm];          // 128 MB
__device__ float g_V[BLv*Dm];          // 128 MB
__device__ float g_M[Bv*Hh*Lv];
__device__ int   g_top[Bv*Hh*Uv];
__device__ float g_pm[Bv*Hh*SPLIT*Uv];
__device__ float g_pl[Bv*Hh*SPLIT*Uv];
__device__ float g_pctx[Bv*Hh*SPLIT*Uv*DKv];
__device__ float g_ctx[Bv*Hh*Uv*DKv];
__device__ float g_vsum[Bv*Dm];
__device__ float g_base[Bv*Dm];

// ---------------- f32x2 helpers (FFMA2 path, sm_103a) -----------------------
__device__ __forceinline__ u64 pack2(float x, float y){
    u64 r; asm("mov.b64 %0, {%1, %2};" : "=l"(r) : "f"(x), "f"(y)); return r;
}
__device__ __forceinline__ float2 unpack2(u64 v){
    float x, y; asm("mov.b64 {%0, %1}, %2;" : "=f"(x), "=f"(y) : "l"(v));
    return make_float2(x, y);
}
__device__ __forceinline__ void ffma2(u64 &acc, u64 a, u64 b){
    asm("fma.rn.f32x2 %0, %1, %2, %0;" : "+l"(acc) : "l"(a), "l"(b));
}

// ---------------- kernel 0: zero vsum ---------------------------------------
__global__ void zero_vsum_kernel(){
    int i = blockIdx.x*blockDim.x + threadIdx.x;
    if (i < Bv*Dm) g_vsum[i] = 0.0f;
}

// ---------------- kernel 1: fused Q/K/V GEMM (fp32, FFMA2) ------------------
// out[m][n] = sum_k X[m][k]*W[n][k] + bias[n]
#define BM 128
#define BN 128
#define BK 16
__global__ __launch_bounds__(256, 2) void qkv_gemm_kernel(
    const float* __restrict__ X,
    const float* __restrict__ Wq, const float* __restrict__ bq,
    const float* __restrict__ Wk, const float* __restrict__ bk,
    const float* __restrict__ Wv, const float* __restrict__ bv)
{
    const float* W; const float* bias; float* out;
    if (blockIdx.z == 0)      { W = Wq; bias = bq; out = g_Q; }
    else if (blockIdx.z == 1) { W = Wk; bias = bk; out = g_K; }
    else                      { W = Wv; bias = bv; out = g_V; }

    __shared__ u64   As2[BK][BM];   // duplicated (a,a) pairs, 16 KB
    __shared__ float Bs[BK][BN];    // 8 KB

    const int m0 = blockIdx.x * BM;
    const int n0 = blockIdx.y * BN;
    const int t  = threadIdx.x;
    const int tx = t & 15;          // 0..15 (n)
    const int ty = t >> 4;          // 0..15 (m)

    const int arow = t >> 1;        // 0..127
    const int acol = (t & 1) * 8;   // 0 or 8
    const int brow = t >> 1;
    const int bcol = (t & 1) * 8;

    u64 acc[8][4];
    #pragma unroll
    for (int i = 0; i < 8; ++i)
        #pragma unroll
        for (int j = 0; j < 4; ++j) acc[i][j] = 0ULL;

    for (int k0 = 0; k0 < Dm; k0 += BK) {
        // load A tile (dup-packed) and B tile (transposed W)
        float4 a0 = *reinterpret_cast<const float4*>(&X[(size_t)(m0+arow)*Dm + k0 + acol]);
        float4 a1 = *reinterpret_cast<const float4*>(&X[(size_t)(m0+arow)*Dm + k0 + acol + 4]);
        float4 b0 = *reinterpret_cast<const float4*>(&W[(size_t)(n0+brow)*Dm + k0 + bcol]);
        float4 b1 = *reinterpret_cast<const float4*>(&W[(size_t)(n0+brow)*Dm + k0 + bcol + 4]);

        As2[acol+0][arow] = pack2(a0.x, a0.x);
        As2[acol+1][arow] = pack2(a0.y, a0.y);
        As2[acol+2][arow] = pack2(a0.z, a0.z);
        As2[acol+3][arow] = pack2(a0.w, a0.w);
        As2[acol+4][arow] = pack2(a1.x, a1.x);
        As2[acol+5][arow] = pack2(a1.y, a1.y);
        As2[acol+6][arow] = pack2(a1.z, a1.z);
        As2[acol+7][arow] = pack2(a1.w, a1.w);

        Bs[bcol+0][brow] = b0.x;  Bs[bcol+1][brow] = b0.y;
        Bs[bcol+2][brow] = b0.z;  Bs[bcol+3][brow] = b0.w;
        Bs[bcol+4][brow] = b1.x;  Bs[bcol+5][brow] = b1.y;
        Bs[bcol+6][brow] = b1.z;  Bs[bcol+7][brow] = b1.w;

        __syncthreads();

        #pragma unroll
        for (int kk = 0; kk < BK; ++kk) {
            u64 a[8], bb[4];
            #pragma unroll
            for (int ii = 0; ii < 4; ++ii) {
                ulonglong2 tmp = *reinterpret_cast<const ulonglong2*>(&As2[kk][ty*8 + ii*2]);
                a[ii*2] = tmp.x; a[ii*2+1] = tmp.y;
            }
            {
                ulonglong2 t0 = *reinterpret_cast<const ulonglong2*>(&Bs[kk][tx*8]);
                ulonglong2 t1 = *reinterpret_cast<const ulonglong2*>(&Bs[kk][tx*8 + 4]);
                bb[0] = t0.x; bb[1] = t0.y; bb[2] = t1.x; bb[3] = t1.y;
            }
            #pragma unroll
            for (int i = 0; i < 8; ++i)
                #pragma unroll
                for (int j = 0; j < 4; ++j)
                    ffma2(acc[i][j], a[i], bb[j]);
        }
        __syncthreads();
    }

    const int ncol = n0 + tx*8;
    float bvals[8];
    #pragma unroll
    for (int j = 0; j < 8; ++j) bvals[j] = bias[ncol + j];

    #pragma unroll
    for (int i = 0; i < 8; ++i) {
        float* orow = out + (size_t)(m0 + ty*8 + i)*Dm + ncol;
        #pragma unroll
        for (int jp = 0; jp < 4; ++jp) {
            float2 v = unpack2(acc[i][jp]);
            v.x += bvals[2*jp];
            v.y += bvals[2*jp+1];
            *reinterpret_cast<float2*>(orow + 2*jp) = v;
        }
    }
}

// ---------------- kernel 2: sparsity measure M -------------------------------
// M[b,h,l] = max_u(q·k_u) - mean_u(q·k_u)   (unscaled; monotone under *scale)
__global__ __launch_bounds__(128) void m_kernel(const int* __restrict__ idx_k){
    const int b = blockIdx.z, h = blockIdx.y;
    const int l0 = blockIdx.x * 128;
    __shared__ float Ks[Uv*DKv];      // 12800 B
    __shared__ float Qs[128*65];      // 33280 B (pad 65 avoids bank conflicts)
    const int t = threadIdx.x;

    for (int i = t; i < Uv*DKv; i += 128) {
        int u = i >> 6, d = i & 63;
        Ks[i] = g_K[(size_t)(b*Lv + idx_k[u])*Dm + h*DKv + d];
    }
    for (int i = t; i < 128*DKv; i += 128) {
        int r = i >> 6, d = i & 63;
        Qs[r*65 + d] = g_Q[(size_t)(b*Lv + l0 + r)*Dm + h*DKv + d];
    }
    __syncthreads();

    float acc[Uv];
    #pragma unroll
    for (int u = 0; u < Uv; ++u) acc[u] = 0.0f;

    for (int d = 0; d < DKv; ++d) {
        float qd = Qs[t*65 + d];
        #pragma unroll
        for (int u = 0; u < Uv; ++u) acc[u] += qd * Ks[u*DKv + d];
    }
    float mx = -1e30f, sm = 0.0f;
    #pragma unroll
    for (int u = 0; u < Uv; ++u) { mx = fmaxf(mx, acc[u]); sm += acc[u]; }
    g_M[(size_t)(b*Hh + h)*Lv + l0 + t] = mx - sm*(1.0f/Uv);
}

// ---------------- kernel 3: top-k (k=50 of 8192) per (b,h) -------------------
__global__ __launch_bounds__(256) void topk_kernel(){
    const int bh = blockIdx.x;
    __shared__ float vals[Lv];     // 32 KB
    __shared__ float rv[256];
    __shared__ int   ri[256];
    const int t = threadIdx.x;

    for (int i = t; i < Lv; i += 256) vals[i] = g_M[(size_t)bh*Lv + i];
    __syncthreads();

    for (int it = 0; it < Uv; ++it) {
        float best = -1e30f; int bi = Lv;
        for (int i = t; i < Lv; i += 256) {
            float v = vals[i];
            if (v > best || (v == best && i < bi)) { best = v; bi = i; }
        }
        rv[t] = best; ri[t] = bi;
        __syncthreads();
        for (int s = 128; s > 0; s >>= 1) {
            if (t < s) {
                if (rv[t+s] > rv[t] || (rv[t+s] == rv[t] && ri[t+s] < ri[t])) {
                    rv[t] = rv[t+s]; ri[t] = ri[t+s];
                }
            }
            __syncthreads();
        }
        if (t == 0) { g_top[bh*Uv + it] = ri[0]; vals[ri[0]] = -1e30f; }
        __syncthreads();
    }
}

// ---------------- kernel 4: V column sums (for mean) -------------------------
__global__ void vsum_kernel(){
    const int b = blockIdx.z;
    const int d = blockIdx.x*128 + threadIdx.x;
    const int c = blockIdx.y;
    float s = 0.0f;
    const int lbeg = c*256, lend = lbeg + 256;
    for (int l = lbeg; l < lend; ++l) s += g_V[(size_t)(b*Lv + l)*Dm + d];
    atomicAdd(&g_vsum[b*Dm + d], s);
}

// ---------------- kernel 5: flash attention for top queries (split-K) --------
__global__ __launch_bounds__(512) void attn_partial_kernel(){
    const int bh = blockIdx.x;
    const int sp = blockIdx.y;
    const int b = bh / Hh, h = bh % Hh;
    const int t = threadIdx.x;

    __shared__ float Qs[Uv][DKv];        // 12800
    __shared__ float Ks[TK][65];         // 8320
    __shared__ float Vs[TK][65];         // 8320
    __shared__ float Ps[Uv][33];         // 6600
    __shared__ float m_s[Uv], l_s[Uv], c_s[Uv];

    for (int i = t; i < Uv*DKv; i += 512) {
        int q = i >> 6, d = i & 63;
        int l = g_top[bh*Uv + q];
        Qs[q][d] = g_Q[(size_t)(b*Lv + l)*Dm + h*DKv + d];
    }
    if (t < Uv) { m_s[t] = -1e30f; l_s[t] = 0.0f; }

    float ctx[7];
    #pragma unroll
    for (int j = 0; j < 7; ++j) ctx[j] = 0.0f;
    const int d = t & 63;
    const int qb = t >> 6;   // 0..7

    __syncthreads();

    for (int l0 = sp*LSPL; l0 < (sp+1)*LSPL; l0 += TK) {
        for (int i = t; i < TK*DKv; i += 512) {
            int kk = i >> 6, dd = i & 63;
            size_t g = (size_t)(b*Lv + l0 + kk)*Dm + h*DKv + dd;
            Ks[kk][dd] = g_K[g];
            Vs[kk][dd] = g_V[g];
        }
        __syncthreads();

        if (t < 400) {                       // 50 q * 8 key-groups
            const int q = t >> 3, kg = t & 7;
            float a0 = 0.f, a1 = 0.f, a2 = 0.f, a3 = 0.f;
            for (int dd = 0; dd < DKv; ++dd) {
                float qv = Qs[q][dd];
                a0 += qv * Ks[kg][dd];
                a1 += qv * Ks[kg+8][dd];
                a2 += qv * Ks[kg+16][dd];
                a3 += qv * Ks[kg+24][dd];
            }
            Ps[q][kg]    = a0 * 0.125f;
            Ps[q][kg+8]  = a1 * 0.125f;
            Ps[q][kg+16] = a2 * 0.125f;
            Ps[q][kg+24] = a3 * 0.125f;
        }
        __syncthreads();

        if (t < Uv) {
            float tm = -1e30f;
            #pragma unroll
            for (int k = 0; k < TK; ++k) tm = fmaxf(tm, Ps[t][k]);
            float nm = fmaxf(m_s[t], tm);
            float cc = __expf(m_s[t] - nm);
            float ls = l_s[t]*cc;
            #pragma unroll
            for (int k = 0; k < TK; ++k) {
                float p = __expf(Ps[t][k] - nm);
                Ps[t][k] = p;
                ls += p;
            }
            m_s[t] = nm; l_s[t] = ls; c_s[t] = cc;
        }
        __syncthreads();

        #pragma unroll
        for (int j = 0; j < 7; ++j) {
            int q = qb + 8*j;
            if (q < Uv) {
                float a = ctx[j] * c_s[q];
                #pragma unroll
                for (int k = 0; k < TK; ++k) a += Ps[q][k] * Vs[k][d];
                ctx[j] = a;
            }
        }
        __syncthreads();
    }

    #pragma unroll
    for (int j = 0; j < 7; ++j) {
        int q = qb + 8*j;
        if (q < Uv)
            g_pctx[(size_t)((bh*SPLIT + sp)*Uv + q)*DKv + d] = ctx[j];
    }
    if (t < Uv) {
        g_pm[(bh*SPLIT + sp)*Uv + t] = m_s[t];
        g_pl[(bh*SPLIT + sp)*Uv + t] = l_s[t];
    }
}

// ---------------- kernel 6: combine split partials ---------------------------
__global__ __launch_bounds__(64) void attn_combine_kernel(){
    const int i = blockIdx.x;          // bh*U + q
    const int q = i % Uv, bh = i / Uv;
    __shared__ float w[SPLIT];
    __shared__ float inv;
    if (threadIdx.x == 0) {
        float M = -1e30f;
        for (int s = 0; s < SPLIT; ++s) M = fmaxf(M, g_pm[(bh*SPLIT+s)*Uv + q]);
        float tot = 0.f;
        for (int s = 0; s < SPLIT; ++s) {
            float e = __expf(g_pm[(bh*SPLIT+s)*Uv + q] - M);
            w[s] = e;
            tot += g_pl[(bh*SPLIT+s)*Uv + q] * e;
        }
        inv = 1.0f / tot;
    }
    __syncthreads();
    const int d = threadIdx.x;
    float c = 0.f;
    for (int s = 0; s < SPLIT; ++s)
        c += g_pctx[(size_t)((bh*SPLIT+s)*Uv + q)*DKv + d] * w[s];
    g_ctx[(size_t)i*DKv + d] = c * inv;
}

// ---------------- kernel 7: base output row per batch ------------------------
// base[b][j] = vmean[b]·Wo[j] + bo[j]
__global__ __launch_bounds__(256) void base_kernel(const float* __restrict__ Wo,
                                                   const float* __restrict__ bo){
    const int b = blockIdx.y;
    const int warp = threadIdx.x >> 5, lane = threadIdx.x & 31;
    const int j = blockIdx.x*8 + warp;
    float s = 0.f;
    for (int d0 = lane; d0 < Dm; d0 += 32)
        s += g_vsum[b*Dm + d0] * Wo[(size_t)j*Dm + d0];
    #pragma unroll
    for (int o = 16; o; o >>= 1) s += __shfl_down_sync(0xffffffffu, s, o);
    if (lane == 0) g_base[b*Dm + j] = s*(1.0f/Lv) + bo[j];
}

// ---------------- kernel 8: broadcast base rows into output -------------------
__global__ void fill_kernel(float* __restrict__ out){
    const int i = blockIdx.x*blockDim.x + threadIdx.x;   // i < BL*D/4
    const int b  = i >> 21;                              // (i*4) >> 23
    const int j4 = i & 255;                              // ((i*4)&1023)/4
    float4 v = *reinterpret_cast<const float4*>(&g_base[b*Dm + j4*4]);
    reinterpret_cast<float4*>(out)[i] = v;
}

// ---------------- kernel 9: rank-64 corrections for top rows ------------------
__global__ __launch_bounds__(256) void corr_kernel(const float* __restrict__ Wo,
                                                   float* __restrict__ out){
    const int i = blockIdx.x;             // bh*U + u
    const int bh = i / Uv;
    const int b = bh / Hh, h = bh % Hh;
    const int l = g_top[i];
    __shared__ float delta[DKv];
    const int t = threadIdx.x;
    if (t < DKv)
        delta[t] = g_ctx[(size_t)i*DKv + t] - g_vsum[b*Dm + h*DKv + t]*(1.0f/Lv);
    __syncthreads();
    for (int j = t; j < Dm; j += 256) {
        const float4* wr = reinterpret_cast<const float4*>(Wo + (size_t)j*Dm + h*DKv);
        float s = 0.f;
        #pragma unroll
        for (int dd = 0; dd < 16; ++dd) {
            float4 wv = wr[dd];
            s += delta[dd*4+0]*wv.x + delta[dd*4+1]*wv.y
               + delta[dd*4+2]*wv.z + delta[dd*4+3]*wv.w;
        }
        atomicAdd(&out[(size_t)(b*Lv + l)*Dm + j], s);
    }
}

// ---------------- launch ------------------------------------------------------
extern "C" void kernel_launch(void* const* d_in, const int* in_sizes, int n_in,
                              void* d_out, int out_size)
{
    const float* x    = (const float*)d_in[0];
    const float* Wq   = (const float*)d_in[1];
    const float* bq   = (const float*)d_in[2];
    const float* Wk   = (const float*)d_in[3];
    const float* bk   = (const float*)d_in[4];
    const float* Wv   = (const float*)d_in[5];
    const float* bv   = (const float*)d_in[6];
    const float* Wo   = (const float*)d_in[7];
    const float* bo   = (const float*)d_in[8];
    const int*   idxk = (const int*)d_in[9];
    float* out = (float*)d_out;

    zero_vsum_kernel<<<(Bv*Dm)/256, 256>>>();
    qkv_gemm_kernel<<<dim3(BLv/BM, Dm/BN, 3), 256>>>(x, Wq, bq, Wk, bk, Wv, bv);
    m_kernel<<<dim3(Lv/128, Hh, Bv), 128>>>(idxk);
    vsum_kernel<<<dim3(Dm/128, Lv/256, Bv), 128>>>();
    topk_kernel<<<Bv*Hh, 256>>>();
    attn_partial_kernel<<<dim3(Bv*Hh, SPLIT), 512>>>();
    attn_combine_kernel<<<Bv*Hh*Uv, 64>>>();
    base_kernel<<<dim3(Dm/8, Bv), 256>>>(Wo, bo);
    fill_kernel<<<(BLv*Dm/4)/256, 256>>>(out);
    corr_kernel<<<Bv*Hh*Uv, 256>>>(Wo, out);
}

// round 3
// speedup vs baseline: 1.3076x; 1.3076x over previous
#include <cuda_runtime.h>
#include <math.h>
#include <stdint.h>

#define Bv 4
#define Lv 8192
#define Dm 1024
#define Hh 16
#define DKv 64
#define Uv 50
#define BLv (Bv*Lv)            // 32768
#define SPLIT 4
#define LSPL (Lv/SPLIT)        // 2048
#define TK 32

// ---------------- scratch (device globals; no allocations allowed) ----------
__device__ float g_Q[BLv*Dm];          // 128 MB
__device__ float g_K[BLv*Dm];          // 128 MB
__device__ float g_V[BLv*Dm];          // 128 MB
__device__ float g_M[Bv*Hh*Lv];
__device__ int   g_top[Bv*Hh*Uv];
__device__ float g_pm[Bv*Hh*SPLIT*Uv];
__device__ float g_pl[Bv*Hh*SPLIT*Uv];
__device__ float g_pctx[Bv*Hh*SPLIT*Uv*DKv];
__device__ float g_ctx[Bv*Hh*Uv*DKv];
__device__ float g_vsum[Bv*Dm];
__device__ float g_base[Bv*Dm];

// ---------------- tf32 helpers ------------------------------------------------
__device__ __forceinline__ void tf32_split(float x, uint32_t &hi, uint32_t &lo){
    asm("cvt.rna.tf32.f32 %0, %1;" : "=r"(hi) : "f"(x));
    float res = x - __uint_as_float(hi);
    asm("cvt.rna.tf32.f32 %0, %1;" : "=r"(lo) : "f"(res));
}

__device__ __forceinline__ void mma8(float* c, const uint32_t* a, const uint32_t* b){
    asm volatile(
        "mma.sync.aligned.m16n8k8.row.col.f32.tf32.tf32.f32 "
        "{%0,%1,%2,%3}, {%4,%5,%6,%7}, {%8,%9}, {%0,%1,%2,%3};"
        : "+f"(c[0]), "+f"(c[1]), "+f"(c[2]), "+f"(c[3])
        : "r"(a[0]), "r"(a[1]), "r"(a[2]), "r"(a[3]), "r"(b[0]), "r"(b[1]));
}

// ======================= kernel 1: QKV GEMM via mma.sync 3xTF32 ==============
// out[m][n] = sum_k X[m,k]*W[n,k] + bias[n]
// Tile 128(M) x 128(N) x 8(K). 256 thr = 8 warps (2 M x 4 N), warp = 64x32.
// Smem stores operands in mma-fragment order:
//   A_hi/lo: [8 frag][32 lane][4 slots]   (frag = mtile)
//   B_hi/lo: [16 frag][32 lane][2 slots]  (frag = ntile)
// Stage = 4096 floats (16 KB); 2 stages ping-pong (32 KB static).
#define STG 4096
#define AHI 0
#define ALO 1024
#define BHI 2048
#define BLO 3072

__global__ __launch_bounds__(256,1) void qkv_mma_kernel(
    const float* __restrict__ X,
    const float* __restrict__ Wq, const float* __restrict__ bq,
    const float* __restrict__ Wk, const float* __restrict__ bk,
    const float* __restrict__ Wv, const float* __restrict__ bv)
{
    const float* W; const float* bias; float* out;
    if (blockIdx.z == 0)      { W = Wq; bias = bq; out = g_Q; }
    else if (blockIdx.z == 1) { W = Wk; bias = bk; out = g_K; }
    else                      { W = Wv; bias = bv; out = g_V; }

    const int n0 = blockIdx.x * 128;
    const int m0 = blockIdx.y * 128;

    __shared__ float sm[2][STG];

    const int t = threadIdx.x;
    const int lane = t & 31;
    const int wid  = t >> 5;
    const int warp_m = wid & 1;
    const int warp_n = wid >> 1;

    // writer task coordinates
    const int a_m = (wid << 4) + (lane >> 2);        // A frag = wid (mtile)
    const int a_k = lane & 3;
    const int b_nA = (wid << 3) + (lane >> 2);       // B frag = wid
    const int b_nB = ((wid + 8) << 3) + (lane >> 2); // B frag = wid+8
    const int b_k = lane & 3;

    const float* Ar0 = X + (size_t)(m0 + a_m)*Dm + a_k;
    const float* Ar1 = Ar0 + 8*Dm;
    const float* Br0 = W + (size_t)(n0 + b_nA)*Dm + b_k;
    const float* Br1 = W + (size_t)(n0 + b_nB)*Dm + b_k;

    float acc[4][4][4];
    #pragma unroll
    for (int i = 0; i < 4; ++i)
        #pragma unroll
        for (int j = 0; j < 4; ++j)
            #pragma unroll
            for (int r = 0; r < 4; ++r) acc[i][j][r] = 0.0f;

    float av[4], bva[2], bvb[2];

    // prologue: chunk 0
    av[0] = Ar0[0]; av[1] = Ar1[0]; av[2] = Ar0[4]; av[3] = Ar1[4];
    bva[0] = Br0[0]; bva[1] = Br0[4];
    bvb[0] = Br1[0]; bvb[1] = Br1[4];
    {
        uint32_t h[4], l[4];
        #pragma unroll
        for (int i = 0; i < 4; ++i) tf32_split(av[i], h[i], l[i]);
        *reinterpret_cast<uint4*>(&sm[0][AHI + (wid*32 + lane)*4]) = make_uint4(h[0],h[1],h[2],h[3]);
        *reinterpret_cast<uint4*>(&sm[0][ALO + (wid*32 + lane)*4]) = make_uint4(l[0],l[1],l[2],l[3]);
        uint32_t bh0,bl0,bh1,bl1;
        tf32_split(bva[0], bh0, bl0); tf32_split(bva[1], bh1, bl1);
        *reinterpret_cast<uint2*>(&sm[0][BHI + (wid*32 + lane)*2]) = make_uint2(bh0, bh1);
        *reinterpret_cast<uint2*>(&sm[0][BLO + (wid*32 + lane)*2]) = make_uint2(bl0, bl1);
        tf32_split(bvb[0], bh0, bl0); tf32_split(bvb[1], bh1, bl1);
        *reinterpret_cast<uint2*>(&sm[0][BHI + ((wid+8)*32 + lane)*2]) = make_uint2(bh0, bh1);
        *reinterpret_cast<uint2*>(&sm[0][BLO + ((wid+8)*32 + lane)*2]) = make_uint2(bl0, bl1);
    }
    __syncthreads();

    #pragma unroll 1
    for (int c = 0; c < Dm/8; ++c) {
        const int cur = c & 1;

        // prefetch chunk c+1 (global -> regs), overlapped with MMA below
        if (c < Dm/8 - 1) {
            const int k0 = (c + 1) * 8;
            av[0] = Ar0[k0]; av[1] = Ar1[k0]; av[2] = Ar0[k0+4]; av[3] = Ar1[k0+4];
            bva[0] = Br0[k0]; bva[1] = Br0[k0+4];
            bvb[0] = Br1[k0]; bvb[1] = Br1[k0+4];
        }

        // fragment loads from stage cur
        const float* S = sm[cur];
        uint32_t ah[4][4], al[4][4], bh[4][2], bl[4][2];
        #pragma unroll
        for (int im = 0; im < 4; ++im) {
            const int fa = warp_m*4 + im;
            uint4 h = *reinterpret_cast<const uint4*>(&S[AHI + (fa*32 + lane)*4]);
            uint4 l = *reinterpret_cast<const uint4*>(&S[ALO + (fa*32 + lane)*4]);
            ah[im][0]=h.x; ah[im][1]=h.y; ah[im][2]=h.z; ah[im][3]=h.w;
            al[im][0]=l.x; al[im][1]=l.y; al[im][2]=l.z; al[im][3]=l.w;
        }
        #pragma unroll
        for (int in = 0; in < 4; ++in) {
            const int fb = warp_n*4 + in;
            uint2 h = *reinterpret_cast<const uint2*>(&S[BHI + (fb*32 + lane)*2]);
            uint2 l = *reinterpret_cast<const uint2*>(&S[BLO + (fb*32 + lane)*2]);
            bh[in][0]=h.x; bh[in][1]=h.y;
            bl[in][0]=l.x; bl[in][1]=l.y;
        }

        // 3xTF32: corrections first, then main product
        #pragma unroll
        for (int im = 0; im < 4; ++im)
            #pragma unroll
            for (int in = 0; in < 4; ++in) {
                mma8(acc[im][in], ah[im], bl[in]);
                mma8(acc[im][in], al[im], bh[in]);
                mma8(acc[im][in], ah[im], bh[in]);
            }

        // convert + store chunk c+1 into the other stage
        if (c < Dm/8 - 1) {
            float* D = sm[cur ^ 1];
            uint32_t h[4], l[4];
            #pragma unroll
            for (int i = 0; i < 4; ++i) tf32_split(av[i], h[i], l[i]);
            *reinterpret_cast<uint4*>(&D[AHI + (wid*32 + lane)*4]) = make_uint4(h[0],h[1],h[2],h[3]);
            *reinterpret_cast<uint4*>(&D[ALO + (wid*32 + lane)*4]) = make_uint4(l[0],l[1],l[2],l[3]);
            uint32_t bh0,bl0,bh1,bl1;
            tf32_split(bva[0], bh0, bl0); tf32_split(bva[1], bh1, bl1);
            *reinterpret_cast<uint2*>(&D[BHI + (wid*32 + lane)*2]) = make_uint2(bh0, bh1);
            *reinterpret_cast<uint2*>(&D[BLO + (wid*32 + lane)*2]) = make_uint2(bl0, bl1);
            tf32_split(bvb[0], bh0, bl0); tf32_split(bvb[1], bh1, bl1);
            *reinterpret_cast<uint2*>(&D[BHI + ((wid+8)*32 + lane)*2]) = make_uint2(bh0, bh1);
            *reinterpret_cast<uint2*>(&D[BLO + ((wid+8)*32 + lane)*2]) = make_uint2(bl0, bl1);
        }
        __syncthreads();
    }

    // ---- epilogue: acc + bias -> gmem ----
    #pragma unroll
    for (int im = 0; im < 4; ++im) {
        const int m = m0 + warp_m*64 + im*16 + (lane >> 2);
        #pragma unroll
        for (int in = 0; in < 4; ++in) {
            const int n = n0 + warp_n*32 + in*8 + (lane & 3)*2;
            const float b0 = __ldg(&bias[n]);
            const float b1 = __ldg(&bias[n+1]);
            float2 v0 = make_float2(acc[im][in][0] + b0, acc[im][in][1] + b1);
            float2 v1 = make_float2(acc[im][in][2] + b0, acc[im][in][3] + b1);
            *reinterpret_cast<float2*>(&out[(size_t)m*Dm + n])     = v0;
            *reinterpret_cast<float2*>(&out[(size_t)(m+8)*Dm + n]) = v1;
        }
    }
}

// ---------------- kernel 0: zero vsum ---------------------------------------
__global__ void zero_vsum_kernel(){
    int i = blockIdx.x*blockDim.x + threadIdx.x;
    if (i < Bv*Dm) g_vsum[i] = 0.0f;
}

// ---------------- kernel 2: sparsity measure M -------------------------------
__global__ __launch_bounds__(128) void m_kernel(const int* __restrict__ idx_k){
    const int b = blockIdx.z, h = blockIdx.y;
    const int l0 = blockIdx.x * 128;
    __shared__ float Ks[Uv*DKv];
    __shared__ float Qs[128*65];
    const int t = threadIdx.x;

    for (int i = t; i < Uv*DKv; i += 128) {
        int u = i >> 6, d = i & 63;
        Ks[i] = g_K[(size_t)(b*Lv + idx_k[u])*Dm + h*DKv + d];
    }
    for (int i = t; i < 128*DKv; i += 128) {
        int r = i >> 6, d = i & 63;
        Qs[r*65 + d] = g_Q[(size_t)(b*Lv + l0 + r)*Dm + h*DKv + d];
    }
    __syncthreads();

    float acc[Uv];
    #pragma unroll
    for (int u = 0; u < Uv; ++u) acc[u] = 0.0f;

    for (int d = 0; d < DKv; ++d) {
        float qd = Qs[t*65 + d];
        #pragma unroll
        for (int u = 0; u < Uv; ++u) acc[u] += qd * Ks[u*DKv + d];
    }
    float mx = -1e30f, smv = 0.0f;
    #pragma unroll
    for (int u = 0; u < Uv; ++u) { mx = fmaxf(mx, acc[u]); smv += acc[u]; }
    g_M[(size_t)(b*Hh + h)*Lv + l0 + t] = mx - smv*(1.0f/Uv);
}

// ---------------- kernel 3: top-k (k=50 of 8192) per (b,h) -------------------
__global__ __launch_bounds__(256) void topk_kernel(){
    const int bh = blockIdx.x;
    __shared__ float vals[Lv];
    __shared__ float rv[256];
    __shared__ int   ri[256];
    const int t = threadIdx.x;

    for (int i = t; i < Lv; i += 256) vals[i] = g_M[(size_t)bh*Lv + i];
    __syncthreads();

    for (int it = 0; it < Uv; ++it) {
        float best = -1e30f; int bi = Lv;
        for (int i = t; i < Lv; i += 256) {
            float v = vals[i];
            if (v > best || (v == best && i < bi)) { best = v; bi = i; }
        }
        rv[t] = best; ri[t] = bi;
        __syncthreads();
        for (int s = 128; s > 0; s >>= 1) {
            if (t < s) {
                if (rv[t+s] > rv[t] || (rv[t+s] == rv[t] && ri[t+s] < ri[t])) {
                    rv[t] = rv[t+s]; ri[t] = ri[t+s];
                }
            }
            __syncthreads();
        }
        if (t == 0) { g_top[bh*Uv + it] = ri[0]; vals[ri[0]] = -1e30f; }
        __syncthreads();
    }
}

// ---------------- kernel 4: V column sums (for mean) -------------------------
__global__ void vsum_kernel(){
    const int b = blockIdx.z;
    const int d = blockIdx.x*128 + threadIdx.x;
    const int c = blockIdx.y;
    float s = 0.0f;
    const int lbeg = c*256, lend = lbeg + 256;
    for (int l = lbeg; l < lend; ++l) s += g_V[(size_t)(b*Lv + l)*Dm + d];
    atomicAdd(&g_vsum[b*Dm + d], s);
}

// ---------------- kernel 5: flash attention for top queries (split-K) --------
__global__ __launch_bounds__(512) void attn_partial_kernel(){
    const int bh = blockIdx.x;
    const int sp = blockIdx.y;
    const int b = bh / Hh, h = bh % Hh;
    const int t = threadIdx.x;

    __shared__ float Qs[Uv][DKv];
    __shared__ float Ks[TK][65];
    __shared__ float Vs[TK][65];
    __shared__ float Ps[Uv][33];
    __shared__ float m_s[Uv], l_s[Uv], c_s[Uv];

    for (int i = t; i < Uv*DKv; i += 512) {
        int q = i >> 6, d = i & 63;
        int l = g_top[bh*Uv + q];
        Qs[q][d] = g_Q[(size_t)(b*Lv + l)*Dm + h*DKv + d];
    }
    if (t < Uv) { m_s[t] = -1e30f; l_s[t] = 0.0f; }

    float ctx[7];
    #pragma unroll
    for (int j = 0; j < 7; ++j) ctx[j] = 0.0f;
    const int d = t & 63;
    const int qb = t >> 6;

    __syncthreads();

    for (int l0 = sp*LSPL; l0 < (sp+1)*LSPL; l0 += TK) {
        for (int i = t; i < TK*DKv; i += 512) {
            int kk = i >> 6, dd = i & 63;
            size_t g = (size_t)(b*Lv + l0 + kk)*Dm + h*DKv + dd;
            Ks[kk][dd] = g_K[g];
            Vs[kk][dd] = g_V[g];
        }
        __syncthreads();

        if (t < 400) {
            const int q = t >> 3, kg = t & 7;
            float a0 = 0.f, a1 = 0.f, a2 = 0.f, a3 = 0.f;
            for (int dd = 0; dd < DKv; ++dd) {
                float qv = Qs[q][dd];
                a0 += qv * Ks[kg][dd];
                a1 += qv * Ks[kg+8][dd];
                a2 += qv * Ks[kg+16][dd];
                a3 += qv * Ks[kg+24][dd];
            }
            Ps[q][kg]    = a0 * 0.125f;
            Ps[q][kg+8]  = a1 * 0.125f;
            Ps[q][kg+16] = a2 * 0.125f;
            Ps[q][kg+24] = a3 * 0.125f;
        }
        __syncthreads();

        if (t < Uv) {
            float tm = -1e30f;
            #pragma unroll
            for (int k = 0; k < TK; ++k) tm = fmaxf(tm, Ps[t][k]);
            float nm = fmaxf(m_s[t], tm);
            float cc = __expf(m_s[t] - nm);
            float ls = l_s[t]*cc;
            #pragma unroll
            for (int k = 0; k < TK; ++k) {
                float p = __expf(Ps[t][k] - nm);
                Ps[t][k] = p;
                ls += p;
            }
            m_s[t] = nm; l_s[t] = ls; c_s[t] = cc;
        }
        __syncthreads();

        #pragma unroll
        for (int j = 0; j < 7; ++j) {
            int q = qb + 8*j;
            if (q < Uv) {
                float a = ctx[j] * c_s[q];
                #pragma unroll
                for (int k = 0; k < TK; ++k) a += Ps[q][k] * Vs[k][d];
                ctx[j] = a;
            }
        }
        __syncthreads();
    }

    #pragma unroll
    for (int j = 0; j < 7; ++j) {
        int q = qb + 8*j;
        if (q < Uv)
            g_pctx[(size_t)((bh*SPLIT + sp)*Uv + q)*DKv + d] = ctx[j];
    }
    if (t < Uv) {
        g_pm[(bh*SPLIT + sp)*Uv + t] = m_s[t];
        g_pl[(bh*SPLIT + sp)*Uv + t] = l_s[t];
    }
}

// ---------------- kernel 6: combine split partials ---------------------------
__global__ __launch_bounds__(64) void attn_combine_kernel(){
    const int i = blockIdx.x;
    const int q = i % Uv, bh = i / Uv;
    __shared__ float w[SPLIT];
    __shared__ float inv;
    if (threadIdx.x == 0) {
        float M = -1e30f;
        for (int s = 0; s < SPLIT; ++s) M = fmaxf(M, g_pm[(bh*SPLIT+s)*Uv + q]);
        float tot = 0.f;
        for (int s = 0; s < SPLIT; ++s) {
            float e = __expf(g_pm[(bh*SPLIT+s)*Uv + q] - M);
            w[s] = e;
            tot += g_pl[(bh*SPLIT+s)*Uv + q] * e;
        }
        inv = 1.0f / tot;
    }
    __syncthreads();
    const int d = threadIdx.x;
    float c = 0.f;
    for (int s = 0; s < SPLIT; ++s)
        c += g_pctx[(size_t)((bh*SPLIT+s)*Uv + q)*DKv + d] * w[s];
    g_ctx[(size_t)i*DKv + d] = c * inv;
}

// ---------------- kernel 7: base output row per batch ------------------------
__global__ __launch_bounds__(256) void base_kernel(const float* __restrict__ Wo,
                                                   const float* __restrict__ bo){
    const int b = blockIdx.y;
    const int warp = threadIdx.x >> 5, lane = threadIdx.x & 31;
    const int j = blockIdx.x*8 + warp;
    float s = 0.f;
    for (int d0 = lane; d0 < Dm; d0 += 32)
        s += g_vsum[b*Dm + d0] * Wo[(size_t)j*Dm + d0];
    #pragma unroll
    for (int o = 16; o; o >>= 1) s += __shfl_down_sync(0xffffffffu, s, o);
    if (lane == 0) g_base[b*Dm + j] = s*(1.0f/Lv) + bo[j];
}

// ---------------- kernel 8: broadcast base rows into output -------------------
__global__ void fill_kernel(float* __restrict__ out){
    const int i = blockIdx.x*blockDim.x + threadIdx.x;
    const int b  = i >> 21;
    const int j4 = i & 255;
    float4 v = *reinterpret_cast<const float4*>(&g_base[b*Dm + j4*4]);
    reinterpret_cast<float4*>(out)[i] = v;
}

// ---------------- kernel 9: rank-64 corrections for top rows ------------------
__global__ __launch_bounds__(256) void corr_kernel(const float* __restrict__ Wo,
                                                   float* __restrict__ out){
    const int i = blockIdx.x;
    const int bh = i / Uv;
    const int b = bh / Hh, h = bh % Hh;
    const int l = g_top[i];
    __shared__ float delta[DKv];
    const int t = threadIdx.x;
    if (t < DKv)
        delta[t] = g_ctx[(size_t)i*DKv + t] - g_vsum[b*Dm + h*DKv + t]*(1.0f/Lv);
    __syncthreads();
    for (int j = t; j < Dm; j += 256) {
        const float4* wr = reinterpret_cast<const float4*>(Wo + (size_t)j*Dm + h*DKv);
        float s = 0.f;
        #pragma unroll
        for (int dd = 0; dd < 16; ++dd) {
            float4 wv = wr[dd];
            s += delta[dd*4+0]*wv.x + delta[dd*4+1]*wv.y
               + delta[dd*4+2]*wv.z + delta[dd*4+3]*wv.w;
        }
        atomicAdd(&out[(size_t)(b*Lv + l)*Dm + j], s);
    }
}

// ---------------- launch ------------------------------------------------------
extern "C" void kernel_launch(void* const* d_in, const int* in_sizes, int n_in,
                              void* d_out, int out_size)
{
    const float* x    = (const float*)d_in[0];
    const float* Wq   = (const float*)d_in[1];
    const float* bq   = (const float*)d_in[2];
    const float* Wk   = (const float*)d_in[3];
    const float* bk   = (const float*)d_in[4];
    const float* Wv   = (const float*)d_in[5];
    const float* bv   = (const float*)d_in[6];
    const float* Wo   = (const float*)d_in[7];
    const float* bo   = (const float*)d_in[8];
    const int*   idxk = (const int*)d_in[9];
    float* out = (float*)d_out;

    zero_vsum_kernel<<<(Bv*Dm)/256, 256>>>();
    qkv_mma_kernel<<<dim3(Dm/128, BLv/128, 3), 256>>>(x, Wq, bq, Wk, bk, Wv, bv);
    m_kernel<<<dim3(Lv/128, Hh, Bv), 128>>>(idxk);
    vsum_kernel<<<dim3(Dm/128, Lv/256, Bv), 128>>>();
    topk_kernel<<<Bv*Hh, 256>>>();
    attn_partial_kernel<<<dim3(Bv*Hh, SPLIT), 512>>>();
    attn_combine_kernel<<<Bv*Hh*Uv, 64>>>();
    base_kernel<<<dim3(Dm/8, Bv), 256>>>(Wo, bo);
    fill_kernel<<<(BLv*Dm/4)/256, 256>>>(out);
    corr_kernel<<<Bv*Hh*Uv, 256>>>(Wo, out);
}

// round 4
// speedup vs baseline: 1.7750x; 1.3575x over previous
#include <cuda_runtime.h>
#include <cuda_fp16.h>
#include <math.h>
#include <stdint.h>

#define Bv 4
#define Lv 8192
#define Dm 1024
#define Hh 16
#define DKv 64
#define Uv 50
#define BLv (Bv*Lv)            // 32768
#define SPLIT 4
#define LSPL (Lv/SPLIT)        // 2048
#define TK 32

// ---------------- scratch (device globals; no allocations allowed) ----------
__device__ float g_Q[BLv*Dm];          // 128 MB
__device__ float g_K[BLv*Dm];          // 128 MB
__device__ float g_V[BLv*Dm];          // 128 MB
__device__ float g_M[Bv*Hh*Lv];
__device__ int   g_top[Bv*Hh*Uv];
__device__ float g_pm[Bv*Hh*SPLIT*Uv];
__device__ float g_pl[Bv*Hh*SPLIT*Uv];
__device__ float g_pctx[Bv*Hh*SPLIT*Uv*DKv];
__device__ float g_ctx[Bv*Hh*Uv*DKv];
__device__ float g_vsum[Bv*Dm];
__device__ float g_base[Bv*Dm];

// ---------------- f16 split helpers -----------------------------------------
// x -> hi (f16) + lo (f16), packed pairwise into f16x2 registers.
__device__ __forceinline__ uint32_t packsplit(float x, float y, uint32_t &lo){
    __half hx = __float2half_rn(x);
    __half hy = __float2half_rn(y);
    __half lx = __float2half_rn(x - __half2float(hx));
    __half ly = __float2half_rn(y - __half2float(hy));
    __half2 h2 = __halves2half2(hx, hy);
    __half2 l2 = __halves2half2(lx, ly);
    lo = *reinterpret_cast<uint32_t*>(&l2);
    return *reinterpret_cast<uint32_t*>(&h2);
}

__device__ __forceinline__ void mma16(float* c, const uint32_t* a, const uint32_t* b){
    asm volatile(
        "mma.sync.aligned.m16n8k16.row.col.f32.f16.f16.f32 "
        "{%0,%1,%2,%3}, {%4,%5,%6,%7}, {%8,%9}, {%0,%1,%2,%3};"
        : "+f"(c[0]), "+f"(c[1]), "+f"(c[2]), "+f"(c[3])
        : "r"(a[0]), "r"(a[1]), "r"(a[2]), "r"(a[3]), "r"(b[0]), "r"(b[1]));
}

// ======================= kernel 1: QKV GEMM via mma.sync 3xF16 ===============
// out[m][n] = sum_k X[m,k]*W[n,k] + bias[n]
// Tile 128(M) x 128(N) x 16(K) per stage. 256 thr = 8 warps (2M x 4N),
// warp tile 64x32. W scaled x32 in producer (keeps lo-limb in f16 normal
// range); epilogue divides by 32.
// Smem fragment-order layout per stage (uint32 units):
//   A_hi [8 frag][32 lane][4 regs] @0     A_lo @1024
//   B_hi [16 frag][32 lane][2 regs] @2048 B_lo @3072
#define QSTG 4096

__global__ __launch_bounds__(256,1) void qkv_f16_kernel(
    const float* __restrict__ X,
    const float* __restrict__ Wq, const float* __restrict__ bq,
    const float* __restrict__ Wk, const float* __restrict__ bk,
    const float* __restrict__ Wv, const float* __restrict__ bv)
{
    const float* W; const float* bias; float* out;
    if (blockIdx.z == 0)      { W = Wq; bias = bq; out = g_Q; }
    else if (blockIdx.z == 1) { W = Wk; bias = bk; out = g_K; }
    else                      { W = Wv; bias = bv; out = g_V; }

    const int n0 = blockIdx.x * 128;
    const int m0 = blockIdx.y * 128;

    __shared__ uint32_t smbuf[2][QSTG];   // 32 KB

    const int t = threadIdx.x;
    const int lane = t & 31;
    const int wid  = t >> 5;
    const int warp_m = wid & 1;
    const int warp_n = wid >> 1;

    // ---- producer coordinates ----
    // A: frag = wid, this lane fills all 4 regs of cell (wid, lane)
    const int arow = m0 + wid*16 + (lane >> 2);
    const int akb  = 2*(lane & 3);
    const float* pa0 = X + (size_t)arow*Dm + akb;
    const float* pa1 = pa0 + 8*Dm;
    // B: frag fB = t>>4 (0..15); j = t&15 covers lanes 2j, 2j+1
    const int fB = t >> 4;
    const int jj = t & 15;
    const float* pb = W + (size_t)(n0 + fB*8 + (jj >> 1))*Dm + 4*(jj & 1);

    float acc[4][4][4];
    #pragma unroll
    for (int i = 0; i < 4; ++i)
        #pragma unroll
        for (int j = 0; j < 4; ++j)
            #pragma unroll
            for (int r = 0; r < 4; ++r) acc[i][j][r] = 0.0f;

    // ---- prologue: produce stage 0 ----
    {
        float2 a00 = *reinterpret_cast<const float2*>(pa0);
        float2 a10 = *reinterpret_cast<const float2*>(pa1);
        float2 a01 = *reinterpret_cast<const float2*>(pa0 + 8);
        float2 a11 = *reinterpret_cast<const float2*>(pa1 + 8);
        float4 b0v = *reinterpret_cast<const float4*>(pb);
        float4 b1v = *reinterpret_cast<const float4*>(pb + 8);
        uint32_t* S = smbuf[0];
        uint32_t h0,h1,h2,h3, l0,l1,l2,l3;
        h0 = packsplit(a00.x, a00.y, l0);
        h1 = packsplit(a10.x, a10.y, l1);
        h2 = packsplit(a01.x, a01.y, l2);
        h3 = packsplit(a11.x, a11.y, l3);
        *reinterpret_cast<uint4*>(&S[wid*128 + lane*4])        = make_uint4(h0,h1,h2,h3);
        *reinterpret_cast<uint4*>(&S[1024 + wid*128 + lane*4]) = make_uint4(l0,l1,l2,l3);
        h0 = packsplit(b0v.x*32.f, b0v.y*32.f, l0);
        h1 = packsplit(b1v.x*32.f, b1v.y*32.f, l1);
        h2 = packsplit(b0v.z*32.f, b0v.w*32.f, l2);
        h3 = packsplit(b1v.z*32.f, b1v.w*32.f, l3);
        *reinterpret_cast<uint4*>(&S[2048 + fB*64 + jj*4]) = make_uint4(h0,h1,h2,h3);
        *reinterpret_cast<uint4*>(&S[3072 + fB*64 + jj*4]) = make_uint4(l0,l1,l2,l3);
    }
    __syncthreads();

    #pragma unroll 1
    for (int c = 0; c < 64; ++c) {
        const int cur = c & 1;

        // prefetch next chunk's globals into regs (overlaps MMA)
        float2 na00, na10, na01, na11; float4 nb0, nb1;
        if (c < 63) {
            const int k0 = (c + 1) * 16;
            na00 = *reinterpret_cast<const float2*>(pa0 + k0);
            na10 = *reinterpret_cast<const float2*>(pa1 + k0);
            na01 = *reinterpret_cast<const float2*>(pa0 + k0 + 8);
            na11 = *reinterpret_cast<const float2*>(pa1 + k0 + 8);
            nb0  = *reinterpret_cast<const float4*>(pb + k0);
            nb1  = *reinterpret_cast<const float4*>(pb + k0 + 8);
        }

        // fragment loads
        const uint32_t* S = smbuf[cur];
        uint32_t ah[4][4], al[4][4], bh[4][2], bl[4][2];
        #pragma unroll
        for (int im = 0; im < 4; ++im) {
            const int base = (warp_m*4 + im)*128 + lane*4;
            *reinterpret_cast<uint4*>(ah[im]) = *reinterpret_cast<const uint4*>(&S[base]);
            *reinterpret_cast<uint4*>(al[im]) = *reinterpret_cast<const uint4*>(&S[1024 + base]);
        }
        #pragma unroll
        for (int in = 0; in < 4; ++in) {
            const int base = 2048 + (warp_n*4 + in)*64 + lane*2;
            *reinterpret_cast<uint2*>(bh[in]) = *reinterpret_cast<const uint2*>(&S[base]);
            *reinterpret_cast<uint2*>(bl[in]) = *reinterpret_cast<const uint2*>(&S[1024 + base]);
        }

        // 3-term f16 split MMA: corrections then main
        #pragma unroll
        for (int im = 0; im < 4; ++im)
            #pragma unroll
            for (int in = 0; in < 4; ++in) {
                mma16(acc[im][in], al[im], bh[in]);
                mma16(acc[im][in], ah[im], bl[in]);
                mma16(acc[im][in], ah[im], bh[in]);
            }

        // produce next stage
        if (c < 63) {
            uint32_t* D = smbuf[cur ^ 1];
            uint32_t h0,h1,h2,h3, l0,l1,l2,l3;
            h0 = packsplit(na00.x, na00.y, l0);
            h1 = packsplit(na10.x, na10.y, l1);
            h2 = packsplit(na01.x, na01.y, l2);
            h3 = packsplit(na11.x, na11.y, l3);
            *reinterpret_cast<uint4*>(&D[wid*128 + lane*4])        = make_uint4(h0,h1,h2,h3);
            *reinterpret_cast<uint4*>(&D[1024 + wid*128 + lane*4]) = make_uint4(l0,l1,l2,l3);
            h0 = packsplit(nb0.x*32.f, nb0.y*32.f, l0);
            h1 = packsplit(nb1.x*32.f, nb1.y*32.f, l1);
            h2 = packsplit(nb0.z*32.f, nb0.w*32.f, l2);
            h3 = packsplit(nb1.z*32.f, nb1.w*32.f, l3);
            *reinterpret_cast<uint4*>(&D[2048 + fB*64 + jj*4]) = make_uint4(h0,h1,h2,h3);
            *reinterpret_cast<uint4*>(&D[3072 + fB*64 + jj*4]) = make_uint4(l0,l1,l2,l3);
        }
        __syncthreads();
    }

    // ---- epilogue: acc/32 + bias -> gmem ----
    const float inv32 = 0.03125f;
    #pragma unroll
    for (int im = 0; im < 4; ++im) {
        const int m = m0 + warp_m*64 + im*16 + (lane >> 2);
        #pragma unroll
        for (int in = 0; in < 4; ++in) {
            const int n = n0 + warp_n*32 + in*8 + (lane & 3)*2;
            const float b0 = __ldg(&bias[n]);
            const float b1 = __ldg(&bias[n+1]);
            float2 v0 = make_float2(acc[im][in][0]*inv32 + b0, acc[im][in][1]*inv32 + b1);
            float2 v1 = make_float2(acc[im][in][2]*inv32 + b0, acc[im][in][3]*inv32 + b1);
            *reinterpret_cast<float2*>(&out[(size_t)m*Dm + n])     = v0;
            *reinterpret_cast<float2*>(&out[(size_t)(m+8)*Dm + n]) = v1;
        }
    }
}

// ---------------- kernel 0: zero vsum ---------------------------------------
__global__ void zero_vsum_kernel(){
    int i = blockIdx.x*blockDim.x + threadIdx.x;
    if (i < Bv*Dm) g_vsum[i] = 0.0f;
}

// ---------------- kernel 2: sparsity measure M -------------------------------
__global__ __launch_bounds__(128) void m_kernel(const int* __restrict__ idx_k){
    const int b = blockIdx.z, h = blockIdx.y;
    const int l0 = blockIdx.x * 128;
    __shared__ float Ks[Uv*DKv];
    __shared__ float Qs[128*65];
    const int t = threadIdx.x;

    for (int i = t; i < Uv*DKv; i += 128) {
        int u = i >> 6, d = i & 63;
        Ks[i] = g_K[(size_t)(b*Lv + idx_k[u])*Dm + h*DKv + d];
    }
    for (int i = t; i < 128*DKv; i += 128) {
        int r = i >> 6, d = i & 63;
        Qs[r*65 + d] = g_Q[(size_t)(b*Lv + l0 + r)*Dm + h*DKv + d];
    }
    __syncthreads();

    float acc[Uv];
    #pragma unroll
    for (int u = 0; u < Uv; ++u) acc[u] = 0.0f;

    for (int d = 0; d < DKv; ++d) {
        float qd = Qs[t*65 + d];
        #pragma unroll
        for (int u = 0; u < Uv; ++u) acc[u] += qd * Ks[u*DKv + d];
    }
    float mx = -1e30f, smv = 0.0f;
    #pragma unroll
    for (int u = 0; u < Uv; ++u) { mx = fmaxf(mx, acc[u]); smv += acc[u]; }
    g_M[(size_t)(b*Hh + h)*Lv + l0 + t] = mx - smv*(1.0f/Uv);
}

// ---------------- kernel 3: top-k (k=50 of 8192) per (b,h) -------------------
__global__ __launch_bounds__(256) void topk_kernel(){
    const int bh = blockIdx.x;
    __shared__ float vals[Lv];
    __shared__ float rv[256];
    __shared__ int   ri[256];
    const int t = threadIdx.x;

    for (int i = t; i < Lv; i += 256) vals[i] = g_M[(size_t)bh*Lv + i];
    __syncthreads();

    for (int it = 0; it < Uv; ++it) {
        float best = -1e30f; int bi = Lv;
        for (int i = t; i < Lv; i += 256) {
            float v = vals[i];
            if (v > best || (v == best && i < bi)) { best = v; bi = i; }
        }
        rv[t] = best; ri[t] = bi;
        __syncthreads();
        for (int s = 128; s > 0; s >>= 1) {
            if (t < s) {
                if (rv[t+s] > rv[t] || (rv[t+s] == rv[t] && ri[t+s] < ri[t])) {
                    rv[t] = rv[t+s]; ri[t] = ri[t+s];
                }
            }
            __syncthreads();
        }
        if (t == 0) { g_top[bh*Uv + it] = ri[0]; vals[ri[0]] = -1e30f; }
        __syncthreads();
    }
}

// ---------------- kernel 4: V column sums (for mean) -------------------------
__global__ void vsum_kernel(){
    const int b = blockIdx.z;
    const int d = blockIdx.x*128 + threadIdx.x;
    const int c = blockIdx.y;
    float s = 0.0f;
    const int lbeg = c*256, lend = lbeg + 256;
    for (int l = lbeg; l < lend; ++l) s += g_V[(size_t)(b*Lv + l)*Dm + d];
    atomicAdd(&g_vsum[b*Dm + d], s);
}

// ---------------- kernel 5: flash attention for top queries (split-K) --------
__global__ __launch_bounds__(512) void attn_partial_kernel(){
    const int bh = blockIdx.x;
    const int sp = blockIdx.y;
    const int b = bh / Hh, h = bh % Hh;
    const int t = threadIdx.x;

    __shared__ float Qs[Uv][DKv];
    __shared__ float Ks[TK][65];
    __shared__ float Vs[TK][65];
    __shared__ float Ps[Uv][33];
    __shared__ float m_s[Uv], l_s[Uv], c_s[Uv];

    for (int i = t; i < Uv*DKv; i += 512) {
        int q = i >> 6, d = i & 63;
        int l = g_top[bh*Uv + q];
        Qs[q][d] = g_Q[(size_t)(b*Lv + l)*Dm + h*DKv + d];
    }
    if (t < Uv) { m_s[t] = -1e30f; l_s[t] = 0.0f; }

    float ctx[7];
    #pragma unroll
    for (int j = 0; j < 7; ++j) ctx[j] = 0.0f;
    const int d = t & 63;
    const int qb = t >> 6;

    __syncthreads();

    for (int l0 = sp*LSPL; l0 < (sp+1)*LSPL; l0 += TK) {
        for (int i = t; i < TK*DKv; i += 512) {
            int kk = i >> 6, dd = i & 63;
            size_t g = (size_t)(b*Lv + l0 + kk)*Dm + h*DKv + dd;
            Ks[kk][dd] = g_K[g];
            Vs[kk][dd] = g_V[g];
        }
        __syncthreads();

        if (t < 400) {
            const int q = t >> 3, kg = t & 7;
            float a0 = 0.f, a1 = 0.f, a2 = 0.f, a3 = 0.f;
            for (int dd = 0; dd < DKv; ++dd) {
                float qv = Qs[q][dd];
                a0 += qv * Ks[kg][dd];
                a1 += qv * Ks[kg+8][dd];
                a2 += qv * Ks[kg+16][dd];
                a3 += qv * Ks[kg+24][dd];
            }
            Ps[q][kg]    = a0 * 0.125f;
            Ps[q][kg+8]  = a1 * 0.125f;
            Ps[q][kg+16] = a2 * 0.125f;
            Ps[q][kg+24] = a3 * 0.125f;
        }
        __syncthreads();

        if (t < Uv) {
            float tm = -1e30f;
            #pragma unroll
            for (int k = 0; k < TK; ++k) tm = fmaxf(tm, Ps[t][k]);
            float nm = fmaxf(m_s[t], tm);
            float cc = __expf(m_s[t] - nm);
            float ls = l_s[t]*cc;
            #pragma unroll
            for (int k = 0; k < TK; ++k) {
                float p = __expf(Ps[t][k] - nm);
                Ps[t][k] = p;
                ls += p;
            }
            m_s[t] = nm; l_s[t] = ls; c_s[t] = cc;
        }
        __syncthreads();

        #pragma unroll
        for (int j = 0; j < 7; ++j) {
            int q = qb + 8*j;
            if (q < Uv) {
                float a = ctx[j] * c_s[q];
                #pragma unroll
                for (int k = 0; k < TK; ++k) a += Ps[q][k] * Vs[k][d];
                ctx[j] = a;
            }
        }
        __syncthreads();
    }

    #pragma unroll
    for (int j = 0; j < 7; ++j) {
        int q = qb + 8*j;
        if (q < Uv)
            g_pctx[(size_t)((bh*SPLIT + sp)*Uv + q)*DKv + d] = ctx[j];
    }
    if (t < Uv) {
        g_pm[(bh*SPLIT + sp)*Uv + t] = m_s[t];
        g_pl[(bh*SPLIT + sp)*Uv + t] = l_s[t];
    }
}

// ---------------- kernel 6: combine split partials ---------------------------
__global__ __launch_bounds__(64) void attn_combine_kernel(){
    const int i = blockIdx.x;
    const int q = i % Uv, bh = i / Uv;
    __shared__ float w[SPLIT];
    __shared__ float inv;
    if (threadIdx.x == 0) {
        float M = -1e30f;
        for (int s = 0; s < SPLIT; ++s) M = fmaxf(M, g_pm[(bh*SPLIT+s)*Uv + q]);
        float tot = 0.f;
        for (int s = 0; s < SPLIT; ++s) {
            float e = __expf(g_pm[(bh*SPLIT+s)*Uv + q] - M);
            w[s] = e;
            tot += g_pl[(bh*SPLIT+s)*Uv + q] * e;
        }
        inv = 1.0f / tot;
    }
    __syncthreads();
    const int d = threadIdx.x;
    float c = 0.f;
    for (int s = 0; s < SPLIT; ++s)
        c += g_pctx[(size_t)((bh*SPLIT+s)*Uv + q)*DKv + d] * w[s];
    g_ctx[(size_t)i*DKv + d] = c * inv;
}

// ---------------- kernel 7: base output row per batch ------------------------
__global__ __launch_bounds__(256) void base_kernel(const float* __restrict__ Wo,
                                                   const float* __restrict__ bo){
    const int b = blockIdx.y;
    const int warp = threadIdx.x >> 5, lane = threadIdx.x & 31;
    const int j = blockIdx.x*8 + warp;
    float s = 0.f;
    for (int d0 = lane; d0 < Dm; d0 += 32)
        s += g_vsum[b*Dm + d0] * Wo[(size_t)j*Dm + d0];
    #pragma unroll
    for (int o = 16; o; o >>= 1) s += __shfl_down_sync(0xffffffffu, s, o);
    if (lane == 0) g_base[b*Dm + j] = s*(1.0f/Lv) + bo[j];
}

// ---------------- kernel 8: broadcast base rows into output -------------------
__global__ void fill_kernel(float* __restrict__ out){
    const int i = blockIdx.x*blockDim.x + threadIdx.x;
    const int b  = i >> 21;
    const int j4 = i & 255;
    float4 v = *reinterpret_cast<const float4*>(&g_base[b*Dm + j4*4]);
    reinterpret_cast<float4*>(out)[i] = v;
}

// ---------------- kernel 9: rank-64 corrections for top rows ------------------
__global__ __launch_bounds__(256) void corr_kernel(const float* __restrict__ Wo,
                                                   float* __restrict__ out){
    const int i = blockIdx.x;
    const int bh = i / Uv;
    const int b = bh / Hh, h = bh % Hh;
    const int l = g_top[i];
    __shared__ float delta[DKv];
    const int t = threadIdx.x;
    if (t < DKv)
        delta[t] = g_ctx[(size_t)i*DKv + t] - g_vsum[b*Dm + h*DKv + t]*(1.0f/Lv);
    __syncthreads();
    for (int j = t; j < Dm; j += 256) {
        const float4* wr = reinterpret_cast<const float4*>(Wo + (size_t)j*Dm + h*DKv);
        float s = 0.f;
        #pragma unroll
        for (int dd = 0; dd < 16; ++dd) {
            float4 wv = wr[dd];
            s += delta[dd*4+0]*wv.x + delta[dd*4+1]*wv.y
               + delta[dd*4+2]*wv.z + delta[dd*4+3]*wv.w;
        }
        atomicAdd(&out[(size_t)(b*Lv + l)*Dm + j], s);
    }
}

// ---------------- launch ------------------------------------------------------
extern "C" void kernel_launch(void* const* d_in, const int* in_sizes, int n_in,
                              void* d_out, int out_size)
{
    const float* x    = (const float*)d_in[0];
    const float* Wq   = (const float*)d_in[1];
    const float* bq   = (const float*)d_in[2];
    const float* Wk   = (const float*)d_in[3];
    const float* bk   = (const float*)d_in[4];
    const float* Wv   = (const float*)d_in[5];
    const float* bv   = (const float*)d_in[6];
    const float* Wo   = (const float*)d_in[7];
    const float* bo   = (const float*)d_in[8];
    const int*   idxk = (const int*)d_in[9];
    float* out = (float*)d_out;

    zero_vsum_kernel<<<(Bv*Dm)/256, 256>>>();
    qkv_f16_kernel<<<dim3(Dm/128, BLv/128, 3), 256>>>(x, Wq, bq, Wk, bk, Wv, bv);
    m_kernel<<<dim3(Lv/128, Hh, Bv), 128>>>(idxk);
    vsum_kernel<<<dim3(Dm/128, Lv/256, Bv), 128>>>();
    topk_kernel<<<Bv*Hh, 256>>>();
    attn_partial_kernel<<<dim3(Bv*Hh, SPLIT), 512>>>();
    attn_combine_kernel<<<Bv*Hh*Uv, 64>>>();
    base_kernel<<<dim3(Dm/8, Bv), 256>>>(Wo, bo);
    fill_kernel<<<(BLv*Dm/4)/256, 256>>>(out);
    corr_kernel<<<Bv*Hh*Uv, 256>>>(Wo, out);
}

// round 5
// speedup vs baseline: 1.9686x; 1.1091x over previous
#include <cuda_runtime.h>
#include <cuda_fp16.h>
#include <math.h>
#include <stdint.h>

#define Bv 4
#define Lv 8192
#define Dm 1024
#define Hh 16
#define DKv 64
#define Uv 50
#define BLv (Bv*Lv)            // 32768
#define SPLIT 4
#define LSPL (Lv/SPLIT)        // 2048
#define TK 32

// ---------------- scratch (device globals; no allocations allowed) ----------
__device__ float g_Q[BLv*Dm];          // 128 MB
__device__ float g_K[BLv*Dm];          // 128 MB
__device__ float g_V[BLv*Dm];          // 128 MB
__device__ float g_M[Bv*Hh*Lv];
__device__ int   g_top[Bv*Hh*Uv];
__device__ float g_pm[Bv*Hh*SPLIT*Uv];
__device__ float g_pl[Bv*Hh*SPLIT*Uv];
__device__ float g_pctx[Bv*Hh*SPLIT*Uv*DKv];
__device__ float g_ctx[Bv*Hh*Uv*DKv];
__device__ float g_vsum[Bv*Dm];
__device__ float g_base[Bv*Dm];

// ---------------- f16 split helpers -----------------------------------------
__device__ __forceinline__ uint32_t packsplit(float x, float y, uint32_t &lo){
    __half hx = __float2half_rn(x);
    __half hy = __float2half_rn(y);
    __half lx = __float2half_rn(x - __half2float(hx));
    __half ly = __float2half_rn(y - __half2float(hy));
    __half2 h2 = __halves2half2(hx, hy);
    __half2 l2 = __halves2half2(lx, ly);
    lo = *reinterpret_cast<uint32_t*>(&l2);
    return *reinterpret_cast<uint32_t*>(&h2);
}

__device__ __forceinline__ void mma16(float* c, const uint32_t* a, const uint32_t* b){
    asm volatile(
        "mma.sync.aligned.m16n8k16.row.col.f32.f16.f16.f32 "
        "{%0,%1,%2,%3}, {%4,%5,%6,%7}, {%8,%9}, {%0,%1,%2,%3};"
        : "+f"(c[0]), "+f"(c[1]), "+f"(c[2]), "+f"(c[3])
        : "r"(a[0]), "r"(a[1]), "r"(a[2]), "r"(a[3]), "r"(b[0]), "r"(b[1]));
}

// ======================= kernel 1: QKV GEMM via mma.sync 3xF16 ===============
// out[m][n] = sum_k X[m,k]*W[n,k] + bias[n]
// Tile 128(M) x 64(N) x 16(K) per stage. 256 thr = 8 warps (4M x 2N),
// warp tile 32x32 -> low regs -> 2 CTAs/SM (bubble overlap).
// W scaled x32 in producer (keeps lo-limb in f16 normal range); epilogue /32.
// Smem per stage (uint32 units):
//   A_hi [8 frag][32 lane][4 regs] @0     A_lo @1024
//   B_hi [8 frag][32 lane][2 regs] @2048  B_lo @2560
#define QSTG 3072

__global__ __launch_bounds__(256,2) void qkv_f16_kernel(
    const float* __restrict__ X,
    const float* __restrict__ Wq, const float* __restrict__ bq,
    const float* __restrict__ Wk, const float* __restrict__ bk,
    const float* __restrict__ Wv, const float* __restrict__ bv)
{
    const float* W; const float* bias; float* out;
    if (blockIdx.z == 0)      { W = Wq; bias = bq; out = g_Q; }
    else if (blockIdx.z == 1) { W = Wk; bias = bk; out = g_K; }
    else                      { W = Wv; bias = bv; out = g_V; }

    const int n0 = blockIdx.x * 64;
    const int m0 = blockIdx.y * 128;

    __shared__ uint32_t smbuf[2][QSTG];   // 24 KB

    const int t = threadIdx.x;
    const int lane = t & 31;
    const int wid  = t >> 5;
    const int warp_m = wid & 3;
    const int warp_n = wid >> 2;

    // ---- producer coordinates ----
    // A: frag = wid (8 frags of 16 rows); lane fills 4 regs of (wid, lane)
    const int arow = m0 + wid*16 + (lane >> 2);
    const int akb  = 2*(lane & 3);
    const float* pa0 = X + (size_t)arow*Dm + akb;
    const float* pa1 = pa0 + 8*Dm;
    // B: frag g = t>>5 (8 frags of 8 cols); u = t&31 = fragment lane
    const int gB = t >> 5;
    const int uB = t & 31;
    const float* pb = W + (size_t)(n0 + gB*8 + (uB >> 2))*Dm + 2*(uB & 3);

    float acc[2][4][4];
    #pragma unroll
    for (int i = 0; i < 2; ++i)
        #pragma unroll
        for (int j = 0; j < 4; ++j)
            #pragma unroll
            for (int r = 0; r < 4; ++r) acc[i][j][r] = 0.0f;

    // ---- prologue: produce stage 0 ----
    {
        float2 a00 = *reinterpret_cast<const float2*>(pa0);
        float2 a10 = *reinterpret_cast<const float2*>(pa1);
        float2 a01 = *reinterpret_cast<const float2*>(pa0 + 8);
        float2 a11 = *reinterpret_cast<const float2*>(pa1 + 8);
        float2 b0v = *reinterpret_cast<const float2*>(pb);
        float2 b1v = *reinterpret_cast<const float2*>(pb + 8);
        uint32_t* S = smbuf[0];
        uint32_t h0,h1,h2,h3, l0,l1,l2,l3;
        h0 = packsplit(a00.x, a00.y, l0);
        h1 = packsplit(a10.x, a10.y, l1);
        h2 = packsplit(a01.x, a01.y, l2);
        h3 = packsplit(a11.x, a11.y, l3);
        *reinterpret_cast<uint4*>(&S[wid*128 + lane*4])        = make_uint4(h0,h1,h2,h3);
        *reinterpret_cast<uint4*>(&S[1024 + wid*128 + lane*4]) = make_uint4(l0,l1,l2,l3);
        uint32_t bh0, bh1, bl0, bl1;
        bh0 = packsplit(b0v.x*32.f, b0v.y*32.f, bl0);
        bh1 = packsplit(b1v.x*32.f, b1v.y*32.f, bl1);
        *reinterpret_cast<uint2*>(&S[2048 + gB*64 + uB*2]) = make_uint2(bh0, bh1);
        *reinterpret_cast<uint2*>(&S[2560 + gB*64 + uB*2]) = make_uint2(bl0, bl1);
    }
    __syncthreads();

    #pragma unroll 1
    for (int c = 0; c < 64; ++c) {
        const int cur = c & 1;

        // prefetch next chunk's globals into regs (overlaps MMA)
        float2 na00, na10, na01, na11, nb0, nb1;
        if (c < 63) {
            const int k0 = (c + 1) * 16;
            na00 = *reinterpret_cast<const float2*>(pa0 + k0);
            na10 = *reinterpret_cast<const float2*>(pa1 + k0);
            na01 = *reinterpret_cast<const float2*>(pa0 + k0 + 8);
            na11 = *reinterpret_cast<const float2*>(pa1 + k0 + 8);
            nb0  = *reinterpret_cast<const float2*>(pb + k0);
            nb1  = *reinterpret_cast<const float2*>(pb + k0 + 8);
        }

        // fragment loads
        const uint32_t* S = smbuf[cur];
        uint32_t ah[2][4], al[2][4], bh[4][2], bl[4][2];
        #pragma unroll
        for (int im = 0; im < 2; ++im) {
            const int base = (warp_m*2 + im)*128 + lane*4;
            *reinterpret_cast<uint4*>(ah[im]) = *reinterpret_cast<const uint4*>(&S[base]);
            *reinterpret_cast<uint4*>(al[im]) = *reinterpret_cast<const uint4*>(&S[1024 + base]);
        }
        #pragma unroll
        for (int in = 0; in < 4; ++in) {
            const int base = 2048 + (warp_n*4 + in)*64 + lane*2;
            *reinterpret_cast<uint2*>(bh[in]) = *reinterpret_cast<const uint2*>(&S[base]);
            *reinterpret_cast<uint2*>(bl[in]) = *reinterpret_cast<const uint2*>(&S[512 + base]);
        }

        // 3-term f16 split MMA: corrections then main
        #pragma unroll
        for (int im = 0; im < 2; ++im)
            #pragma unroll
            for (int in = 0; in < 4; ++in) {
                mma16(acc[im][in], al[im], bh[in]);
                mma16(acc[im][in], ah[im], bl[in]);
                mma16(acc[im][in], ah[im], bh[in]);
            }

        // produce next stage
        if (c < 63) {
            uint32_t* D = smbuf[cur ^ 1];
            uint32_t h0,h1,h2,h3, l0,l1,l2,l3;
            h0 = packsplit(na00.x, na00.y, l0);
            h1 = packsplit(na10.x, na10.y, l1);
            h2 = packsplit(na01.x, na01.y, l2);
            h3 = packsplit(na11.x, na11.y, l3);
            *reinterpret_cast<uint4*>(&D[wid*128 + lane*4])        = make_uint4(h0,h1,h2,h3);
            *reinterpret_cast<uint4*>(&D[1024 + wid*128 + lane*4]) = make_uint4(l0,l1,l2,l3);
            uint32_t bh0, bh1, bl0, bl1;
            bh0 = packsplit(nb0.x*32.f, nb0.y*32.f, bl0);
            bh1 = packsplit(nb1.x*32.f, nb1.y*32.f, bl1);
            *reinterpret_cast<uint2*>(&D[2048 + gB*64 + uB*2]) = make_uint2(bh0, bh1);
            *reinterpret_cast<uint2*>(&D[2560 + gB*64 + uB*2]) = make_uint2(bl0, bl1);
        }
        __syncthreads();
    }

    // ---- epilogue: acc/32 + bias -> gmem ----
    const float inv32 = 0.03125f;
    #pragma unroll
    for (int im = 0; im < 2; ++im) {
        const int m = m0 + warp_m*32 + im*16 + (lane >> 2);
        #pragma unroll
        for (int in = 0; in < 4; ++in) {
            const int n = n0 + warp_n*32 + in*8 + (lane & 3)*2;
            const float b0 = __ldg(&bias[n]);
            const float b1 = __ldg(&bias[n+1]);
            float2 v0 = make_float2(acc[im][in][0]*inv32 + b0, acc[im][in][1]*inv32 + b1);
            float2 v1 = make_float2(acc[im][in][2]*inv32 + b0, acc[im][in][3]*inv32 + b1);
            *reinterpret_cast<float2*>(&out[(size_t)m*Dm + n])     = v0;
            *reinterpret_cast<float2*>(&out[(size_t)(m+8)*Dm + n]) = v1;
        }
    }
}

// ---------------- kernel 0: zero vsum ---------------------------------------
__global__ void zero_vsum_kernel(){
    int i = blockIdx.x*blockDim.x + threadIdx.x;
    if (i < Bv*Dm) g_vsum[i] = 0.0f;
}

// ---------------- kernel 2: sparsity measure M -------------------------------
__global__ __launch_bounds__(128) void m_kernel(const int* __restrict__ idx_k){
    const int b = blockIdx.z, h = blockIdx.y;
    const int l0 = blockIdx.x * 128;
    __shared__ float Ks[Uv*DKv];
    __shared__ float Qs[128*65];
    const int t = threadIdx.x;

    for (int i = t; i < Uv*DKv; i += 128) {
        int u = i >> 6, d = i & 63;
        Ks[i] = g_K[(size_t)(b*Lv + idx_k[u])*Dm + h*DKv + d];
    }
    for (int i = t; i < 128*DKv; i += 128) {
        int r = i >> 6, d = i & 63;
        Qs[r*65 + d] = g_Q[(size_t)(b*Lv + l0 + r)*Dm + h*DKv + d];
    }
    __syncthreads();

    float acc[Uv];
    #pragma unroll
    for (int u = 0; u < Uv; ++u) acc[u] = 0.0f;

    for (int d = 0; d < DKv; ++d) {
        float qd = Qs[t*65 + d];
        #pragma unroll
        for (int u = 0; u < Uv; ++u) acc[u] += qd * Ks[u*DKv + d];
    }
    float mx = -1e30f, smv = 0.0f;
    #pragma unroll
    for (int u = 0; u < Uv; ++u) { mx = fmaxf(mx, acc[u]); smv += acc[u]; }
    g_M[(size_t)(b*Hh + h)*Lv + l0 + t] = mx - smv*(1.0f/Uv);
}

// ---------------- kernel 3: top-k (k=50 of 8192) per (b,h) -------------------
__global__ __launch_bounds__(256) void topk_kernel(){
    const int bh = blockIdx.x;
    __shared__ float vals[Lv];
    __shared__ float rv[256];
    __shared__ int   ri[256];
    const int t = threadIdx.x;

    for (int i = t; i < Lv; i += 256) vals[i] = g_M[(size_t)bh*Lv + i];
    __syncthreads();

    for (int it = 0; it < Uv; ++it) {
        float best = -1e30f; int bi = Lv;
        for (int i = t; i < Lv; i += 256) {
            float v = vals[i];
            if (v > best || (v == best && i < bi)) { best = v; bi = i; }
        }
        rv[t] = best; ri[t] = bi;
        __syncthreads();
        for (int s = 128; s > 0; s >>= 1) {
            if (t < s) {
                if (rv[t+s] > rv[t] || (rv[t+s] == rv[t] && ri[t+s] < ri[t])) {
                    rv[t] = rv[t+s]; ri[t] = ri[t+s];
                }
            }
            __syncthreads();
        }
        if (t == 0) { g_top[bh*Uv + it] = ri[0]; vals[ri[0]] = -1e30f; }
        __syncthreads();
    }
}

// ---------------- kernel 4: V column sums (for mean) -------------------------
__global__ void vsum_kernel(){
    const int b = blockIdx.z;
    const int d = blockIdx.x*128 + threadIdx.x;
    const int c = blockIdx.y;
    float s = 0.0f;
    const int lbeg = c*256, lend = lbeg + 256;
    for (int l = lbeg; l < lend; ++l) s += g_V[(size_t)(b*Lv + l)*Dm + d];
    atomicAdd(&g_vsum[b*Dm + d], s);
}

// ---------------- kernel 5: flash attention for top queries (split-K) --------
__global__ __launch_bounds__(512) void attn_partial_kernel(){
    const int bh = blockIdx.x;
    const int sp = blockIdx.y;
    const int b = bh / Hh, h = bh % Hh;
    const int t = threadIdx.x;

    __shared__ float Qs[Uv][DKv];
    __shared__ float Ks[TK][65];
    __shared__ float Vs[TK][65];
    __shared__ float Ps[Uv][33];
    __shared__ float m_s[Uv], l_s[Uv], c_s[Uv];

    for (int i = t; i < Uv*DKv; i += 512) {
        int q = i >> 6, d = i & 63;
        int l = g_top[bh*Uv + q];
        Qs[q][d] = g_Q[(size_t)(b*Lv + l)*Dm + h*DKv + d];
    }
    if (t < Uv) { m_s[t] = -1e30f; l_s[t] = 0.0f; }

    float ctx[7];
    #pragma unroll
    for (int j = 0; j < 7; ++j) ctx[j] = 0.0f;
    const int d = t & 63;
    const int qb = t >> 6;

    __syncthreads();

    for (int l0 = sp*LSPL; l0 < (sp+1)*LSPL; l0 += TK) {
        for (int i = t; i < TK*DKv; i += 512) {
            int kk = i >> 6, dd = i & 63;
            size_t g = (size_t)(b*Lv + l0 + kk)*Dm + h*DKv + dd;
            Ks[kk][dd] = g_K[g];
            Vs[kk][dd] = g_V[g];
        }
        __syncthreads();

        if (t < 400) {
            const int q = t >> 3, kg = t & 7;
            float a0 = 0.f, a1 = 0.f, a2 = 0.f, a3 = 0.f;
            for (int dd = 0; dd < DKv; ++dd) {
                float qv = Qs[q][dd];
                a0 += qv * Ks[kg][dd];
                a1 += qv * Ks[kg+8][dd];
                a2 += qv * Ks[kg+16][dd];
                a3 += qv * Ks[kg+24][dd];
            }
            Ps[q][kg]    = a0 * 0.125f;
            Ps[q][kg+8]  = a1 * 0.125f;
            Ps[q][kg+16] = a2 * 0.125f;
            Ps[q][kg+24] = a3 * 0.125f;
        }
        __syncthreads();

        if (t < Uv) {
            float tm = -1e30f;
            #pragma unroll
            for (int k = 0; k < TK; ++k) tm = fmaxf(tm, Ps[t][k]);
            float nm = fmaxf(m_s[t], tm);
            float cc = __expf(m_s[t] - nm);
            float ls = l_s[t]*cc;
            #pragma unroll
            for (int k = 0; k < TK; ++k) {
                float p = __expf(Ps[t][k] - nm);
                Ps[t][k] = p;
                ls += p;
            }
            m_s[t] = nm; l_s[t] = ls; c_s[t] = cc;
        }
        __syncthreads();

        #pragma unroll
        for (int j = 0; j < 7; ++j) {
            int q = qb + 8*j;
            if (q < Uv) {
                float a = ctx[j] * c_s[q];
                #pragma unroll
                for (int k = 0; k < TK; ++k) a += Ps[q][k] * Vs[k][d];
                ctx[j] = a;
            }
        }
        __syncthreads();
    }

    #pragma unroll
    for (int j = 0; j < 7; ++j) {
        int q = qb + 8*j;
        if (q < Uv)
            g_pctx[(size_t)((bh*SPLIT + sp)*Uv + q)*DKv + d] = ctx[j];
    }
    if (t < Uv) {
        g_pm[(bh*SPLIT + sp)*Uv + t] = m_s[t];
        g_pl[(bh*SPLIT + sp)*Uv + t] = l_s[t];
    }
}

// ---------------- kernel 6: combine split partials ---------------------------
__global__ __launch_bounds__(64) void attn_combine_kernel(){
    const int i = blockIdx.x;
    const int q = i % Uv, bh = i / Uv;
    __shared__ float w[SPLIT];
    __shared__ float inv;
    if (threadIdx.x == 0) {
        float M = -1e30f;
        for (int s = 0; s < SPLIT; ++s) M = fmaxf(M, g_pm[(bh*SPLIT+s)*Uv + q]);
        float tot = 0.f;
        for (int s = 0; s < SPLIT; ++s) {
            float e = __expf(g_pm[(bh*SPLIT+s)*Uv + q] - M);
            w[s] = e;
            tot += g_pl[(bh*SPLIT+s)*Uv + q] * e;
        }
        inv = 1.0f / tot;
    }
    __syncthreads();
    const int d = threadIdx.x;
    float c = 0.f;
    for (int s = 0; s < SPLIT; ++s)
        c += g_pctx[(size_t)((bh*SPLIT+s)*Uv + q)*DKv + d] * w[s];
    g_ctx[(size_t)i*DKv + d] = c * inv;
}

// ---------------- kernel 7: base output row per batch ------------------------
__global__ __launch_bounds__(256) void base_kernel(const float* __restrict__ Wo,
                                                   const float* __restrict__ bo){
    const int b = blockIdx.y;
    const int warp = threadIdx.x >> 5, lane = threadIdx.x & 31;
    const int j = blockIdx.x*8 + warp;
    float s = 0.f;
    for (int d0 = lane; d0 < Dm; d0 += 32)
        s += g_vsum[b*Dm + d0] * Wo[(size_t)j*Dm + d0];
    #pragma unroll
    for (int o = 16; o; o >>= 1) s += __shfl_down_sync(0xffffffffu, s, o);
    if (lane == 0) g_base[b*Dm + j] = s*(1.0f/Lv) + bo[j];
}

// ---------------- kernel 8: broadcast base rows into output -------------------
__global__ void fill_kernel(float* __restrict__ out){
    const int i = blockIdx.x*blockDim.x + threadIdx.x;
    const int b  = i >> 21;
    const int j4 = i & 255;
    float4 v = *reinterpret_cast<const float4*>(&g_base[b*Dm + j4*4]);
    reinterpret_cast<float4*>(out)[i] = v;
}

// ---------------- kernel 9: rank-64 corrections for top rows ------------------
__global__ __launch_bounds__(256) void corr_kernel(const float* __restrict__ Wo,
                                                   float* __restrict__ out){
    const int i = blockIdx.x;
    const int bh = i / Uv;
    const int b = bh / Hh, h = bh % Hh;
    const int l = g_top[i];
    __shared__ float delta[DKv];
    const int t = threadIdx.x;
    if (t < DKv)
        delta[t] = g_ctx[(size_t)i*DKv + t] - g_vsum[b*Dm + h*DKv + t]*(1.0f/Lv);
    __syncthreads();
    for (int j = t; j < Dm; j += 256) {
        const float4* wr = reinterpret_cast<const float4*>(Wo + (size_t)j*Dm + h*DKv);
        float s = 0.f;
        #pragma unroll
        for (int dd = 0; dd < 16; ++dd) {
            float4 wv = wr[dd];
            s += delta[dd*4+0]*wv.x + delta[dd*4+1]*wv.y
               + delta[dd*4+2]*wv.z + delta[dd*4+3]*wv.w;
        }
        atomicAdd(&out[(size_t)(b*Lv + l)*Dm + j], s);
    }
}

// ---------------- launch ------------------------------------------------------
extern "C" void kernel_launch(void* const* d_in, const int* in_sizes, int n_in,
                              void* d_out, int out_size)
{
    const float* x    = (const float*)d_in[0];
    const float* Wq   = (const float*)d_in[1];
    const float* bq   = (const float*)d_in[2];
    const float* Wk   = (const float*)d_in[3];
    const float* bk   = (const float*)d_in[4];
    const float* Wv   = (const float*)d_in[5];
    const float* bv   = (const float*)d_in[6];
    const float* Wo   = (const float*)d_in[7];
    const float* bo   = (const float*)d_in[8];
    const int*   idxk = (const int*)d_in[9];
    float* out = (float*)d_out;

    zero_vsum_kernel<<<(Bv*Dm)/256, 256>>>();
    qkv_f16_kernel<<<dim3(Dm/64, BLv/128, 3), 256>>>(x, Wq, bq, Wk, bk, Wv, bv);
    m_kernel<<<dim3(Lv/128, Hh, Bv), 128>>>(idxk);
    vsum_kernel<<<dim3(Dm/128, Lv/256, Bv), 128>>>();
    topk_kernel<<<Bv*Hh, 256>>>();
    attn_partial_kernel<<<dim3(Bv*Hh, SPLIT), 512>>>();
    attn_combine_kernel<<<Bv*Hh*Uv, 64>>>();
    base_kernel<<<dim3(Dm/8, Bv), 256>>>(Wo, bo);
    fill_kernel<<<(BLv*Dm/4)/256, 256>>>(out);
    corr_kernel<<<Bv*Hh*Uv, 256>>>(Wo, out);
}

// round 7
// speedup vs baseline: 2.3660x; 1.2018x over previous
#include <cuda_runtime.h>
#include <cuda_fp16.h>
#include <math.h>
#include <stdint.h>

#define Bv 4
#define Lv 8192
#define Dm 1024
#define Hh 16
#define DKv 64
#define Uv 50
#define BLv (Bv*Lv)            // 32768
#define SPLIT 4
#define LSPL (Lv/SPLIT)        // 2048
#define TK 32

// ---------------- scratch (device globals; no allocations allowed) ----------
__device__ float g_Q[BLv*Dm];          // 128 MB
__device__ float g_K[BLv*Dm];          // 128 MB
__device__ float g_V[BLv*Dm];          // 128 MB
__device__ uint32_t g_XS[(size_t)2048*64*32*8];   // 128 MB: X split, frag order
__device__ uint32_t g_WS[(size_t)3*128*64*32*4];  // 12 MB: W split (x32), frag order
__device__ float g_M[Bv*Hh*Lv];
__device__ int   g_top[Bv*Hh*Uv];
__device__ float g_pm[Bv*Hh*SPLIT*Uv];
__device__ float g_pl[Bv*Hh*SPLIT*Uv];
__device__ float g_pctx[Bv*Hh*SPLIT*Uv*DKv];
__device__ float g_ctx[Bv*Hh*Uv*DKv];
__device__ float g_vsum[Bv*Dm];
__device__ float g_base[Bv*Dm];

// ---------------- f16 split helpers -----------------------------------------
__device__ __forceinline__ uint32_t packsplit(float x, float y, uint32_t &lo){
    __half hx = __float2half_rn(x);
    __half hy = __float2half_rn(y);
    __half lx = __float2half_rn(x - __half2float(hx));
    __half ly = __float2half_rn(y - __half2float(hy));
    __half2 h2 = __halves2half2(hx, hy);
    __half2 l2 = __halves2half2(lx, ly);
    lo = *reinterpret_cast<uint32_t*>(&l2);
    return *reinterpret_cast<uint32_t*>(&h2);
}

__device__ __forceinline__ void mma16(float* c, const uint32_t* a, const uint32_t* b){
    asm volatile(
        "mma.sync.aligned.m16n8k16.row.col.f32.f16.f16.f32 "
        "{%0,%1,%2,%3}, {%4,%5,%6,%7}, {%8,%9}, {%0,%1,%2,%3};"
        : "+f"(c[0]), "+f"(c[1]), "+f"(c[2]), "+f"(c[3])
        : "r"(a[0]), "r"(a[1]), "r"(a[2]), "r"(a[3]), "r"(b[0]), "r"(b[1]));
}

// ---------------- kernel A: split X into fragment-ordered f16 limbs ----------
// cell = (mb, c, lane): 8 uint32 {ah0..ah3, al0..al3} at g_XS[cell*8]
__global__ __launch_bounds__(256) void split_x_kernel(const float* __restrict__ X){
    const int id = blockIdx.x*256 + threadIdx.x;       // 2048*64*32 cells
    const int mb   = id >> 11;
    const int c    = (id >> 5) & 63;
    const int lane = id & 31;
    const int r0 = mb*16 + (lane >> 2);
    const int k0 = c*16 + 2*(lane & 3);
    const float* p0 = X + (size_t)r0*Dm + k0;
    float2 a00 = *reinterpret_cast<const float2*>(p0);
    float2 a10 = *reinterpret_cast<const float2*>(p0 + 8*Dm);
    float2 a01 = *reinterpret_cast<const float2*>(p0 + 8);
    float2 a11 = *reinterpret_cast<const float2*>(p0 + 8*Dm + 8);
    uint32_t h0,h1,h2,h3, l0,l1,l2,l3;
    h0 = packsplit(a00.x, a00.y, l0);
    h1 = packsplit(a10.x, a10.y, l1);
    h2 = packsplit(a01.x, a01.y, l2);
    h3 = packsplit(a11.x, a11.y, l3);
    uint4* dst = reinterpret_cast<uint4*>(&g_XS[(size_t)id*8]);
    dst[0] = make_uint4(h0,h1,h2,h3);
    dst[1] = make_uint4(l0,l1,l2,l3);
}

// ---------------- kernel B: split W (x32) into fragment-ordered limbs --------
// cell = (gemm, nb, c, lane): 4 uint32 {bh0,bh1,bl0,bl1} at g_WS[cell*4]
__global__ __launch_bounds__(256) void split_w_kernel(
    const float* __restrict__ Wq, const float* __restrict__ Wk,
    const float* __restrict__ Wv)
{
    const int id = blockIdx.x*256 + threadIdx.x;       // 3*128*64*32 cells
    const int gemm = id >> 18;
    const int rem  = id & 262143;
    const int nb   = rem >> 11;
    const int c    = (rem >> 5) & 63;
    const int lane = rem & 31;
    const float* W = (gemm == 0) ? Wq : (gemm == 1) ? Wk : Wv;
    const int row = nb*8 + (lane >> 2);
    const int k0  = c*16 + 2*(lane & 3);
    const float* p = W + (size_t)row*Dm + k0;
    float2 b0 = *reinterpret_cast<const float2*>(p);
    float2 b1 = *reinterpret_cast<const float2*>(p + 8);
    uint32_t bh0, bh1, bl0, bl1;
    bh0 = packsplit(b0.x*32.f, b0.y*32.f, bl0);
    bh1 = packsplit(b1.x*32.f, b1.y*32.f, bl1);
    reinterpret_cast<uint4*>(&g_WS[(size_t)id*4])[0] = make_uint4(bh0,bh1,bl0,bl1);
}

// ======================= kernel 1: QKV GEMM (pre-split f16 limbs) ============
// Tile 128M x 64N x 32K per stage (2 chunks of 16). 256 thr = 8 warps (4Mx2N),
// warp tile 32x32, 2 CTAs/SM. Producer = pure LDG.128->STS.128 copy.
// Smem stage layout (uint32): chunk ch at ch*3072:
//   Ahi @0 (1024: (f*32+lane)*4), Alo @1024, B @2048 (1024: (g*32+lane)*4)
__global__ __launch_bounds__(256,2) void qkv_f16_kernel(
    const float* __restrict__ bq, const float* __restrict__ bk,
    const float* __restrict__ bv)
{
    const int gemm = blockIdx.z;
    const float* bias = (gemm == 0) ? bq : (gemm == 1) ? bk : bv;
    float* out = (gemm == 0) ? g_Q : (gemm == 1) ? g_K : g_V;

    const int n0 = blockIdx.x * 64;
    const int m0 = blockIdx.y * 128;

    __shared__ uint32_t smbuf[2*6144];   // 48 KB

    const int t = threadIdx.x;
    const int lane = t & 31;
    const int wid  = t >> 5;
    const int warp_m = wid & 3;
    const int warp_n = wid >> 2;

    // ---- producer cell coords ----
    const int fA = (t >> 5) & 7;          // A frag 0..7
    const int lA = t & 31;
    const int gBf = (t >> 5) & 7;         // B frag
    // global read pointers (uint4 units)
    const uint4* pA0 = reinterpret_cast<const uint4*>(g_XS)
        + (((size_t)(blockIdx.y*8 + fA)*64 + 0)*32 + lA)*2;         // chunk c=2s
    const uint4* pA1 = pA0 + 64;                                     // c=2s+1
    const uint4* pB0 = reinterpret_cast<const uint4*>(g_WS)
        + (((size_t)gemm*128 + blockIdx.x*8 + gBf)*64 + 0)*32 + lA; // chunk c=2s
    const uint4* pB1 = pB0 + 32;                                     // c=2s+1
    // smem write offsets (uint32 units, relative to stage base)
    const int dA = (fA*32 + lA)*4;        // hi at dA, lo at dA+1024
    const int dB = 2048 + (gBf*32 + lA)*4;

    float acc[2][4][4];
    #pragma unroll
    for (int i = 0; i < 2; ++i)
        #pragma unroll
        for (int j = 0; j < 4; ++j)
            #pragma unroll
            for (int r = 0; r < 4; ++r) acc[i][j][r] = 0.0f;

    // ---- prologue: produce stage 0 ----
    {
        uint4 a0h = pA0[0], a0l = pA0[1];
        uint4 a1h = pA1[0], a1l = pA1[1];
        uint4 b0  = pB0[0], b1  = pB1[0];
        pA0 += 128; pA1 += 128; pB0 += 64; pB1 += 64;   // advance 2 chunks (FIX)
        uint32_t* S = smbuf;
        *reinterpret_cast<uint4*>(&S[dA])               = a0h;
        *reinterpret_cast<uint4*>(&S[dA + 1024])        = a0l;
        *reinterpret_cast<uint4*>(&S[3072 + dA])        = a1h;
        *reinterpret_cast<uint4*>(&S[3072 + dA + 1024]) = a1l;
        *reinterpret_cast<uint4*>(&S[dB])               = b0;
        *reinterpret_cast<uint4*>(&S[3072 + dB])        = b1;
    }
    __syncthreads();

    #pragma unroll 1
    for (int s = 0; s < 32; ++s) {
        const uint32_t* buf = smbuf + (s & 1)*6144;

        // prefetch next stage's globals (overlaps MMA)
        uint4 na0h, na0l, na1h, na1l, nb0, nb1;
        if (s < 31) {
            na0h = pA0[0]; na0l = pA0[1];
            na1h = pA1[0]; na1l = pA1[1];
            nb0  = pB0[0]; nb1  = pB1[0];
            pA0 += 128; pA1 += 128; pB0 += 64; pB1 += 64;   // FIX: B advances 2 chunks
        }

        // consume both chunks
        #pragma unroll
        for (int ch = 0; ch < 2; ++ch) {
            const uint32_t* C = buf + ch*3072;
            uint32_t ah[2][4], al[2][4], bh[4][2], bl[4][2];
            #pragma unroll
            for (int im = 0; im < 2; ++im) {
                const int base = ((warp_m*2 + im)*32 + lane)*4;
                *reinterpret_cast<uint4*>(ah[im]) = *reinterpret_cast<const uint4*>(&C[base]);
                *reinterpret_cast<uint4*>(al[im]) = *reinterpret_cast<const uint4*>(&C[base + 1024]);
            }
            #pragma unroll
            for (int in = 0; in < 4; ++in) {
                const int base = 2048 + ((warp_n*4 + in)*32 + lane)*4;
                uint4 q = *reinterpret_cast<const uint4*>(&C[base]);
                bh[in][0] = q.x; bh[in][1] = q.y;
                bl[in][0] = q.z; bl[in][1] = q.w;
            }
            #pragma unroll
            for (int im = 0; im < 2; ++im)
                #pragma unroll
                for (int in = 0; in < 4; ++in) {
                    mma16(acc[im][in], al[im], bh[in]);
                    mma16(acc[im][in], ah[im], bl[in]);
                    mma16(acc[im][in], ah[im], bh[in]);
                }
        }

        // store next stage
        if (s < 31) {
            uint32_t* D = smbuf + ((s & 1) ^ 1)*6144;
            *reinterpret_cast<uint4*>(&D[dA])               = na0h;
            *reinterpret_cast<uint4*>(&D[dA + 1024])        = na0l;
            *reinterpret_cast<uint4*>(&D[3072 + dA])        = na1h;
            *reinterpret_cast<uint4*>(&D[3072 + dA + 1024]) = na1l;
            *reinterpret_cast<uint4*>(&D[dB])               = nb0;
            *reinterpret_cast<uint4*>(&D[3072 + dB])        = nb1;
        }
        __syncthreads();
    }

    // ---- epilogue: acc/32 + bias -> gmem ----
    const float inv32 = 0.03125f;
    #pragma unroll
    for (int im = 0; im < 2; ++im) {
        const int m = m0 + warp_m*32 + im*16 + (lane >> 2);
        #pragma unroll
        for (int in = 0; in < 4; ++in) {
            const int n = n0 + warp_n*32 + in*8 + (lane & 3)*2;
            const float b0 = __ldg(&bias[n]);
            const float b1 = __ldg(&bias[n+1]);
            float2 v0 = make_float2(acc[im][in][0]*inv32 + b0, acc[im][in][1]*inv32 + b1);
            float2 v1 = make_float2(acc[im][in][2]*inv32 + b0, acc[im][in][3]*inv32 + b1);
            *reinterpret_cast<float2*>(&out[(size_t)m*Dm + n])     = v0;
            *reinterpret_cast<float2*>(&out[(size_t)(m+8)*Dm + n]) = v1;
        }
    }
}

// ---------------- kernel 0: zero vsum ---------------------------------------
__global__ void zero_vsum_kernel(){
    int i = blockIdx.x*blockDim.x + threadIdx.x;
    if (i < Bv*Dm) g_vsum[i] = 0.0f;
}

// ---------------- kernel 2: sparsity measure M -------------------------------
__global__ __launch_bounds__(128) void m_kernel(const int* __restrict__ idx_k){
    const int b = blockIdx.z, h = blockIdx.y;
    const int l0 = blockIdx.x * 128;
    __shared__ float Ks[Uv*DKv];
    __shared__ float Qs[128*65];
    const int t = threadIdx.x;

    for (int i = t; i < Uv*DKv; i += 128) {
        int u = i >> 6, d = i & 63;
        Ks[i] = g_K[(size_t)(b*Lv + idx_k[u])*Dm + h*DKv + d];
    }
    for (int i = t; i < 128*DKv; i += 128) {
        int r = i >> 6, d = i & 63;
        Qs[r*65 + d] = g_Q[(size_t)(b*Lv + l0 + r)*Dm + h*DKv + d];
    }
    __syncthreads();

    float acc[Uv];
    #pragma unroll
    for (int u = 0; u < Uv; ++u) acc[u] = 0.0f;

    for (int d = 0; d < DKv; ++d) {
        float qd = Qs[t*65 + d];
        #pragma unroll
        for (int u = 0; u < Uv; ++u) acc[u] += qd * Ks[u*DKv + d];
    }
    float mx = -1e30f, smv = 0.0f;
    #pragma unroll
    for (int u = 0; u < Uv; ++u) { mx = fmaxf(mx, acc[u]); smv += acc[u]; }
    g_M[(size_t)(b*Hh + h)*Lv + l0 + t] = mx - smv*(1.0f/Uv);
}

// ---------------- kernel 3: top-k (k=50 of 8192) per (b,h) -------------------
__global__ __launch_bounds__(256) void topk_kernel(){
    const int bh = blockIdx.x;
    __shared__ float vals[Lv];
    __shared__ float rv[256];
    __shared__ int   ri[256];
    const int t = threadIdx.x;

    for (int i = t; i < Lv; i += 256) vals[i] = g_M[(size_t)bh*Lv + i];
    __syncthreads();

    for (int it = 0; it < Uv; ++it) {
        float best = -1e30f; int bi = Lv;
        for (int i = t; i < Lv; i += 256) {
            float v = vals[i];
            if (v > best || (v == best && i < bi)) { best = v; bi = i; }
        }
        rv[t] = best; ri[t] = bi;
        __syncthreads();
        for (int s = 128; s > 0; s >>= 1) {
            if (t < s) {
                if (rv[t+s] > rv[t] || (rv[t+s] == rv[t] && ri[t+s] < ri[t])) {
                    rv[t] = rv[t+s]; ri[t] = ri[t+s];
                }
            }
            __syncthreads();
        }
        if (t == 0) { g_top[bh*Uv + it] = ri[0]; vals[ri[0]] = -1e30f; }
        __syncthreads();
    }
}

// ---------------- kernel 4: V column sums (for mean) -------------------------
__global__ void vsum_kernel(){
    const int b = blockIdx.z;
    const int d = blockIdx.x*128 + threadIdx.x;
    const int c = blockIdx.y;
    float s = 0.0f;
    const int lbeg = c*256, lend = lbeg + 256;
    for (int l = lbeg; l < lend; ++l) s += g_V[(size_t)(b*Lv + l)*Dm + d];
    atomicAdd(&g_vsum[b*Dm + d], s);
}

// ---------------- kernel 5: flash attention for top queries (split-K) --------
__global__ __launch_bounds__(512) void attn_partial_kernel(){
    const int bh = blockIdx.x;
    const int sp = blockIdx.y;
    const int b = bh / Hh, h = bh % Hh;
    const int t = threadIdx.x;

    __shared__ float Qs[Uv][DKv];
    __shared__ float Ks[TK][65];
    __shared__ float Vs[TK][65];
    __shared__ float Ps[Uv][33];
    __shared__ float m_s[Uv], l_s[Uv], c_s[Uv];

    for (int i = t; i < Uv*DKv; i += 512) {
        int q = i >> 6, d = i & 63;
        int l = g_top[bh*Uv + q];
        Qs[q][d] = g_Q[(size_t)(b*Lv + l)*Dm + h*DKv + d];
    }
    if (t < Uv) { m_s[t] = -1e30f; l_s[t] = 0.0f; }

    float ctx[7];
    #pragma unroll
    for (int j = 0; j < 7; ++j) ctx[j] = 0.0f;
    const int d = t & 63;
    const int qb = t >> 6;

    __syncthreads();

    for (int l0 = sp*LSPL; l0 < (sp+1)*LSPL; l0 += TK) {
        for (int i = t; i < TK*DKv; i += 512) {
            int kk = i >> 6, dd = i & 63;
            size_t g = (size_t)(b*Lv + l0 + kk)*Dm + h*DKv + dd;
            Ks[kk][dd] = g_K[g];
            Vs[kk][dd] = g_V[g];
        }
        __syncthreads();

        if (t < 400) {
            const int q = t >> 3, kg = t & 7;
            float a0 = 0.f, a1 = 0.f, a2 = 0.f, a3 = 0.f;
            for (int dd = 0; dd < DKv; ++dd) {
                float qv = Qs[q][dd];
                a0 += qv * Ks[kg][dd];
                a1 += qv * Ks[kg+8][dd];
                a2 += qv * Ks[kg+16][dd];
                a3 += qv * Ks[kg+24][dd];
            }
            Ps[q][kg]    = a0 * 0.125f;
            Ps[q][kg+8]  = a1 * 0.125f;
            Ps[q][kg+16] = a2 * 0.125f;
            Ps[q][kg+24] = a3 * 0.125f;
        }
        __syncthreads();

        if (t < Uv) {
            float tm = -1e30f;
            #pragma unroll
            for (int k = 0; k < TK; ++k) tm = fmaxf(tm, Ps[t][k]);
            float nm = fmaxf(m_s[t], tm);
            float cc = __expf(m_s[t] - nm);
            float ls = l_s[t]*cc;
            #pragma unroll
            for (int k = 0; k < TK; ++k) {
                float p = __expf(Ps[t][k] - nm);
                Ps[t][k] = p;
                ls += p;
            }
            m_s[t] = nm; l_s[t] = ls; c_s[t] = cc;
        }
        __syncthreads();

        #pragma unroll
        for (int j = 0; j < 7; ++j) {
            int q = qb + 8*j;
            if (q < Uv) {
                float a = ctx[j] * c_s[q];
                #pragma unroll
                for (int k = 0; k < TK; ++k) a += Ps[q][k] * Vs[k][d];
                ctx[j] = a;
            }
        }
        __syncthreads();
    }

    #pragma unroll
    for (int j = 0; j < 7; ++j) {
        int q = qb + 8*j;
        if (q < Uv)
            g_pctx[(size_t)((bh*SPLIT + sp)*Uv + q)*DKv + d] = ctx[j];
    }
    if (t < Uv) {
        g_pm[(bh*SPLIT + sp)*Uv + t] = m_s[t];
        g_pl[(bh*SPLIT + sp)*Uv + t] = l_s[t];
    }
}

// ---------------- kernel 6: combine split partials ---------------------------
__global__ __launch_bounds__(64) void attn_combine_kernel(){
    const int i = blockIdx.x;
    const int q = i % Uv, bh = i / Uv;
    __shared__ float w[SPLIT];
    __shared__ float inv;
    if (threadIdx.x == 0) {
        float M = -1e30f;
        for (int s = 0; s < SPLIT; ++s) M = fmaxf(M, g_pm[(bh*SPLIT+s)*Uv + q]);
        float tot = 0.f;
        for (int s = 0; s < SPLIT; ++s) {
            float e = __expf(g_pm[(bh*SPLIT+s)*Uv + q] - M);
            w[s] = e;
            tot += g_pl[(bh*SPLIT+s)*Uv + q] * e;
        }
        inv = 1.0f / tot;
    }
    __syncthreads();
    const int d = threadIdx.x;
    float c = 0.f;
    for (int s = 0; s < SPLIT; ++s)
        c += g_pctx[(size_t)((bh*SPLIT+s)*Uv + q)*DKv + d] * w[s];
    g_ctx[(size_t)i*DKv + d] = c * inv;
}

// ---------------- kernel 7: base output row per batch ------------------------
__global__ __launch_bounds__(256) void base_kernel(const float* __restrict__ Wo,
                                                   const float* __restrict__ bo){
    const int b = blockIdx.y;
    const int warp = threadIdx.x >> 5, lane = threadIdx.x & 31;
    const int j = blockIdx.x*8 + warp;
    float s = 0.f;
    for (int d0 = lane; d0 < Dm; d0 += 32)
        s += g_vsum[b*Dm + d0] * Wo[(size_t)j*Dm + d0];
    #pragma unroll
    for (int o = 16; o; o >>= 1) s += __shfl_down_sync(0xffffffffu, s, o);
    if (lane == 0) g_base[b*Dm + j] = s*(1.0f/Lv) + bo[j];
}

// ---------------- kernel 8: broadcast base rows into output -------------------
__global__ void fill_kernel(float* __restrict__ out){
    const int i = blockIdx.x*blockDim.x + threadIdx.x;
    const int b  = i >> 21;
    const int j4 = i & 255;
    float4 v = *reinterpret_cast<const float4*>(&g_base[b*Dm + j4*4]);
    reinterpret_cast<float4*>(out)[i] = v;
}

// ---------------- kernel 9: rank-64 corrections for top rows ------------------
__global__ __launch_bounds__(256) void corr_kernel(const float* __restrict__ Wo,
                                                   float* __restrict__ out){
    const int i = blockIdx.x;
    const int bh = i / Uv;
    const int b = bh / Hh, h = bh % Hh;
    const int l = g_top[i];
    __shared__ float delta[DKv];
    const int t = threadIdx.x;
    if (t < DKv)
        delta[t] = g_ctx[(size_t)i*DKv + t] - g_vsum[b*Dm + h*DKv + t]*(1.0f/Lv);
    __syncthreads();
    for (int j = t; j < Dm; j += 256) {
        const float4* wr = reinterpret_cast<const float4*>(Wo + (size_t)j*Dm + h*DKv);
        float s = 0.f;
        #pragma unroll
        for (int dd = 0; dd < 16; ++dd) {
            float4 wv = wr[dd];
            s += delta[dd*4+0]*wv.x + delta[dd*4+1]*wv.y
               + delta[dd*4+2]*wv.z + delta[dd*4+3]*wv.w;
        }
        atomicAdd(&out[(size_t)(b*Lv + l)*Dm + j], s);
    }
}

// ---------------- launch ------------------------------------------------------
extern "C" void kernel_launch(void* const* d_in, const int* in_sizes, int n_in,
                              void* d_out, int out_size)
{
    const float* x    = (const float*)d_in[0];
    const float* Wq   = (const float*)d_in[1];
    const float* bq   = (const float*)d_in[2];
    const float* Wk   = (const float*)d_in[3];
    const float* bk   = (const float*)d_in[4];
    const float* Wv   = (const float*)d_in[5];
    const float* bv   = (const float*)d_in[6];
    const float* Wo   = (const float*)d_in[7];
    const float* bo   = (const float*)d_in[8];
    const int*   idxk = (const int*)d_in[9];
    float* out = (float*)d_out;

    zero_vsum_kernel<<<(Bv*Dm)/256, 256>>>();
    split_x_kernel<<<(2048*64*32)/256, 256>>>(x);
    split_w_kernel<<<(3*128*64*32)/256, 256>>>(Wq, Wk, Wv);
    qkv_f16_kernel<<<dim3(Dm/64, BLv/128, 3), 256>>>(bq, bk, bv);
    m_kernel<<<dim3(Lv/128, Hh, Bv), 128>>>(idxk);
    vsum_kernel<<<dim3(Dm/128, Lv/256, Bv), 128>>>();
    topk_kernel<<<Bv*Hh, 256>>>();
    attn_partial_kernel<<<dim3(Bv*Hh, SPLIT), 512>>>();
    attn_combine_kernel<<<Bv*Hh*Uv, 64>>>();
    base_kernel<<<dim3(Dm/8, Bv), 256>>>(Wo, bo);
    fill_kernel<<<(BLv*Dm/4)/256, 256>>>(out);
    corr_kernel<<<Bv*Hh*Uv, 256>>>(Wo, out);
}

// round 8
// speedup vs baseline: 2.8119x; 1.1885x over previous
#include <cuda_runtime.h>
#include <cuda_fp16.h>
#include <math.h>
#include <stdint.h>

#define Bv 4
#define Lv 8192
#define Dm 1024
#define Hh 16
#define DKv 64
#define Uv 50
#define BLv (Bv*Lv)            // 32768
#define SPLIT 4
#define LSPL (Lv/SPLIT)        // 2048
#define TK 32

// ---------------- scratch (device globals; no allocations allowed) ----------
#define XS_CELLS ((size_t)2048*64*32)
__device__ float g_Q[BLv*Dm];          // 128 MB
__device__ float g_K[BLv*Dm];          // 128 MB
__device__ float g_V[BLv*Dm];          // 128 MB
__device__ uint32_t g_XS[XS_CELLS*8];             // 128 MB: X limbs, hi plane then lo plane
__device__ uint32_t g_WS[(size_t)3*128*64*32*4];  // 12 MB: W limbs (x32), frag order
__device__ float g_M[Bv*Hh*Lv];
__device__ int   g_top[Bv*Hh*Uv];
__device__ float g_pm[Bv*Hh*SPLIT*Uv];
__device__ float g_pl[Bv*Hh*SPLIT*Uv];
__device__ float g_pctx[Bv*Hh*SPLIT*Uv*DKv];
__device__ float g_ctx[Bv*Hh*Uv*DKv];
__device__ float g_vsum[Bv*Dm];
__device__ float g_base[Bv*Dm];

// ---------------- helpers ----------------------------------------------------
__device__ __forceinline__ uint32_t packsplit(float x, float y, uint32_t &lo){
    __half hx = __float2half_rn(x);
    __half hy = __float2half_rn(y);
    __half lx = __float2half_rn(x - __half2float(hx));
    __half ly = __float2half_rn(y - __half2float(hy));
    __half2 h2 = __halves2half2(hx, hy);
    __half2 l2 = __halves2half2(lx, ly);
    lo = *reinterpret_cast<uint32_t*>(&l2);
    return *reinterpret_cast<uint32_t*>(&h2);
}

__device__ __forceinline__ void mma16(float* c, const uint32_t* a, const uint32_t* b){
    asm volatile(
        "mma.sync.aligned.m16n8k16.row.col.f32.f16.f16.f32 "
        "{%0,%1,%2,%3}, {%4,%5,%6,%7}, {%8,%9}, {%0,%1,%2,%3};"
        : "+f"(c[0]), "+f"(c[1]), "+f"(c[2]), "+f"(c[3])
        : "r"(a[0]), "r"(a[1]), "r"(a[2]), "r"(a[3]), "r"(b[0]), "r"(b[1]));
}

__device__ __forceinline__ uint32_t sm_u32(const void* p){
    uint32_t a;
    asm("{ .reg .u64 t; cvta.to.shared.u64 t, %1; cvt.u32.u64 %0, t; }"
        : "=r"(a) : "l"(p));
    return a;
}

__device__ __forceinline__ void cpasync16(uint32_t dst, const void* src){
    asm volatile("cp.async.cg.shared.global [%0], [%1], 16;"
                 :: "r"(dst), "l"(src) : "memory");
}
#define CP_COMMIT() asm volatile("cp.async.commit_group;" ::: "memory")
#define CP_WAIT2()  asm volatile("cp.async.wait_group 2;" ::: "memory")

// ---------------- kernel A: split X into limb planes (frag order) -----------
// cell = (mb, c, lane); hi quad at g_XS[cell*4], lo quad at g_XS[XS_CELLS*4 + cell*4]
__global__ __launch_bounds__(256) void split_x_kernel(const float* __restrict__ X){
    const int id = blockIdx.x*256 + threadIdx.x;
    const int mb   = id >> 11;
    const int c    = (id >> 5) & 63;
    const int lane = id & 31;
    const int r0 = mb*16 + (lane >> 2);
    const int k0 = c*16 + 2*(lane & 3);
    const float* p0 = X + (size_t)r0*Dm + k0;
    float2 a00 = *reinterpret_cast<const float2*>(p0);
    float2 a10 = *reinterpret_cast<const float2*>(p0 + 8*Dm);
    float2 a01 = *reinterpret_cast<const float2*>(p0 + 8);
    float2 a11 = *reinterpret_cast<const float2*>(p0 + 8*Dm + 8);
    uint32_t h0,h1,h2,h3, l0,l1,l2,l3;
    h0 = packsplit(a00.x, a00.y, l0);
    h1 = packsplit(a10.x, a10.y, l1);
    h2 = packsplit(a01.x, a01.y, l2);
    h3 = packsplit(a11.x, a11.y, l3);
    *reinterpret_cast<uint4*>(&g_XS[(size_t)id*4])              = make_uint4(h0,h1,h2,h3);
    *reinterpret_cast<uint4*>(&g_XS[XS_CELLS*4 + (size_t)id*4]) = make_uint4(l0,l1,l2,l3);
}

// ---------------- kernel B: split W (x32) into fragment-ordered limbs --------
// cell = (gemm, nb, c, lane): {bh0,bh1,bl0,bl1} at g_WS[cell*4]
__global__ __launch_bounds__(256) void split_w_kernel(
    const float* __restrict__ Wq, const float* __restrict__ Wk,
    const float* __restrict__ Wv)
{
    const int id = blockIdx.x*256 + threadIdx.x;
    const int gemm = id >> 18;
    const int rem  = id & 262143;
    const int nb   = rem >> 11;
    const int c    = (rem >> 5) & 63;
    const int lane = rem & 31;
    const float* W = (gemm == 0) ? Wq : (gemm == 1) ? Wk : Wv;
    const int row = nb*8 + (lane >> 2);
    const int k0  = c*16 + 2*(lane & 3);
    const float* p = W + (size_t)row*Dm + k0;
    float2 b0 = *reinterpret_cast<const float2*>(p);
    float2 b1 = *reinterpret_cast<const float2*>(p + 8);
    uint32_t bh0, bh1, bl0, bl1;
    bh0 = packsplit(b0.x*32.f, b0.y*32.f, bl0);
    bh1 = packsplit(b1.x*32.f, b1.y*32.f, bl1);
    reinterpret_cast<uint4*>(&g_WS[(size_t)id*4])[0] = make_uint4(bh0,bh1,bl0,bl1);
}

// ======================= kernel 1: QKV GEMM (cp.async + f16 limbs) ===========
// CTA 128M x 128N, 8 warps (4M x 2N), warp tile 32x64. K chunk = 16.
// 4 smem buffers x 16KB, cp.async lookahead 2, one barrier per chunk.
// Chunk layout (uint32): Ahi[8fr][32ln][4] @0, Alo @1024, B[16fr][32ln][4] @2048
__global__ __launch_bounds__(256,2) void qkv_f16_kernel(
    const float* __restrict__ bq, const float* __restrict__ bk,
    const float* __restrict__ bv)
{
    const int gemm = blockIdx.z;
    const float* bias = (gemm == 0) ? bq : (gemm == 1) ? bk : bv;
    float* out = (gemm == 0) ? g_Q : (gemm == 1) ? g_K : g_V;

    const int n0 = blockIdx.x * 128;
    const int m0 = blockIdx.y * 128;

    extern __shared__ uint32_t smq[];
    const uint32_t smb = sm_u32(smq);

    const int t = threadIdx.x;
    const int lane = t & 31;
    const int wid  = t >> 5;
    const int warp_m = wid & 3;
    const int warp_n = wid >> 2;

    // ---- producer coords: frag fA = wid, lane lA ----
    const int fA = wid, lA = lane;
    const char* srcAh = (const char*)g_XS
        + ((size_t)((blockIdx.y*8 + fA)*64)*32 + lA)*16;           // +512B per chunk
    const char* srcAl = srcAh + XS_CELLS*16;
    const char* srcB1 = (const char*)g_WS
        + ((size_t)((gemm*128 + blockIdx.x*16 + fA)*64)*32 + lA)*16; // +512B per chunk
    const char* srcB2 = srcB1 + (size_t)8*64*32*16;
    const uint32_t dAh = (fA*32 + lA)*16;          // byte offsets in chunk
    const uint32_t dAl = dAh + 4096;
    const uint32_t dB1 = 8192 + (fA*32 + lA)*16;
    const uint32_t dB2 = dB1 + 4096;

    float acc[2][8][4];
    #pragma unroll
    for (int i = 0; i < 2; ++i)
        #pragma unroll
        for (int j = 0; j < 8; ++j)
            #pragma unroll
            for (int r = 0; r < 4; ++r) acc[i][j][r] = 0.0f;

    // ---- prologue: chunks 0,1 ----
    #pragma unroll
    for (int p = 0; p < 2; ++p) {
        const uint32_t b = smb + p*16384;
        cpasync16(b + dAh, srcAh + p*512);
        cpasync16(b + dAl, srcAl + p*512);
        cpasync16(b + dB1, srcB1 + p*512);
        cpasync16(b + dB2, srcB2 + p*512);
        CP_COMMIT();
    }

    #pragma unroll 1
    for (int c = 0; c < 64; ++c) {
        if (c + 2 < 64) {
            const uint32_t b = smb + ((c+2) & 3)*16384;
            cpasync16(b + dAh, srcAh + (size_t)(c+2)*512);
            cpasync16(b + dAl, srcAl + (size_t)(c+2)*512);
            cpasync16(b + dB1, srcB1 + (size_t)(c+2)*512);
            cpasync16(b + dB2, srcB2 + (size_t)(c+2)*512);
        }
        CP_COMMIT();          // uniform group count
        CP_WAIT2();           // chunk c complete
        __syncthreads();

        const uint32_t* C = smq + (c & 3)*4096;
        uint32_t ah[2][4], al[2][4];
        #pragma unroll
        for (int im = 0; im < 2; ++im) {
            const int base = ((warp_m*2 + im)*32 + lane)*4;
            *reinterpret_cast<uint4*>(ah[im]) = *reinterpret_cast<const uint4*>(&C[base]);
            *reinterpret_cast<uint4*>(al[im]) = *reinterpret_cast<const uint4*>(&C[base + 1024]);
        }
        #pragma unroll
        for (int in = 0; in < 8; ++in) {
            const int base = 2048 + ((warp_n*8 + in)*32 + lane)*4;
            uint4 q = *reinterpret_cast<const uint4*>(&C[base]);
            uint32_t bh[2] = {q.x, q.y};
            uint32_t bl[2] = {q.z, q.w};
            #pragma unroll
            for (int im = 0; im < 2; ++im) {
                mma16(acc[im][in], al[im], bh);
                mma16(acc[im][in], ah[im], bl);
                mma16(acc[im][in], ah[im], bh);
            }
        }
        __syncthreads();      // all reads of buf[c&3] done before c+4 overwrites
    }

    // ---- epilogue: acc/32 + bias -> gmem ----
    const float inv32 = 0.03125f;
    #pragma unroll
    for (int im = 0; im < 2; ++im) {
        const int m = m0 + warp_m*32 + im*16 + (lane >> 2);
        #pragma unroll
        for (int in = 0; in < 8; ++in) {
            const int n = n0 + warp_n*64 + in*8 + (lane & 3)*2;
            const float b0 = __ldg(&bias[n]);
            const float b1 = __ldg(&bias[n+1]);
            float2 v0 = make_float2(acc[im][in][0]*inv32 + b0, acc[im][in][1]*inv32 + b1);
            float2 v1 = make_float2(acc[im][in][2]*inv32 + b0, acc[im][in][3]*inv32 + b1);
            *reinterpret_cast<float2*>(&out[(size_t)m*Dm + n])     = v0;
            *reinterpret_cast<float2*>(&out[(size_t)(m+8)*Dm + n]) = v1;
        }
    }
}

// ---------------- kernel 0: zero vsum ---------------------------------------
__global__ void zero_vsum_kernel(){
    int i = blockIdx.x*blockDim.x + threadIdx.x;
    if (i < Bv*Dm) g_vsum[i] = 0.0f;
}

// ---------------- kernel 2: sparsity measure M -------------------------------
__global__ __launch_bounds__(128) void m_kernel(const int* __restrict__ idx_k){
    const int b = blockIdx.z, h = blockIdx.y;
    const int l0 = blockIdx.x * 128;
    __shared__ float Ks[Uv*DKv];
    __shared__ float Qs[128*65];
    const int t = threadIdx.x;

    for (int i = t; i < Uv*DKv; i += 128) {
        int u = i >> 6, d = i & 63;
        Ks[i] = g_K[(size_t)(b*Lv + idx_k[u])*Dm + h*DKv + d];
    }
    for (int i = t; i < 128*DKv; i += 128) {
        int r = i >> 6, d = i & 63;
        Qs[r*65 + d] = g_Q[(size_t)(b*Lv + l0 + r)*Dm + h*DKv + d];
    }
    __syncthreads();

    float acc[Uv];
    #pragma unroll
    for (int u = 0; u < Uv; ++u) acc[u] = 0.0f;

    for (int d = 0; d < DKv; ++d) {
        float qd = Qs[t*65 + d];
        #pragma unroll
        for (int u = 0; u < Uv; ++u) acc[u] += qd * Ks[u*DKv + d];
    }
    float mx = -1e30f, smv = 0.0f;
    #pragma unroll
    for (int u = 0; u < Uv; ++u) { mx = fmaxf(mx, acc[u]); smv += acc[u]; }
    g_M[(size_t)(b*Hh + h)*Lv + l0 + t] = mx - smv*(1.0f/Uv);
}

// ---------------- kernel 3: top-k (k=50 of 8192) per (b,h) -------------------
__global__ __launch_bounds__(256) void topk_kernel(){
    const int bh = blockIdx.x;
    __shared__ float vals[Lv];
    __shared__ float rv[256];
    __shared__ int   ri[256];
    const int t = threadIdx.x;

    for (int i = t; i < Lv; i += 256) vals[i] = g_M[(size_t)bh*Lv + i];
    __syncthreads();

    for (int it = 0; it < Uv; ++it) {
        float best = -1e30f; int bi = Lv;
        for (int i = t; i < Lv; i += 256) {
            float v = vals[i];
            if (v > best || (v == best && i < bi)) { best = v; bi = i; }
        }
        rv[t] = best; ri[t] = bi;
        __syncthreads();
        for (int s = 128; s > 0; s >>= 1) {
            if (t < s) {
                if (rv[t+s] > rv[t] || (rv[t+s] == rv[t] && ri[t+s] < ri[t])) {
                    rv[t] = rv[t+s]; ri[t] = ri[t+s];
                }
            }
            __syncthreads();
        }
        if (t == 0) { g_top[bh*Uv + it] = ri[0]; vals[ri[0]] = -1e30f; }
        __syncthreads();
    }
}

// ---------------- kernel 4: V column sums (for mean) -------------------------
__global__ void vsum_kernel(){
    const int b = blockIdx.z;
    const int d = blockIdx.x*128 + threadIdx.x;
    const int c = blockIdx.y;
    float s = 0.0f;
    const int lbeg = c*256, lend = lbeg + 256;
    for (int l = lbeg; l < lend; ++l) s += g_V[(size_t)(b*Lv + l)*Dm + d];
    atomicAdd(&g_vsum[b*Dm + d], s);
}

// ---------------- kernel 5: flash attention for top queries (split-K) --------
__global__ __launch_bounds__(512) void attn_partial_kernel(){
    const int bh = blockIdx.x;
    const int sp = blockIdx.y;
    const int b = bh / Hh, h = bh % Hh;
    const int t = threadIdx.x;

    __shared__ float Qs[Uv][DKv];
    __shared__ float Ks[TK][65];
    __shared__ float Vs[TK][65];
    __shared__ float Ps[Uv][33];
    __shared__ float m_s[Uv], l_s[Uv], c_s[Uv];

    for (int i = t; i < Uv*DKv; i += 512) {
        int q = i >> 6, d = i & 63;
        int l = g_top[bh*Uv + q];
        Qs[q][d] = g_Q[(size_t)(b*Lv + l)*Dm + h*DKv + d];
    }
    if (t < Uv) { m_s[t] = -1e30f; l_s[t] = 0.0f; }

    float ctx[7];
    #pragma unroll
    for (int j = 0; j < 7; ++j) ctx[j] = 0.0f;
    const int d = t & 63;
    const int qb = t >> 6;

    __syncthreads();

    for (int l0 = sp*LSPL; l0 < (sp+1)*LSPL; l0 += TK) {
        for (int i = t; i < TK*DKv; i += 512) {
            int kk = i >> 6, dd = i & 63;
            size_t g = (size_t)(b*Lv + l0 + kk)*Dm + h*DKv + dd;
            Ks[kk][dd] = g_K[g];
            Vs[kk][dd] = g_V[g];
        }
        __syncthreads();

        if (t < 400) {
            const int q = t >> 3, kg = t & 7;
            float a0 = 0.f, a1 = 0.f, a2 = 0.f, a3 = 0.f;
            for (int dd = 0; dd < DKv; ++dd) {
                float qv = Qs[q][dd];
                a0 += qv * Ks[kg][dd];
                a1 += qv * Ks[kg+8][dd];
                a2 += qv * Ks[kg+16][dd];
                a3 += qv * Ks[kg+24][dd];
            }
            Ps[q][kg]    = a0 * 0.125f;
            Ps[q][kg+8]  = a1 * 0.125f;
            Ps[q][kg+16] = a2 * 0.125f;
            Ps[q][kg+24] = a3 * 0.125f;
        }
        __syncthreads();

        if (t < Uv) {
            float tm = -1e30f;
            #pragma unroll
            for (int k = 0; k < TK; ++k) tm = fmaxf(tm, Ps[t][k]);
            float nm = fmaxf(m_s[t], tm);
            float cc = __expf(m_s[t] - nm);
            float ls = l_s[t]*cc;
            #pragma unroll
            for (int k = 0; k < TK; ++k) {
                float p = __expf(Ps[t][k] - nm);
                Ps[t][k] = p;
                ls += p;
            }
            m_s[t] = nm; l_s[t] = ls; c_s[t] = cc;
        }
        __syncthreads();

        #pragma unroll
        for (int j = 0; j < 7; ++j) {
            int q = qb + 8*j;
            if (q < Uv) {
                float a = ctx[j] * c_s[q];
                #pragma unroll
                for (int k = 0; k < TK; ++k) a += Ps[q][k] * Vs[k][d];
                ctx[j] = a;
            }
        }
        __syncthreads();
    }

    #pragma unroll
    for (int j = 0; j < 7; ++j) {
        int q = qb + 8*j;
        if (q < Uv)
            g_pctx[(size_t)((bh*SPLIT + sp)*Uv + q)*DKv + d] = ctx[j];
    }
    if (t < Uv) {
        g_pm[(bh*SPLIT + sp)*Uv + t] = m_s[t];
        g_pl[(bh*SPLIT + sp)*Uv + t] = l_s[t];
    }
}

// ---------------- kernel 6: combine split partials ---------------------------
__global__ __launch_bounds__(64) void attn_combine_kernel(){
    const int i = blockIdx.x;
    const int q = i % Uv, bh = i / Uv;
    __shared__ float w[SPLIT];
    __shared__ float inv;
    if (threadIdx.x == 0) {
        float M = -1e30f;
        for (int s = 0; s < SPLIT; ++s) M = fmaxf(M, g_pm[(bh*SPLIT+s)*Uv + q]);
        float tot = 0.f;
        for (int s = 0; s < SPLIT; ++s) {
            float e = __expf(g_pm[(bh*SPLIT+s)*Uv + q] - M);
            w[s] = e;
            tot += g_pl[(bh*SPLIT+s)*Uv + q] * e;
        }
        inv = 1.0f / tot;
    }
    __syncthreads();
    const int d = threadIdx.x;
    float c = 0.f;
    for (int s = 0; s < SPLIT; ++s)
        c += g_pctx[(size_t)((bh*SPLIT+s)*Uv + q)*DKv + d] * w[s];
    g_ctx[(size_t)i*DKv + d] = c * inv;
}

// ---------------- kernel 7: base output row per batch ------------------------
__global__ __launch_bounds__(256) void base_kernel(const float* __restrict__ Wo,
                                                   const float* __restrict__ bo){
    const int b = blockIdx.y;
    const int warp = threadIdx.x >> 5, lane = threadIdx.x & 31;
    const int j = blockIdx.x*8 + warp;
    float s = 0.f;
    for (int d0 = lane; d0 < Dm; d0 += 32)
        s += g_vsum[b*Dm + d0] * Wo[(size_t)j*Dm + d0];
    #pragma unroll
    for (int o = 16; o; o >>= 1) s += __shfl_down_sync(0xffffffffu, s, o);
    if (lane == 0) g_base[b*Dm + j] = s*(1.0f/Lv) + bo[j];
}

// ---------------- kernel 8: broadcast base rows into output -------------------
__global__ void fill_kernel(float* __restrict__ out){
    const int i = blockIdx.x*blockDim.x + threadIdx.x;
    const int b  = i >> 21;
    const int j4 = i & 255;
    float4 v = *reinterpret_cast<const float4*>(&g_base[b*Dm + j4*4]);
    reinterpret_cast<float4*>(out)[i] = v;
}

// ---------------- kernel 9: rank-64 corrections for top rows ------------------
__global__ __launch_bounds__(256) void corr_kernel(const float* __restrict__ Wo,
                                                   float* __restrict__ out){
    const int i = blockIdx.x;
    const int bh = i / Uv;
    const int b = bh / Hh, h = bh % Hh;
    const int l = g_top[i];
    __shared__ float delta[DKv];
    const int t = threadIdx.x;
    if (t < DKv)
        delta[t] = g_ctx[(size_t)i*DKv + t] - g_vsum[b*Dm + h*DKv + t]*(1.0f/Lv);
    __syncthreads();
    for (int j = t; j < Dm; j += 256) {
        const float4* wr = reinterpret_cast<const float4*>(Wo + (size_t)j*Dm + h*DKv);
        float s = 0.f;
        #pragma unroll
        for (int dd = 0; dd < 16; ++dd) {
            float4 wv = wr[dd];
            s += delta[dd*4+0]*wv.x + delta[dd*4+1]*wv.y
               + delta[dd*4+2]*wv.z + delta[dd*4+3]*wv.w;
        }
        atomicAdd(&out[(size_t)(b*Lv + l)*Dm + j], s);
    }
}

// ---------------- launch ------------------------------------------------------
extern "C" void kernel_launch(void* const* d_in, const int* in_sizes, int n_in,
                              void* d_out, int out_size)
{
    const float* x    = (const float*)d_in[0];
    const float* Wq   = (const float*)d_in[1];
    const float* bq   = (const float*)d_in[2];
    const float* Wk   = (const float*)d_in[3];
    const float* bk   = (const float*)d_in[4];
    const float* Wv   = (const float*)d_in[5];
    const float* bv   = (const float*)d_in[6];
    const float* Wo   = (const float*)d_in[7];
    const float* bo   = (const float*)d_in[8];
    const int*   idxk = (const int*)d_in[9];
    float* out = (float*)d_out;

    static bool attr_set = false;
    if (!attr_set) {
        cudaFuncSetAttribute(qkv_f16_kernel,
                             cudaFuncAttributeMaxDynamicSharedMemorySize, 65536);
        attr_set = true;
    }

    zero_vsum_kernel<<<(Bv*Dm)/256, 256>>>();
    split_x_kernel<<<(2048*64*32)/256, 256>>>(x);
    split_w_kernel<<<(3*128*64*32)/256, 256>>>(Wq, Wk, Wv);
    qkv_f16_kernel<<<dim3(Dm/128, BLv/128, 3), 256, 65536>>>(bq, bk, bv);
    m_kernel<<<dim3(Lv/128, Hh, Bv), 128>>>(idxk);
    vsum_kernel<<<dim3(Dm/128, Lv/256, Bv), 128>>>();
    topk_kernel<<<Bv*Hh, 256>>>();
    attn_partial_kernel<<<dim3(Bv*Hh, SPLIT), 512>>>();
    attn_combine_kernel<<<Bv*Hh*Uv, 64>>>();
    base_kernel<<<dim3(Dm/8, Bv), 256>>>(Wo, bo);
    fill_kernel<<<(BLv*Dm/4)/256, 256>>>(out);
    corr_kernel<<<Bv*Hh*Uv, 256>>>(Wo, out);
}

// round 9
// speedup vs baseline: 2.9829x; 1.0608x over previous
#include <cuda_runtime.h>
#include <cuda_fp16.h>
#include <math.h>
#include <stdint.h>

#define Bv 4
#define Lv 8192
#define Dm 1024
#define Hh 16
#define DKv 64
#define Uv 50
#define BLv (Bv*Lv)            // 32768
#define SPLIT 8
#define LSPL (Lv/SPLIT)        // 1024
#define TK 32

// ---------------- scratch (device globals; no allocations allowed) ----------
#define XS_CELLS ((size_t)2048*64*32)
__device__ float g_Q[BLv*Dm];          // 128 MB
__device__ float g_K[BLv*Dm];          // 128 MB
__device__ float g_V[BLv*Dm];          // 128 MB
__device__ uint32_t g_XS[XS_CELLS*8];             // 128 MB: X limbs, hi plane then lo plane
__device__ uint32_t g_WS[(size_t)3*128*64*32*4];  // 12 MB: W limbs (x32), frag order
__device__ float g_M[Bv*Hh*Lv];
__device__ int   g_top[Bv*Hh*Uv];
__device__ float g_pm[Bv*Hh*SPLIT*Uv];
__device__ float g_pl[Bv*Hh*SPLIT*Uv];
__device__ float g_pctx[Bv*Hh*SPLIT*Uv*DKv];
__device__ float g_ctx[Bv*Hh*Uv*DKv];
__device__ float g_vsum[Bv*Dm];
__device__ float g_base[Bv*Dm];

// ---------------- helpers ----------------------------------------------------
__device__ __forceinline__ uint32_t packsplit(float x, float y, uint32_t &lo){
    __half hx = __float2half_rn(x);
    __half hy = __float2half_rn(y);
    __half lx = __float2half_rn(x - __half2float(hx));
    __half ly = __float2half_rn(y - __half2float(hy));
    __half2 h2 = __halves2half2(hx, hy);
    __half2 l2 = __halves2half2(lx, ly);
    lo = *reinterpret_cast<uint32_t*>(&l2);
    return *reinterpret_cast<uint32_t*>(&h2);
}

__device__ __forceinline__ void mma16(float* c, const uint32_t* a, const uint32_t* b){
    asm volatile(
        "mma.sync.aligned.m16n8k16.row.col.f32.f16.f16.f32 "
        "{%0,%1,%2,%3}, {%4,%5,%6,%7}, {%8,%9}, {%0,%1,%2,%3};"
        : "+f"(c[0]), "+f"(c[1]), "+f"(c[2]), "+f"(c[3])
        : "r"(a[0]), "r"(a[1]), "r"(a[2]), "r"(a[3]), "r"(b[0]), "r"(b[1]));
}

__device__ __forceinline__ uint32_t sm_u32(const void* p){
    uint32_t a;
    asm("{ .reg .u64 t; cvta.to.shared.u64 t, %1; cvt.u32.u64 %0, t; }"
        : "=r"(a) : "l"(p));
    return a;
}

__device__ __forceinline__ void cpasync16(uint32_t dst, const void* src){
    asm volatile("cp.async.cg.shared.global [%0], [%1], 16;"
                 :: "r"(dst), "l"(src) : "memory");
}
#define CP_COMMIT() asm volatile("cp.async.commit_group;" ::: "memory")
#define CP_WAIT1()  asm volatile("cp.async.wait_group 1;" ::: "memory")

// ---------------- kernel A: split X into limb planes (frag order) -----------
__global__ __launch_bounds__(256) void split_x_kernel(const float* __restrict__ X){
    const int id = blockIdx.x*256 + threadIdx.x;
    const int mb   = id >> 11;
    const int c    = (id >> 5) & 63;
    const int lane = id & 31;
    const int r0 = mb*16 + (lane >> 2);
    const int k0 = c*16 + 2*(lane & 3);
    const float* p0 = X + (size_t)r0*Dm + k0;
    float2 a00 = *reinterpret_cast<const float2*>(p0);
    float2 a10 = *reinterpret_cast<const float2*>(p0 + 8*Dm);
    float2 a01 = *reinterpret_cast<const float2*>(p0 + 8);
    float2 a11 = *reinterpret_cast<const float2*>(p0 + 8*Dm + 8);
    uint32_t h0,h1,h2,h3, l0,l1,l2,l3;
    h0 = packsplit(a00.x, a00.y, l0);
    h1 = packsplit(a10.x, a10.y, l1);
    h2 = packsplit(a01.x, a01.y, l2);
    h3 = packsplit(a11.x, a11.y, l3);
    *reinterpret_cast<uint4*>(&g_XS[(size_t)id*4])              = make_uint4(h0,h1,h2,h3);
    *reinterpret_cast<uint4*>(&g_XS[XS_CELLS*4 + (size_t)id*4]) = make_uint4(l0,l1,l2,l3);
}

// ---------------- kernel B: split W (x32) into fragment-ordered limbs --------
__global__ __launch_bounds__(256) void split_w_kernel(
    const float* __restrict__ Wq, const float* __restrict__ Wk,
    const float* __restrict__ Wv)
{
    const int id = blockIdx.x*256 + threadIdx.x;
    const int gemm = id >> 18;
    const int rem  = id & 262143;
    const int nb   = rem >> 11;
    const int c    = (rem >> 5) & 63;
    const int lane = rem & 31;
    const float* W = (gemm == 0) ? Wq : (gemm == 1) ? Wk : Wv;
    const int row = nb*8 + (lane >> 2);
    const int k0  = c*16 + 2*(lane & 3);
    const float* p = W + (size_t)row*Dm + k0;
    float2 b0 = *reinterpret_cast<const float2*>(p);
    float2 b1 = *reinterpret_cast<const float2*>(p + 8);
    uint32_t bh0, bh1, bl0, bl1;
    bh0 = packsplit(b0.x*32.f, b0.y*32.f, bl0);
    bh1 = packsplit(b1.x*32.f, b1.y*32.f, bl1);
    reinterpret_cast<uint4*>(&g_WS[(size_t)id*4])[0] = make_uint4(bh0,bh1,bl0,bl1);
}

// ======================= kernel 1: QKV GEMM (cp.async + f16 limbs) ===========
// CTA 128M x 128N, 8 warps (4M x 2N), warp tile 32x64. K chunk = 16.
// 4 smem buffers x 16KB, cp.async lookahead 2, ONE barrier per chunk.
__global__ __launch_bounds__(256,2) void qkv_f16_kernel(
    const float* __restrict__ bq, const float* __restrict__ bk,
    const float* __restrict__ bv)
{
    const int gemm = blockIdx.z;
    const float* bias = (gemm == 0) ? bq : (gemm == 1) ? bk : bv;
    float* out = (gemm == 0) ? g_Q : (gemm == 1) ? g_K : g_V;

    const int n0 = blockIdx.x * 128;
    const int m0 = blockIdx.y * 128;

    extern __shared__ uint32_t smq[];
    const uint32_t smb = sm_u32(smq);

    const int t = threadIdx.x;
    const int lane = t & 31;
    const int wid  = t >> 5;
    const int warp_m = wid & 3;
    const int warp_n = wid >> 2;

    const int fA = wid, lA = lane;
    const char* srcAh = (const char*)g_XS
        + ((size_t)((blockIdx.y*8 + fA)*64)*32 + lA)*16;
    const char* srcAl = srcAh + XS_CELLS*16;
    const char* srcB1 = (const char*)g_WS
        + ((size_t)((gemm*128 + blockIdx.x*16 + fA)*64)*32 + lA)*16;
    const char* srcB2 = srcB1 + (size_t)8*64*32*16;
    const uint32_t dAh = (fA*32 + lA)*16;
    const uint32_t dAl = dAh + 4096;
    const uint32_t dB1 = 8192 + (fA*32 + lA)*16;
    const uint32_t dB2 = dB1 + 4096;

    float acc[2][8][4];
    #pragma unroll
    for (int i = 0; i < 2; ++i)
        #pragma unroll
        for (int j = 0; j < 8; ++j)
            #pragma unroll
            for (int r = 0; r < 4; ++r) acc[i][j][r] = 0.0f;

    // prologue: chunks 0,1
    #pragma unroll
    for (int p = 0; p < 2; ++p) {
        const uint32_t b = smb + p*16384;
        cpasync16(b + dAh, srcAh + p*512);
        cpasync16(b + dAl, srcAl + p*512);
        cpasync16(b + dB1, srcB1 + p*512);
        cpasync16(b + dB2, srcB2 + p*512);
        CP_COMMIT();
    }

    #pragma unroll 1
    for (int c = 0; c < 64; ++c) {
        CP_WAIT1();           // chunk c complete (chunk c+1 may be in flight)
        __syncthreads();      // all smem visible; all threads past compute c-1

        if (c + 2 < 64) {
            const uint32_t b = smb + ((c+2) & 3)*16384;
            cpasync16(b + dAh, srcAh + (size_t)(c+2)*512);
            cpasync16(b + dAl, srcAl + (size_t)(c+2)*512);
            cpasync16(b + dB1, srcB1 + (size_t)(c+2)*512);
            cpasync16(b + dB2, srcB2 + (size_t)(c+2)*512);
        }
        CP_COMMIT();          // uniform group count

        const uint32_t* C = smq + (c & 3)*4096;
        uint32_t ah[2][4], al[2][4];
        #pragma unroll
        for (int im = 0; im < 2; ++im) {
            const int base = ((warp_m*2 + im)*32 + lane)*4;
            *reinterpret_cast<uint4*>(ah[im]) = *reinterpret_cast<const uint4*>(&C[base]);
            *reinterpret_cast<uint4*>(al[im]) = *reinterpret_cast<const uint4*>(&C[base + 1024]);
        }
        #pragma unroll
        for (int in = 0; in < 8; ++in) {
            const int base = 2048 + ((warp_n*8 + in)*32 + lane)*4;
            uint4 q = *reinterpret_cast<const uint4*>(&C[base]);
            uint32_t bh[2] = {q.x, q.y};
            uint32_t bl[2] = {q.z, q.w};
            #pragma unroll
            for (int im = 0; im < 2; ++im) {
                mma16(acc[im][in], al[im], bh);
                mma16(acc[im][in], ah[im], bl);
                mma16(acc[im][in], ah[im], bh);
            }
        }
    }

    // epilogue
    const float inv32 = 0.03125f;
    #pragma unroll
    for (int im = 0; im < 2; ++im) {
        const int m = m0 + warp_m*32 + im*16 + (lane >> 2);
        #pragma unroll
        for (int in = 0; in < 8; ++in) {
            const int n = n0 + warp_n*64 + in*8 + (lane & 3)*2;
            const float b0 = __ldg(&bias[n]);
            const float b1 = __ldg(&bias[n+1]);
            float2 v0 = make_float2(acc[im][in][0]*inv32 + b0, acc[im][in][1]*inv32 + b1);
            float2 v1 = make_float2(acc[im][in][2]*inv32 + b0, acc[im][in][3]*inv32 + b1);
            *reinterpret_cast<float2*>(&out[(size_t)m*Dm + n])     = v0;
            *reinterpret_cast<float2*>(&out[(size_t)(m+8)*Dm + n]) = v1;
        }
    }
}

// ---------------- kernel 0: zero vsum ---------------------------------------
__global__ void zero_vsum_kernel(){
    int i = blockIdx.x*blockDim.x + threadIdx.x;
    if (i < Bv*Dm) g_vsum[i] = 0.0f;
}

// ---------------- kernel 2: sparsity measure M (float4 vectorized) ----------
__global__ __launch_bounds__(128) void m_kernel(const int* __restrict__ idx_k){
    const int b = blockIdx.z, h = blockIdx.y;
    const int l0 = blockIdx.x * 128;
    __shared__ float Ks[Uv*DKv];      // 12.8 KB
    __shared__ float Qs[128*68];      // 34.8 KB (68 keeps float4 rows, conflict-free)
    const int t = threadIdx.x;

    for (int i = t; i < Uv*DKv; i += 128) {
        int u = i >> 6, d = i & 63;
        Ks[i] = g_K[(size_t)(b*Lv + idx_k[u])*Dm + h*DKv + d];
    }
    for (int i = t; i < 128*DKv; i += 128) {
        int r = i >> 6, d = i & 63;
        Qs[r*68 + d] = g_Q[(size_t)(b*Lv + l0 + r)*Dm + h*DKv + d];
    }
    __syncthreads();

    float acc[Uv];
    #pragma unroll
    for (int u = 0; u < Uv; ++u) acc[u] = 0.0f;

    #pragma unroll
    for (int dq = 0; dq < 16; ++dq) {
        float4 qv = *reinterpret_cast<const float4*>(&Qs[t*68 + dq*4]);
        #pragma unroll
        for (int u = 0; u < Uv; ++u) {
            float4 kv = *reinterpret_cast<const float4*>(&Ks[u*DKv + dq*4]);
            acc[u] += qv.x*kv.x + qv.y*kv.y + qv.z*kv.z + qv.w*kv.w;
        }
    }
    float mx = -1e30f, smv = 0.0f;
    #pragma unroll
    for (int u = 0; u < Uv; ++u) { mx = fmaxf(mx, acc[u]); smv += acc[u]; }
    g_M[(size_t)(b*Hh + h)*Lv + l0 + t] = mx - smv*(1.0f/Uv);
}

// ---------------- kernel 3: top-k (k=50 of 8192) per (b,h) -------------------
__global__ __launch_bounds__(256) void topk_kernel(){
    const int bh = blockIdx.x;
    __shared__ float vals[Lv];
    __shared__ float rv[256];
    __shared__ int   ri[256];
    const int t = threadIdx.x;

    for (int i = t; i < Lv; i += 256) vals[i] = g_M[(size_t)bh*Lv + i];
    __syncthreads();

    for (int it = 0; it < Uv; ++it) {
        float best = -1e30f; int bi = Lv;
        for (int i = t; i < Lv; i += 256) {
            float v = vals[i];
            if (v > best || (v == best && i < bi)) { best = v; bi = i; }
        }
        rv[t] = best; ri[t] = bi;
        __syncthreads();
        for (int s = 128; s > 0; s >>= 1) {
            if (t < s) {
                if (rv[t+s] > rv[t] || (rv[t+s] == rv[t] && ri[t+s] < ri[t])) {
                    rv[t] = rv[t+s]; ri[t] = ri[t+s];
                }
            }
            __syncthreads();
        }
        if (t == 0) { g_top[bh*Uv + it] = ri[0]; vals[ri[0]] = -1e30f; }
        __syncthreads();
    }
}

// ---------------- kernel 4: V column sums (for mean) -------------------------
__global__ void vsum_kernel(){
    const int b = blockIdx.z;
    const int d = blockIdx.x*128 + threadIdx.x;
    const int c = blockIdx.y;
    float s = 0.0f;
    const int lbeg = c*256, lend = lbeg + 256;
    for (int l = lbeg; l < lend; ++l) s += g_V[(size_t)(b*Lv + l)*Dm + d];
    atomicAdd(&g_vsum[b*Dm + d], s);
}

// ---------------- kernel 5: flash attention (float4-vectorized, SPLIT=8) -----
__global__ __launch_bounds__(512) void attn_partial_kernel(){
    const int bh = blockIdx.x;
    const int sp = blockIdx.y;
    const int b = bh / Hh, h = bh % Hh;
    const int t = threadIdx.x;

    __shared__ float Qs[Uv][DKv];        // 12.8 KB (256B rows, float4 OK)
    __shared__ float Ks[TK][68];         // 8.7 KB
    __shared__ float Vs[TK][68];         // 8.7 KB
    __shared__ float Ps[Uv][36];         // 7.2 KB (144B rows, float4 OK)
    __shared__ float m_s[Uv], l_s[Uv], c_s[Uv];

    for (int i = t; i < Uv*DKv; i += 512) {
        int q = i >> 6, d = i & 63;
        int l = g_top[bh*Uv + q];
        Qs[q][d] = g_Q[(size_t)(b*Lv + l)*Dm + h*DKv + d];
    }
    if (t < Uv) { m_s[t] = -1e30f; l_s[t] = 0.0f; }

    float ctx[7];
    #pragma unroll
    for (int j = 0; j < 7; ++j) ctx[j] = 0.0f;
    const int d = t & 63;
    const int qb = t >> 6;

    // K/V loader coords: one float4 of K and V per thread per tile
    const int ldrow = t >> 4;            // 0..31
    const int lddq  = t & 15;            // 0..15

    __syncthreads();

    for (int l0 = sp*LSPL; l0 < (sp+1)*LSPL; l0 += TK) {
        {
            size_t g = (size_t)(b*Lv + l0 + ldrow)*Dm + h*DKv + lddq*4;
            float4 kv = *reinterpret_cast<const float4*>(&g_K[g]);
            float4 vv = *reinterpret_cast<const float4*>(&g_V[g]);
            *reinterpret_cast<float4*>(&Ks[ldrow][lddq*4]) = kv;
            *reinterpret_cast<float4*>(&Vs[ldrow][lddq*4]) = vv;
        }
        __syncthreads();

        if (t < 400) {                       // 50 q * 8 key-groups
            const int q = t >> 3, kg = t & 7;
            float a0 = 0.f, a1 = 0.f, a2 = 0.f, a3 = 0.f;
            #pragma unroll
            for (int dq = 0; dq < 16; ++dq) {
                float4 qv = *reinterpret_cast<const float4*>(&Qs[q][dq*4]);
                float4 k0 = *reinterpret_cast<const float4*>(&Ks[kg][dq*4]);
                float4 k1 = *reinterpret_cast<const float4*>(&Ks[kg+8][dq*4]);
                float4 k2 = *reinterpret_cast<const float4*>(&Ks[kg+16][dq*4]);
                float4 k3 = *reinterpret_cast<const float4*>(&Ks[kg+24][dq*4]);
                a0 += qv.x*k0.x + qv.y*k0.y + qv.z*k0.z + qv.w*k0.w;
                a1 += qv.x*k1.x + qv.y*k1.y + qv.z*k1.z + qv.w*k1.w;
                a2 += qv.x*k2.x + qv.y*k2.y + qv.z*k2.z + qv.w*k2.w;
                a3 += qv.x*k3.x + qv.y*k3.y + qv.z*k3.z + qv.w*k3.w;
            }
            Ps[q][kg]    = a0 * 0.125f;
            Ps[q][kg+8]  = a1 * 0.125f;
            Ps[q][kg+16] = a2 * 0.125f;
            Ps[q][kg+24] = a3 * 0.125f;
        }
        __syncthreads();

        if (t < Uv) {
            float tm = -1e30f;
            #pragma unroll
            for (int k = 0; k < TK; ++k) tm = fmaxf(tm, Ps[t][k]);
            float nm = fmaxf(m_s[t], tm);
            float cc = __expf(m_s[t] - nm);
            float ls = l_s[t]*cc;
            #pragma unroll
            for (int k = 0; k < TK; ++k) {
                float p = __expf(Ps[t][k] - nm);
                Ps[t][k] = p;
                ls += p;
            }
            m_s[t] = nm; l_s[t] = ls; c_s[t] = cc;
        }
        __syncthreads();

        // ctx update: V column in registers, P rows via float4 broadcast
        {
            float vreg[TK];
            #pragma unroll
            for (int k = 0; k < TK; ++k) vreg[k] = Vs[k][d];
            #pragma unroll
            for (int j = 0; j < 7; ++j) {
                int q = qb + 8*j;
                if (q < Uv) {
                    float a = ctx[j] * c_s[q];
                    #pragma unroll
                    for (int kq = 0; kq < 8; ++kq) {
                        float4 p = *reinterpret_cast<const float4*>(&Ps[q][kq*4]);
                        a += p.x*vreg[kq*4] + p.y*vreg[kq*4+1]
                           + p.z*vreg[kq*4+2] + p.w*vreg[kq*4+3];
                    }
                    ctx[j] = a;
                }
            }
        }
        __syncthreads();
    }

    #pragma unroll
    for (int j = 0; j < 7; ++j) {
        int q = qb + 8*j;
        if (q < Uv)
            g_pctx[(size_t)((bh*SPLIT + sp)*Uv + q)*DKv + d] = ctx[j];
    }
    if (t < Uv) {
        g_pm[(bh*SPLIT + sp)*Uv + t] = m_s[t];
        g_pl[(bh*SPLIT + sp)*Uv + t] = l_s[t];
    }
}

// ---------------- kernel 6: combine split partials ---------------------------
__global__ __launch_bounds__(64) void attn_combine_kernel(){
    const int i = blockIdx.x;
    const int q = i % Uv, bh = i / Uv;
    __shared__ float w[SPLIT];
    __shared__ float inv;
    if (threadIdx.x == 0) {
        float M = -1e30f;
        for (int s = 0; s < SPLIT; ++s) M = fmaxf(M, g_pm[(bh*SPLIT+s)*Uv + q]);
        float tot = 0.f;
        for (int s = 0; s < SPLIT; ++s) {
            float e = __expf(g_pm[(bh*SPLIT+s)*Uv + q] - M);
            w[s] = e;
            tot += g_pl[(bh*SPLIT+s)*Uv + q] * e;
        }
        inv = 1.0f / tot;
    }
    __syncthreads();
    const int d = threadIdx.x;
    float c = 0.f;
    for (int s = 0; s < SPLIT; ++s)
        c += g_pctx[(size_t)((bh*SPLIT+s)*Uv + q)*DKv + d] * w[s];
    g_ctx[(size_t)i*DKv + d] = c * inv;
}

// ---------------- kernel 7: base output row per batch ------------------------
__global__ __launch_bounds__(256) void base_kernel(const float* __restrict__ Wo,
                                                   const float* __restrict__ bo){
    const int b = blockIdx.y;
    const int warp = threadIdx.x >> 5, lane = threadIdx.x & 31;
    const int j = blockIdx.x*8 + warp;
    float s = 0.f;
    for (int d0 = lane; d0 < Dm; d0 += 32)
        s += g_vsum[b*Dm + d0] * Wo[(size_t)j*Dm + d0];
    #pragma unroll
    for (int o = 16; o; o >>= 1) s += __shfl_down_sync(0xffffffffu, s, o);
    if (lane == 0) g_base[b*Dm + j] = s*(1.0f/Lv) + bo[j];
}

// ---------------- kernel 8: broadcast base rows into output -------------------
__global__ void fill_kernel(float* __restrict__ out){
    const int i = blockIdx.x*blockDim.x + threadIdx.x;
    const int b  = i >> 21;
    const int j4 = i & 255;
    float4 v = *reinterpret_cast<const float4*>(&g_base[b*Dm + j4*4]);
    reinterpret_cast<float4*>(out)[i] = v;
}

// ---------------- kernel 9: rank-64 corrections for top rows ------------------
__global__ __launch_bounds__(256) void corr_kernel(const float* __restrict__ Wo,
                                                   float* __restrict__ out){
    const int i = blockIdx.x;
    const int bh = i / Uv;
    const int b = bh / Hh, h = bh % Hh;
    const int l = g_top[i];
    __shared__ float delta[DKv];
    const int t = threadIdx.x;
    if (t < DKv)
        delta[t] = g_ctx[(size_t)i*DKv + t] - g_vsum[b*Dm + h*DKv + t]*(1.0f/Lv);
    __syncthreads();
    for (int j = t; j < Dm; j += 256) {
        const float4* wr = reinterpret_cast<const float4*>(Wo + (size_t)j*Dm + h*DKv);
        float s = 0.f;
        #pragma unroll
        for (int dd = 0; dd < 16; ++dd) {
            float4 wv = wr[dd];
            s += delta[dd*4+0]*wv.x + delta[dd*4+1]*wv.y
               + delta[dd*4+2]*wv.z + delta[dd*4+3]*wv.w;
        }
        atomicAdd(&out[(size_t)(b*Lv + l)*Dm + j], s);
    }
}

// ---------------- launch ------------------------------------------------------
extern "C" void kernel_launch(void* const* d_in, const int* in_sizes, int n_in,
                              void* d_out, int out_size)
{
    const float* x    = (const float*)d_in[0];
    const float* Wq   = (const float*)d_in[1];
    const float* bq   = (const float*)d_in[2];
    const float* Wk   = (const float*)d_in[3];
    const float* bk   = (const float*)d_in[4];
    const float* Wv   = (const float*)d_in[5];
    const float* bv   = (const float*)d_in[6];
    const float* Wo   = (const float*)d_in[7];
    const float* bo   = (const float*)d_in[8];
    const int*   idxk = (const int*)d_in[9];
    float* out = (float*)d_out;

    static bool attr_set = false;
    if (!attr_set) {
        cudaFuncSetAttribute(qkv_f16_kernel,
                             cudaFuncAttributeMaxDynamicSharedMemorySize, 65536);
        attr_set = true;
    }

    zero_vsum_kernel<<<(Bv*Dm)/256, 256>>>();
    split_x_kernel<<<(2048*64*32)/256, 256>>>(x);
    split_w_kernel<<<(3*128*64*32)/256, 256>>>(Wq, Wk, Wv);
    qkv_f16_kernel<<<dim3(Dm/128, BLv/128, 3), 256, 65536>>>(bq, bk, bv);
    m_kernel<<<dim3(Lv/128, Hh, Bv), 128>>>(idxk);
    vsum_kernel<<<dim3(Dm/128, Lv/256, Bv), 128>>>();
    topk_kernel<<<Bv*Hh, 256>>>();
    attn_partial_kernel<<<dim3(Bv*Hh, SPLIT), 512>>>();
    attn_combine_kernel<<<Bv*Hh*Uv, 64>>>();
    base_kernel<<<dim3(Dm/8, Bv), 256>>>(Wo, bo);
    fill_kernel<<<(BLv*Dm/4)/256, 256>>>(out);
    corr_kernel<<<Bv*Hh*Uv, 256>>>(Wo, out);
}

// round 10
// speedup vs baseline: 3.0280x; 1.0151x over previous
#include <cuda_runtime.h>
#include <cuda_fp16.h>
#include <math.h>
#include <stdint.h>

#define Bv 4
#define Lv 8192
#define Dm 1024
#define Hh 16
#define DKv 64
#define Uv 50
#define BLv (Bv*Lv)            // 32768
#define SPLIT 8
#define LSPL (Lv/SPLIT)        // 1024
#define TK 32

// ---------------- scratch (device globals; no allocations allowed) ----------
#define XS_CELLS ((size_t)2048*64*32)
__device__ float g_Q[BLv*Dm];          // 128 MB
__device__ float g_K[BLv*Dm];          // 128 MB
__device__ float g_V[BLv*Dm];          // 128 MB
__device__ uint32_t g_XS[XS_CELLS*8];             // 128 MB: X limbs, hi plane then lo plane
__device__ uint32_t g_WS[(size_t)3*128*64*32*4];  // 12 MB: W limbs (x32), frag order
__device__ float g_M[Bv*Hh*Lv];
__device__ int   g_top[Bv*Hh*Uv];
__device__ float g_pm[Bv*Hh*SPLIT*Uv];
__device__ float g_pl[Bv*Hh*SPLIT*Uv];
__device__ float g_pctx[Bv*Hh*SPLIT*Uv*DKv];
__device__ float g_ctx[Bv*Hh*Uv*DKv];
__device__ float g_vsum[Bv*Dm];
__device__ float g_base[Bv*Dm];

// ---------------- helpers ----------------------------------------------------
__device__ __forceinline__ uint32_t packsplit(float x, float y, uint32_t &lo){
    __half hx = __float2half_rn(x);
    __half hy = __float2half_rn(y);
    __half lx = __float2half_rn(x - __half2float(hx));
    __half ly = __float2half_rn(y - __half2float(hy));
    __half2 h2 = __halves2half2(hx, hy);
    __half2 l2 = __halves2half2(lx, ly);
    lo = *reinterpret_cast<uint32_t*>(&l2);
    return *reinterpret_cast<uint32_t*>(&h2);
}

__device__ __forceinline__ void mma16(float* c, const uint32_t* a, const uint32_t* b){
    asm volatile(
        "mma.sync.aligned.m16n8k16.row.col.f32.f16.f16.f32 "
        "{%0,%1,%2,%3}, {%4,%5,%6,%7}, {%8,%9}, {%0,%1,%2,%3};"
        : "+f"(c[0]), "+f"(c[1]), "+f"(c[2]), "+f"(c[3])
        : "r"(a[0]), "r"(a[1]), "r"(a[2]), "r"(a[3]), "r"(b[0]), "r"(b[1]));
}

__device__ __forceinline__ uint32_t sm_u32(const void* p){
    uint32_t a;
    asm("{ .reg .u64 t; cvta.to.shared.u64 t, %1; cvt.u32.u64 %0, t; }"
        : "=r"(a) : "l"(p));
    return a;
}

__device__ __forceinline__ void cpasync16(uint32_t dst, const void* src){
    asm volatile("cp.async.cg.shared.global [%0], [%1], 16;"
                 :: "r"(dst), "l"(src) : "memory");
}
#define CP_COMMIT() asm volatile("cp.async.commit_group;" ::: "memory")
#define CP_WAIT1()  asm volatile("cp.async.wait_group 1;" ::: "memory")

// ---------------- kernel A: split X into limb planes (frag order) -----------
__global__ __launch_bounds__(256) void split_x_kernel(const float* __restrict__ X){
    const int id = blockIdx.x*256 + threadIdx.x;
    const int mb   = id >> 11;
    const int c    = (id >> 5) & 63;
    const int lane = id & 31;
    const int r0 = mb*16 + (lane >> 2);
    const int k0 = c*16 + 2*(lane & 3);
    const float* p0 = X + (size_t)r0*Dm + k0;
    float2 a00 = *reinterpret_cast<const float2*>(p0);
    float2 a10 = *reinterpret_cast<const float2*>(p0 + 8*Dm);
    float2 a01 = *reinterpret_cast<const float2*>(p0 + 8);
    float2 a11 = *reinterpret_cast<const float2*>(p0 + 8*Dm + 8);
    uint32_t h0,h1,h2,h3, l0,l1,l2,l3;
    h0 = packsplit(a00.x, a00.y, l0);
    h1 = packsplit(a10.x, a10.y, l1);
    h2 = packsplit(a01.x, a01.y, l2);
    h3 = packsplit(a11.x, a11.y, l3);
    *reinterpret_cast<uint4*>(&g_XS[(size_t)id*4])              = make_uint4(h0,h1,h2,h3);
    *reinterpret_cast<uint4*>(&g_XS[XS_CELLS*4 + (size_t)id*4]) = make_uint4(l0,l1,l2,l3);
}

// ---------------- kernel B: split W (x32) into fragment-ordered limbs --------
__global__ __launch_bounds__(256) void split_w_kernel(
    const float* __restrict__ Wq, const float* __restrict__ Wk,
    const float* __restrict__ Wv)
{
    const int id = blockIdx.x*256 + threadIdx.x;
    const int gemm = id >> 18;
    const int rem  = id & 262143;
    const int nb   = rem >> 11;
    const int c    = (rem >> 5) & 63;
    const int lane = rem & 31;
    const float* W = (gemm == 0) ? Wq : (gemm == 1) ? Wk : Wv;
    const int row = nb*8 + (lane >> 2);
    const int k0  = c*16 + 2*(lane & 3);
    const float* p = W + (size_t)row*Dm + k0;
    float2 b0 = *reinterpret_cast<const float2*>(p);
    float2 b1 = *reinterpret_cast<const float2*>(p + 8);
    uint32_t bh0, bh1, bl0, bl1;
    bh0 = packsplit(b0.x*32.f, b0.y*32.f, bl0);
    bh1 = packsplit(b1.x*32.f, b1.y*32.f, bl1);
    reinterpret_cast<uint4*>(&g_WS[(size_t)id*4])[0] = make_uint4(bh0,bh1,bl0,bl1);
}

// ======================= kernel 1: QKV GEMM (6-buffer cp.async pipeline) =====
// CTA 128M x 128N, 8 warps (4M x 2N), warp tile 32x64. K chunk = 16.
// 6 smem buffers x 16KB (96KB dyn), 2-chunk commit groups, 4 chunks in flight,
// ONE barrier per 2 chunks (32 total).
__global__ __launch_bounds__(256,2) void qkv_f16_kernel(
    const float* __restrict__ bq, const float* __restrict__ bk,
    const float* __restrict__ bv)
{
    const int gemm = blockIdx.z;
    const float* bias = (gemm == 0) ? bq : (gemm == 1) ? bk : bv;
    float* out = (gemm == 0) ? g_Q : (gemm == 1) ? g_K : g_V;

    const int n0 = blockIdx.x * 128;
    const int m0 = blockIdx.y * 128;

    extern __shared__ uint32_t smq[];
    const uint32_t smb = sm_u32(smq);

    const int t = threadIdx.x;
    const int lane = t & 31;
    const int wid  = t >> 5;
    const int warp_m = wid & 3;
    const int warp_n = wid >> 2;

    const int fA = wid, lA = lane;
    const char* srcAh = (const char*)g_XS
        + ((size_t)((blockIdx.y*8 + fA)*64)*32 + lA)*16;
    const char* srcAl = srcAh + XS_CELLS*16;
    const char* srcB1 = (const char*)g_WS
        + ((size_t)((gemm*128 + blockIdx.x*16 + fA)*64)*32 + lA)*16;
    const char* srcB2 = srcB1 + (size_t)8*64*32*16;
    const uint32_t dAh = (fA*32 + lA)*16;
    const uint32_t dAl = dAh + 4096;
    const uint32_t dB1 = 8192 + (fA*32 + lA)*16;
    const uint32_t dB2 = dB1 + 4096;

    float acc[2][8][4];
    #pragma unroll
    for (int i = 0; i < 2; ++i)
        #pragma unroll
        for (int j = 0; j < 8; ++j)
            #pragma unroll
            for (int r = 0; r < 4; ++r) acc[i][j][r] = 0.0f;

    // prologue: chunks 0..3 into buffers 0..3, two 2-chunk groups
    #pragma unroll
    for (int p = 0; p < 4; ++p) {
        const uint32_t b = smb + p*16384;
        cpasync16(b + dAh, srcAh + (size_t)p*512);
        cpasync16(b + dAl, srcAl + (size_t)p*512);
        cpasync16(b + dB1, srcB1 + (size_t)p*512);
        cpasync16(b + dB2, srcB2 + (size_t)p*512);
        if (p & 1) CP_COMMIT();
    }

    int bufr = 0;   // read buffer for chunk 2s (even: 0,2,4,...)
    int bufw = 4;   // write buffer for chunk 2s+4

    #pragma unroll 1
    for (int s = 0; s < 32; ++s) {
        CP_WAIT1();           // group s (chunks 2s,2s+1) complete
        __syncthreads();      // all threads done with previous compute

        if (s < 30) {
            const int c0 = 2*s + 4;
            const int bufw2 = (bufw + 1 == 6) ? 0 : bufw + 1;
            const uint32_t b0 = smb + bufw*16384;
            const uint32_t b1 = smb + bufw2*16384;
            cpasync16(b0 + dAh, srcAh + (size_t)c0*512);
            cpasync16(b0 + dAl, srcAl + (size_t)c0*512);
            cpasync16(b0 + dB1, srcB1 + (size_t)c0*512);
            cpasync16(b0 + dB2, srcB2 + (size_t)c0*512);
            cpasync16(b1 + dAh, srcAh + (size_t)(c0+1)*512);
            cpasync16(b1 + dAl, srcAl + (size_t)(c0+1)*512);
            cpasync16(b1 + dB1, srcB1 + (size_t)(c0+1)*512);
            cpasync16(b1 + dB2, srcB2 + (size_t)(c0+1)*512);
            bufw = (bufw2 + 1 == 6) ? 0 : bufw2 + 1;
        }
        CP_COMMIT();          // uniform group count (empty near tail)

        // compute chunks 2s (bufr) and 2s+1 (bufr+1; bufr even so no wrap)
        #pragma unroll
        for (int ch = 0; ch < 2; ++ch) {
            const uint32_t* C = smq + (bufr + ch)*4096;
            uint32_t ah[2][4], al[2][4];
            #pragma unroll
            for (int im = 0; im < 2; ++im) {
                const int base = ((warp_m*2 + im)*32 + lane)*4;
                *reinterpret_cast<uint4*>(ah[im]) = *reinterpret_cast<const uint4*>(&C[base]);
                *reinterpret_cast<uint4*>(al[im]) = *reinterpret_cast<const uint4*>(&C[base + 1024]);
            }
            #pragma unroll
            for (int in = 0; in < 8; ++in) {
                const int base = 2048 + ((warp_n*8 + in)*32 + lane)*4;
                uint4 q = *reinterpret_cast<const uint4*>(&C[base]);
                uint32_t bh[2] = {q.x, q.y};
                uint32_t bl[2] = {q.z, q.w};
                #pragma unroll
                for (int im = 0; im < 2; ++im) {
                    mma16(acc[im][in], al[im], bh);
                    mma16(acc[im][in], ah[im], bl);
                    mma16(acc[im][in], ah[im], bh);
                }
            }
        }
        bufr += 2; if (bufr == 6) bufr = 0;
    }

    // epilogue
    const float inv32 = 0.03125f;
    #pragma unroll
    for (int im = 0; im < 2; ++im) {
        const int m = m0 + warp_m*32 + im*16 + (lane >> 2);
        #pragma unroll
        for (int in = 0; in < 8; ++in) {
            const int n = n0 + warp_n*64 + in*8 + (lane & 3)*2;
            const float b0 = __ldg(&bias[n]);
            const float b1 = __ldg(&bias[n+1]);
            float2 v0 = make_float2(acc[im][in][0]*inv32 + b0, acc[im][in][1]*inv32 + b1);
            float2 v1 = make_float2(acc[im][in][2]*inv32 + b0, acc[im][in][3]*inv32 + b1);
            *reinterpret_cast<float2*>(&out[(size_t)m*Dm + n])     = v0;
            *reinterpret_cast<float2*>(&out[(size_t)(m+8)*Dm + n]) = v1;
        }
    }
}

// ---------------- kernel 0: zero vsum ---------------------------------------
__global__ void zero_vsum_kernel(){
    int i = blockIdx.x*blockDim.x + threadIdx.x;
    if (i < Bv*Dm) g_vsum[i] = 0.0f;
}

// ---------------- kernel 2: sparsity measure M (float4 vectorized) ----------
__global__ __launch_bounds__(128) void m_kernel(const int* __restrict__ idx_k){
    const int b = blockIdx.z, h = blockIdx.y;
    const int l0 = blockIdx.x * 128;
    __shared__ float Ks[Uv*DKv];
    __shared__ float Qs[128*68];
    const int t = threadIdx.x;

    for (int i = t; i < Uv*DKv; i += 128) {
        int u = i >> 6, d = i & 63;
        Ks[i] = g_K[(size_t)(b*Lv + idx_k[u])*Dm + h*DKv + d];
    }
    for (int i = t; i < 128*DKv; i += 128) {
        int r = i >> 6, d = i & 63;
        Qs[r*68 + d] = g_Q[(size_t)(b*Lv + l0 + r)*Dm + h*DKv + d];
    }
    __syncthreads();

    float acc[Uv];
    #pragma unroll
    for (int u = 0; u < Uv; ++u) acc[u] = 0.0f;

    #pragma unroll
    for (int dq = 0; dq < 16; ++dq) {
        float4 qv = *reinterpret_cast<const float4*>(&Qs[t*68 + dq*4]);
        #pragma unroll
        for (int u = 0; u < Uv; ++u) {
            float4 kv = *reinterpret_cast<const float4*>(&Ks[u*DKv + dq*4]);
            acc[u] += qv.x*kv.x + qv.y*kv.y + qv.z*kv.z + qv.w*kv.w;
        }
    }
    float mx = -1e30f, smv = 0.0f;
    #pragma unroll
    for (int u = 0; u < Uv; ++u) { mx = fmaxf(mx, acc[u]); smv += acc[u]; }
    g_M[(size_t)(b*Hh + h)*Lv + l0 + t] = mx - smv*(1.0f/Uv);
}

// ---------------- kernel 3: top-k (k=50 of 8192) per (b,h) -------------------
__global__ __launch_bounds__(256) void topk_kernel(){
    const int bh = blockIdx.x;
    __shared__ float vals[Lv];
    __shared__ float rv[256];
    __shared__ int   ri[256];
    const int t = threadIdx.x;

    for (int i = t; i < Lv; i += 256) vals[i] = g_M[(size_t)bh*Lv + i];
    __syncthreads();

    for (int it = 0; it < Uv; ++it) {
        float best = -1e30f; int bi = Lv;
        for (int i = t; i < Lv; i += 256) {
            float v = vals[i];
            if (v > best || (v == best && i < bi)) { best = v; bi = i; }
        }
        rv[t] = best; ri[t] = bi;
        __syncthreads();
        for (int s = 128; s > 0; s >>= 1) {
            if (t < s) {
                if (rv[t+s] > rv[t] || (rv[t+s] == rv[t] && ri[t+s] < ri[t])) {
                    rv[t] = rv[t+s]; ri[t] = ri[t+s];
                }
            }
            __syncthreads();
        }
        if (t == 0) { g_top[bh*Uv + it] = ri[0]; vals[ri[0]] = -1e30f; }
        __syncthreads();
    }
}

// ---------------- kernel 4: V column sums (for mean) -------------------------
__global__ void vsum_kernel(){
    const int b = blockIdx.z;
    const int d = blockIdx.x*128 + threadIdx.x;
    const int c = blockIdx.y;
    float s = 0.0f;
    const int lbeg = c*256, lend = lbeg + 256;
    for (int l = lbeg; l < lend; ++l) s += g_V[(size_t)(b*Lv + l)*Dm + d];
    atomicAdd(&g_vsum[b*Dm + d], s);
}

// ---------------- kernel 5: flash attention (cp.async double-buffered) -------
// dyn smem (floats): Qs[50*64]@0, stage s@3200+s*4352 (K 32*68, V @+2176),
// Ps[50*36]@11904, m@13704, l@13754, c@13804 ; total 13854 floats = 55416 B
__global__ __launch_bounds__(512) void attn_partial_kernel(){
    extern __shared__ float sma[];
    const int bh = blockIdx.x;
    const int sp = blockIdx.y;
    const int b = bh / Hh, h = bh % Hh;
    const int t = threadIdx.x;

    float* Qs  = sma;
    float* Ps  = sma + 11904;
    float* m_s = sma + 13704;
    float* l_s = sma + 13754;
    float* c_s = sma + 13804;
    const uint32_t smab = sm_u32(sma);

    for (int i = t; i < Uv*DKv; i += 512) {
        int q = i >> 6, d = i & 63;
        int l = g_top[bh*Uv + q];
        Qs[q*64 + d] = g_Q[(size_t)(b*Lv + l)*Dm + h*DKv + d];
    }
    if (t < Uv) { m_s[t] = -1e30f; l_s[t] = 0.0f; }

    float ctx[7];
    #pragma unroll
    for (int j = 0; j < 7; ++j) ctx[j] = 0.0f;
    const int d = t & 63;
    const int qb = t >> 6;

    const int ldrow = t >> 4;            // 0..31
    const int lddq  = t & 15;            // 0..15
    const uint32_t kdst = smab + (3200 + ldrow*68 + lddq*4)*4;
    const uint32_t vdst = kdst + 2176*4;

    // prologue: tile 0 -> stage 0
    {
        size_t g = (size_t)(b*Lv + sp*LSPL + ldrow)*Dm + h*DKv + lddq*4;
        cpasync16(kdst, &g_K[g]);
        cpasync16(vdst, &g_V[g]);
    }
    CP_COMMIT();

    const int NT = LSPL/TK;   // 32
    #pragma unroll 1
    for (int i = 0; i < NT; ++i) {
        __syncthreads();      // prev compute done (and Q/m init on i=0)
        if (i + 1 < NT) {     // issue tile i+1 into stage (i+1)&1
            const uint32_t off = ((i+1) & 1)*4352*4;
            size_t g = (size_t)(b*Lv + sp*LSPL + (i+1)*TK + ldrow)*Dm + h*DKv + lddq*4;
            cpasync16(kdst + off, &g_K[g]);
            cpasync16(vdst + off, &g_V[g]);
        }
        CP_COMMIT();
        CP_WAIT1();           // tile i complete
        __syncthreads();

        const float* Ks = sma + 3200 + (i & 1)*4352;
        const float* Vs = Ks + 2176;

        if (t < 400) {                       // 50 q * 8 key-groups
            const int q = t >> 3, kg = t & 7;
            float a0 = 0.f, a1 = 0.f, a2 = 0.f, a3 = 0.f;
            #pragma unroll
            for (int dq = 0; dq < 16; ++dq) {
                float4 qv = *reinterpret_cast<const float4*>(&Qs[q*64 + dq*4]);
                float4 k0 = *reinterpret_cast<const float4*>(&Ks[kg*68 + dq*4]);
                float4 k1 = *reinterpret_cast<const float4*>(&Ks[(kg+8)*68 + dq*4]);
                float4 k2 = *reinterpret_cast<const float4*>(&Ks[(kg+16)*68 + dq*4]);
                float4 k3 = *reinterpret_cast<const float4*>(&Ks[(kg+24)*68 + dq*4]);
                a0 += qv.x*k0.x + qv.y*k0.y + qv.z*k0.z + qv.w*k0.w;
                a1 += qv.x*k1.x + qv.y*k1.y + qv.z*k1.z + qv.w*k1.w;
                a2 += qv.x*k2.x + qv.y*k2.y + qv.z*k2.z + qv.w*k2.w;
                a3 += qv.x*k3.x + qv.y*k3.y + qv.z*k3.z + qv.w*k3.w;
            }
            Ps[q*36 + kg]    = a0 * 0.125f;
            Ps[q*36 + kg+8]  = a1 * 0.125f;
            Ps[q*36 + kg+16] = a2 * 0.125f;
            Ps[q*36 + kg+24] = a3 * 0.125f;
        }
        __syncthreads();

        if (t < Uv) {
            float tm = -1e30f;
            #pragma unroll
            for (int k = 0; k < TK; ++k) tm = fmaxf(tm, Ps[t*36 + k]);
            float nm = fmaxf(m_s[t], tm);
            float cc = __expf(m_s[t] - nm);
            float ls = l_s[t]*cc;
            #pragma unroll
            for (int k = 0; k < TK; ++k) {
                float p = __expf(Ps[t*36 + k] - nm);
                Ps[t*36 + k] = p;
                ls += p;
            }
            m_s[t] = nm; l_s[t] = ls; c_s[t] = cc;
        }
        __syncthreads();

        {
            float vreg[TK];
            #pragma unroll
            for (int k = 0; k < TK; ++k) vreg[k] = Vs[k*68 + d];
            #pragma unroll
            for (int j = 0; j < 7; ++j) {
                int q = qb + 8*j;
                if (q < Uv) {
                    float a = ctx[j] * c_s[q];
                    #pragma unroll
                    for (int kq = 0; kq < 8; ++kq) {
                        float4 p = *reinterpret_cast<const float4*>(&Ps[q*36 + kq*4]);
                        a += p.x*vreg[kq*4] + p.y*vreg[kq*4+1]
                           + p.z*vreg[kq*4+2] + p.w*vreg[kq*4+3];
                    }
                    ctx[j] = a;
                }
            }
        }
    }

    __syncthreads();
    #pragma unroll
    for (int j = 0; j < 7; ++j) {
        int q = qb + 8*j;
        if (q < Uv)
            g_pctx[(size_t)((bh*SPLIT + sp)*Uv + q)*DKv + d] = ctx[j];
    }
    if (t < Uv) {
        g_pm[(bh*SPLIT + sp)*Uv + t] = m_s[t];
        g_pl[(bh*SPLIT + sp)*Uv + t] = l_s[t];
    }
}

// ---------------- kernel 6: combine split partials ---------------------------
__global__ __launch_bounds__(64) void attn_combine_kernel(){
    const int i = blockIdx.x;
    const int q = i % Uv, bh = i / Uv;
    __shared__ float w[SPLIT];
    __shared__ float inv;
    if (threadIdx.x == 0) {
        float M = -1e30f;
        for (int s = 0; s < SPLIT; ++s) M = fmaxf(M, g_pm[(bh*SPLIT+s)*Uv + q]);
        float tot = 0.f;
        for (int s = 0; s < SPLIT; ++s) {
            float e = __expf(g_pm[(bh*SPLIT+s)*Uv + q] - M);
            w[s] = e;
            tot += g_pl[(bh*SPLIT+s)*Uv + q] * e;
        }
        inv = 1.0f / tot;
    }
    __syncthreads();
    const int d = threadIdx.x;
    float c = 0.f;
    for (int s = 0; s < SPLIT; ++s)
        c += g_pctx[(size_t)((bh*SPLIT+s)*Uv + q)*DKv + d] * w[s];
    g_ctx[(size_t)i*DKv + d] = c * inv;
}

// ---------------- kernel 7: base output row per batch ------------------------
__global__ __launch_bounds__(256) void base_kernel(const float* __restrict__ Wo,
                                                   const float* __restrict__ bo){
    const int b = blockIdx.y;
    const int warp = threadIdx.x >> 5, lane = threadIdx.x & 31;
    const int j = blockIdx.x*8 + warp;
    float s = 0.f;
    for (int d0 = lane; d0 < Dm; d0 += 32)
        s += g_vsum[b*Dm + d0] * Wo[(size_t)j*Dm + d0];
    #pragma unroll
    for (int o = 16; o; o >>= 1) s += __shfl_down_sync(0xffffffffu, s, o);
    if (lane == 0) g_base[b*Dm + j] = s*(1.0f/Lv) + bo[j];
}

// ---------------- kernel 8: broadcast base rows into output -------------------
__global__ void fill_kernel(float* __restrict__ out){
    const int i = blockIdx.x*blockDim.x + threadIdx.x;
    const int b  = i >> 21;
    const int j4 = i & 255;
    float4 v = *reinterpret_cast<const float4*>(&g_base[b*Dm + j4*4]);
    reinterpret_cast<float4*>(out)[i] = v;
}

// ---------------- kernel 9: rank-64 corrections for top rows ------------------
__global__ __launch_bounds__(256) void corr_kernel(const float* __restrict__ Wo,
                                                   float* __restrict__ out){
    const int i = blockIdx.x;
    const int bh = i / Uv;
    const int b = bh / Hh, h = bh % Hh;
    const int l = g_top[i];
    __shared__ float delta[DKv];
    const int t = threadIdx.x;
    if (t < DKv)
        delta[t] = g_ctx[(size_t)i*DKv + t] - g_vsum[b*Dm + h*DKv + t]*(1.0f/Lv);
    __syncthreads();
    for (int j = t; j < Dm; j += 256) {
        const float4* wr = reinterpret_cast<const float4*>(Wo + (size_t)j*Dm + h*DKv);
        float s = 0.f;
        #pragma unroll
        for (int dd = 0; dd < 16; ++dd) {
            float4 wv = wr[dd];
            s += delta[dd*4+0]*wv.x + delta[dd*4+1]*wv.y
               + delta[dd*4+2]*wv.z + delta[dd*4+3]*wv.w;
        }
        atomicAdd(&out[(size_t)(b*Lv + l)*Dm + j], s);
    }
}

// ---------------- launch ------------------------------------------------------
extern "C" void kernel_launch(void* const* d_in, const int* in_sizes, int n_in,
                              void* d_out, int out_size)
{
    const float* x    = (const float*)d_in[0];
    const float* Wq   = (const float*)d_in[1];
    const float* bq   = (const float*)d_in[2];
    const float* Wk   = (const float*)d_in[3];
    const float* bk   = (const float*)d_in[4];
    const float* Wv   = (const float*)d_in[5];
    const float* bv   = (const float*)d_in[6];
    const float* Wo   = (const float*)d_in[7];
    const float* bo   = (const float*)d_in[8];
    const int*   idxk = (const int*)d_in[9];
    float* out = (float*)d_out;

    cudaFuncSetAttribute(qkv_f16_kernel,
                         cudaFuncAttributeMaxDynamicSharedMemorySize, 98304);
    cudaFuncSetAttribute(attn_partial_kernel,
                         cudaFuncAttributeMaxDynamicSharedMemorySize, 55424);

    zero_vsum_kernel<<<(Bv*Dm)/256, 256>>>();
    split_x_kernel<<<(2048*64*32)/256, 256>>>(x);
    split_w_kernel<<<(3*128*64*32)/256, 256>>>(Wq, Wk, Wv);
    qkv_f16_kernel<<<dim3(Dm/128, BLv/128, 3), 256, 98304>>>(bq, bk, bv);
    m_kernel<<<dim3(Lv/128, Hh, Bv), 128>>>(idxk);
    vsum_kernel<<<dim3(Dm/128, Lv/256, Bv), 128>>>();
    topk_kernel<<<Bv*Hh, 256>>>();
    attn_partial_kernel<<<dim3(Bv*Hh, SPLIT), 512, 55424>>>();
    attn_combine_kernel<<<Bv*Hh*Uv, 64>>>();
    base_kernel<<<dim3(Dm/8, Bv), 256>>>(Wo, bo);
    fill_kernel<<<(BLv*Dm/4)/256, 256>>>(out);
    corr_kernel<<<Bv*Hh*Uv, 256>>>(Wo, out);
}

// round 11
// speedup vs baseline: 3.0626x; 1.0114x over previous
#include <cuda_runtime.h>
#include <cuda_fp16.h>
#include <math.h>
#include <stdint.h>

#define Bv 4
#define Lv 8192
#define Dm 1024
#define Hh 16
#define DKv 64
#define Uv 50
#define BLv (Bv*Lv)            // 32768
#define SPLIT 8
#define LSPL (Lv/SPLIT)        // 1024
#define TK 32

// ---------------- scratch (device globals; no allocations allowed) ----------
#define XS_CELLS ((size_t)2048*64*32)
__device__ float g_Q[BLv*Dm];          // 128 MB
__device__ float g_K[BLv*Dm];          // 128 MB
__device__ float g_V[BLv*Dm];          // 128 MB
__device__ uint32_t g_XS[XS_CELLS*8];             // 128 MB: X limbs, hi plane then lo plane
__device__ uint32_t g_WS[(size_t)3*128*64*32*4];  // 12 MB: W limbs (x32), frag order
__device__ float g_M[Bv*Hh*Lv];
__device__ int   g_top[Bv*Hh*Uv];
__device__ float g_pm[Bv*Hh*SPLIT*Uv];
__device__ float g_pl[Bv*Hh*SPLIT*Uv];
__device__ float g_pctx[Bv*Hh*SPLIT*Uv*DKv];
__device__ float g_ctx[Bv*Hh*Uv*DKv];
__device__ float g_vsum[Bv*Dm];
__device__ float g_base[Bv*Dm];

// ---------------- helpers ----------------------------------------------------
__device__ __forceinline__ uint32_t packsplit(float x, float y, uint32_t &lo){
    __half hx = __float2half_rn(x);
    __half hy = __float2half_rn(y);
    __half lx = __float2half_rn(x - __half2float(hx));
    __half ly = __float2half_rn(y - __half2float(hy));
    __half2 h2 = __halves2half2(hx, hy);
    __half2 l2 = __halves2half2(lx, ly);
    lo = *reinterpret_cast<uint32_t*>(&l2);
    return *reinterpret_cast<uint32_t*>(&h2);
}

__device__ __forceinline__ void mma16(float* c, const uint32_t* a, const uint32_t* b){
    asm volatile(
        "mma.sync.aligned.m16n8k16.row.col.f32.f16.f16.f32 "
        "{%0,%1,%2,%3}, {%4,%5,%6,%7}, {%8,%9}, {%0,%1,%2,%3};"
        : "+f"(c[0]), "+f"(c[1]), "+f"(c[2]), "+f"(c[3])
        : "r"(a[0]), "r"(a[1]), "r"(a[2]), "r"(a[3]), "r"(b[0]), "r"(b[1]));
}

__device__ __forceinline__ uint32_t sm_u32(const void* p){
    uint32_t a;
    asm("{ .reg .u64 t; cvta.to.shared.u64 t, %1; cvt.u32.u64 %0, t; }"
        : "=r"(a) : "l"(p));
    return a;
}

__device__ __forceinline__ void cpasync16(uint32_t dst, const void* src){
    asm volatile("cp.async.cg.shared.global [%0], [%1], 16;"
                 :: "r"(dst), "l"(src) : "memory");
}
#define CP_COMMIT() asm volatile("cp.async.commit_group;" ::: "memory")
#define CP_WAIT1()  asm volatile("cp.async.wait_group 1;" ::: "memory")

// ---------------- kernel A: split X into limb planes (frag order) -----------
__global__ __launch_bounds__(256) void split_x_kernel(const float* __restrict__ X){
    const int id = blockIdx.x*256 + threadIdx.x;
    const int mb   = id >> 11;
    const int c    = (id >> 5) & 63;
    const int lane = id & 31;
    const int r0 = mb*16 + (lane >> 2);
    const int k0 = c*16 + 2*(lane & 3);
    const float* p0 = X + (size_t)r0*Dm + k0;
    float2 a00 = *reinterpret_cast<const float2*>(p0);
    float2 a10 = *reinterpret_cast<const float2*>(p0 + 8*Dm);
    float2 a01 = *reinterpret_cast<const float2*>(p0 + 8);
    float2 a11 = *reinterpret_cast<const float2*>(p0 + 8*Dm + 8);
    uint32_t h0,h1,h2,h3, l0,l1,l2,l3;
    h0 = packsplit(a00.x, a00.y, l0);
    h1 = packsplit(a10.x, a10.y, l1);
    h2 = packsplit(a01.x, a01.y, l2);
    h3 = packsplit(a11.x, a11.y, l3);
    *reinterpret_cast<uint4*>(&g_XS[(size_t)id*4])              = make_uint4(h0,h1,h2,h3);
    *reinterpret_cast<uint4*>(&g_XS[XS_CELLS*4 + (size_t)id*4]) = make_uint4(l0,l1,l2,l3);
}

// ---------------- kernel B: split W (x32) into limbs; also zero vsum ---------
__global__ __launch_bounds__(256) void split_w_kernel(
    const float* __restrict__ Wq, const float* __restrict__ Wk,
    const float* __restrict__ Wv)
{
    if (blockIdx.x < 16) g_vsum[blockIdx.x*256 + threadIdx.x] = 0.0f;

    const int id = blockIdx.x*256 + threadIdx.x;
    const int gemm = id >> 18;
    const int rem  = id & 262143;
    const int nb   = rem >> 11;
    const int c    = (rem >> 5) & 63;
    const int lane = rem & 31;
    const float* W = (gemm == 0) ? Wq : (gemm == 1) ? Wk : Wv;
    const int row = nb*8 + (lane >> 2);
    const int k0  = c*16 + 2*(lane & 3);
    const float* p = W + (size_t)row*Dm + k0;
    float2 b0 = *reinterpret_cast<const float2*>(p);
    float2 b1 = *reinterpret_cast<const float2*>(p + 8);
    uint32_t bh0, bh1, bl0, bl1;
    bh0 = packsplit(b0.x*32.f, b0.y*32.f, bl0);
    bh1 = packsplit(b1.x*32.f, b1.y*32.f, bl1);
    reinterpret_cast<uint4*>(&g_WS[(size_t)id*4])[0] = make_uint4(bh0,bh1,bl0,bl1);
}

// ======================= kernel 1: QKV GEMM (R9-best pipeline) ===============
// CTA 128M x 128N, 8 warps (4M x 2N), warp tile 32x64. K chunk = 16.
// 4 smem buffers x 16KB, cp.async lookahead 2, ONE barrier per chunk.
__global__ __launch_bounds__(256,2) void qkv_f16_kernel(
    const float* __restrict__ bq, const float* __restrict__ bk,
    const float* __restrict__ bv)
{
    const int gemm = blockIdx.z;
    const float* bias = (gemm == 0) ? bq : (gemm == 1) ? bk : bv;
    float* out = (gemm == 0) ? g_Q : (gemm == 1) ? g_K : g_V;

    const int n0 = blockIdx.x * 128;
    const int m0 = blockIdx.y * 128;

    extern __shared__ uint32_t smq[];
    const uint32_t smb = sm_u32(smq);

    const int t = threadIdx.x;
    const int lane = t & 31;
    const int wid  = t >> 5;
    const int warp_m = wid & 3;
    const int warp_n = wid >> 2;

    const int fA = wid, lA = lane;
    const char* srcAh = (const char*)g_XS
        + ((size_t)((blockIdx.y*8 + fA)*64)*32 + lA)*16;
    const char* srcAl = srcAh + XS_CELLS*16;
    const char* srcB1 = (const char*)g_WS
        + ((size_t)((gemm*128 + blockIdx.x*16 + fA)*64)*32 + lA)*16;
    const char* srcB2 = srcB1 + (size_t)8*64*32*16;
    const uint32_t dAh = (fA*32 + lA)*16;
    const uint32_t dAl = dAh + 4096;
    const uint32_t dB1 = 8192 + (fA*32 + lA)*16;
    const uint32_t dB2 = dB1 + 4096;

    float acc[2][8][4];
    #pragma unroll
    for (int i = 0; i < 2; ++i)
        #pragma unroll
        for (int j = 0; j < 8; ++j)
            #pragma unroll
            for (int r = 0; r < 4; ++r) acc[i][j][r] = 0.0f;

    // prologue: chunks 0,1
    #pragma unroll
    for (int p = 0; p < 2; ++p) {
        const uint32_t b = smb + p*16384;
        cpasync16(b + dAh, srcAh + (size_t)p*512);
        cpasync16(b + dAl, srcAl + (size_t)p*512);
        cpasync16(b + dB1, srcB1 + (size_t)p*512);
        cpasync16(b + dB2, srcB2 + (size_t)p*512);
        CP_COMMIT();
    }

    #pragma unroll 1
    for (int c = 0; c < 64; ++c) {
        CP_WAIT1();           // chunk c complete (chunk c+1 may be in flight)
        __syncthreads();      // all smem visible; all threads past compute c-1

        if (c + 2 < 64) {
            const uint32_t b = smb + ((c+2) & 3)*16384;
            cpasync16(b + dAh, srcAh + (size_t)(c+2)*512);
            cpasync16(b + dAl, srcAl + (size_t)(c+2)*512);
            cpasync16(b + dB1, srcB1 + (size_t)(c+2)*512);
            cpasync16(b + dB2, srcB2 + (size_t)(c+2)*512);
        }
        CP_COMMIT();          // uniform group count

        const uint32_t* C = smq + (c & 3)*4096;
        uint32_t ah[2][4], al[2][4];
        #pragma unroll
        for (int im = 0; im < 2; ++im) {
            const int base = ((warp_m*2 + im)*32 + lane)*4;
            *reinterpret_cast<uint4*>(ah[im]) = *reinterpret_cast<const uint4*>(&C[base]);
            *reinterpret_cast<uint4*>(al[im]) = *reinterpret_cast<const uint4*>(&C[base + 1024]);
        }
        #pragma unroll
        for (int in = 0; in < 8; ++in) {
            const int base = 2048 + ((warp_n*8 + in)*32 + lane)*4;
            uint4 q = *reinterpret_cast<const uint4*>(&C[base]);
            uint32_t bh[2] = {q.x, q.y};
            uint32_t bl[2] = {q.z, q.w};
            #pragma unroll
            for (int im = 0; im < 2; ++im) {
                mma16(acc[im][in], al[im], bh);
                mma16(acc[im][in], ah[im], bl);
                mma16(acc[im][in], ah[im], bh);
            }
        }
    }

    // epilogue
    const float inv32 = 0.03125f;
    #pragma unroll
    for (int im = 0; im < 2; ++im) {
        const int m = m0 + warp_m*32 + im*16 + (lane >> 2);
        #pragma unroll
        for (int in = 0; in < 8; ++in) {
            const int n = n0 + warp_n*64 + in*8 + (lane & 3)*2;
            const float b0 = __ldg(&bias[n]);
            const float b1 = __ldg(&bias[n+1]);
            float2 v0 = make_float2(acc[im][in][0]*inv32 + b0, acc[im][in][1]*inv32 + b1);
            float2 v1 = make_float2(acc[im][in][2]*inv32 + b0, acc[im][in][3]*inv32 + b1);
            *reinterpret_cast<float2*>(&out[(size_t)m*Dm + n])     = v0;
            *reinterpret_cast<float2*>(&out[(size_t)(m+8)*Dm + n]) = v1;
        }
    }
}

// ---------------- kernel 2: sparsity measure M (float4 vectorized) ----------
__global__ __launch_bounds__(128) void m_kernel(const int* __restrict__ idx_k){
    const int b = blockIdx.z, h = blockIdx.y;
    const int l0 = blockIdx.x * 128;
    __shared__ float Ks[Uv*DKv];
    __shared__ float Qs[128*68];
    const int t = threadIdx.x;

    for (int i = t; i < Uv*DKv; i += 128) {
        int u = i >> 6, d = i & 63;
        Ks[i] = g_K[(size_t)(b*Lv + idx_k[u])*Dm + h*DKv + d];
    }
    for (int i = t; i < 128*DKv; i += 128) {
        int r = i >> 6, d = i & 63;
        Qs[r*68 + d] = g_Q[(size_t)(b*Lv + l0 + r)*Dm + h*DKv + d];
    }
    __syncthreads();

    float acc[Uv];
    #pragma unroll
    for (int u = 0; u < Uv; ++u) acc[u] = 0.0f;

    #pragma unroll
    for (int dq = 0; dq < 16; ++dq) {
        float4 qv = *reinterpret_cast<const float4*>(&Qs[t*68 + dq*4]);
        #pragma unroll
        for (int u = 0; u < Uv; ++u) {
            float4 kv = *reinterpret_cast<const float4*>(&Ks[u*DKv + dq*4]);
            acc[u] += qv.x*kv.x + qv.y*kv.y + qv.z*kv.z + qv.w*kv.w;
        }
    }
    float mx = -1e30f, smv = 0.0f;
    #pragma unroll
    for (int u = 0; u < Uv; ++u) { mx = fmaxf(mx, acc[u]); smv += acc[u]; }
    g_M[(size_t)(b*Hh + h)*Lv + l0 + t] = mx - smv*(1.0f/Uv);
}

// ---------------- kernel 3: top-k (k=50 of 8192) per (b,h) -------------------
__global__ __launch_bounds__(256) void topk_kernel(){
    const int bh = blockIdx.x;
    __shared__ float vals[Lv];
    __shared__ float rv[256];
    __shared__ int   ri[256];
    const int t = threadIdx.x;

    for (int i = t; i < Lv; i += 256) vals[i] = g_M[(size_t)bh*Lv + i];
    __syncthreads();

    for (int it = 0; it < Uv; ++it) {
        float best = -1e30f; int bi = Lv;
        for (int i = t; i < Lv; i += 256) {
            float v = vals[i];
            if (v > best || (v == best && i < bi)) { best = v; bi = i; }
        }
        rv[t] = best; ri[t] = bi;
        __syncthreads();
        for (int s = 128; s > 0; s >>= 1) {
            if (t < s) {
                if (rv[t+s] > rv[t] || (rv[t+s] == rv[t] && ri[t+s] < ri[t])) {
                    rv[t] = rv[t+s]; ri[t] = ri[t+s];
                }
            }
            __syncthreads();
        }
        if (t == 0) { g_top[bh*Uv + it] = ri[0]; vals[ri[0]] = -1e30f; }
        __syncthreads();
    }
}

// ---------------- kernel 4: V column sums (for mean) -------------------------
__global__ void vsum_kernel(){
    const int b = blockIdx.z;
    const int d = blockIdx.x*128 + threadIdx.x;
    const int c = blockIdx.y;
    float s = 0.0f;
    const int lbeg = c*256, lend = lbeg + 256;
    for (int l = lbeg; l < lend; ++l) s += g_V[(size_t)(b*Lv + l)*Dm + d];
    atomicAdd(&g_vsum[b*Dm + d], s);
}

// ---------------- kernel 5: flash attention (cp.async + parallel softmax) ----
// dyn smem (floats): Qs[50*64]@0, stage s@3200+s*4352 (K 32*68, V @+2176),
// Ps[50*36]@11904, m@13704, l@13754, c@13804 ; total 13854 floats = 55416 B
__global__ __launch_bounds__(512) void attn_partial_kernel(){
    extern __shared__ float sma[];
    const int bh = blockIdx.x;
    const int sp = blockIdx.y;
    const int b = bh / Hh, h = bh % Hh;
    const int t = threadIdx.x;

    float* Qs  = sma;
    float* Ps  = sma + 11904;
    float* m_s = sma + 13704;
    float* l_s = sma + 13754;
    float* c_s = sma + 13804;
    const uint32_t smab = sm_u32(sma);

    for (int i = t; i < Uv*DKv; i += 512) {
        int q = i >> 6, d = i & 63;
        int l = g_top[bh*Uv + q];
        Qs[q*64 + d] = g_Q[(size_t)(b*Lv + l)*Dm + h*DKv + d];
    }
    if (t < Uv) { m_s[t] = -1e30f; l_s[t] = 0.0f; }

    float ctx[7];
    #pragma unroll
    for (int j = 0; j < 7; ++j) ctx[j] = 0.0f;
    const int d = t & 63;
    const int qb = t >> 6;

    const int ldrow = t >> 4;            // 0..31
    const int lddq  = t & 15;            // 0..15
    const uint32_t kdst = smab + (3200 + ldrow*68 + lddq*4)*4;
    const uint32_t vdst = kdst + 2176*4;

    // prologue: tile 0 -> stage 0
    {
        size_t g = (size_t)(b*Lv + sp*LSPL + ldrow)*Dm + h*DKv + lddq*4;
        cpasync16(kdst, &g_K[g]);
        cpasync16(vdst, &g_V[g]);
    }
    CP_COMMIT();

    const int NT = LSPL/TK;   // 32
    #pragma unroll 1
    for (int i = 0; i < NT; ++i) {
        __syncthreads();      // prev compute done (and Q/m init on i=0)
        if (i + 1 < NT) {     // issue tile i+1 into stage (i+1)&1
            const uint32_t off = ((i+1) & 1)*4352*4;
            size_t g = (size_t)(b*Lv + sp*LSPL + (i+1)*TK + ldrow)*Dm + h*DKv + lddq*4;
            cpasync16(kdst + off, &g_K[g]);
            cpasync16(vdst + off, &g_V[g]);
        }
        CP_COMMIT();
        CP_WAIT1();           // tile i complete
        __syncthreads();

        const float* Ks = sma + 3200 + (i & 1)*4352;
        const float* Vs = Ks + 2176;

        if (t < 400) {                       // 50 q * 8 key-groups (scores)
            const int q = t >> 3, kg = t & 7;
            float a0 = 0.f, a1 = 0.f, a2 = 0.f, a3 = 0.f;
            #pragma unroll
            for (int dq = 0; dq < 16; ++dq) {
                float4 qv = *reinterpret_cast<const float4*>(&Qs[q*64 + dq*4]);
                float4 k0 = *reinterpret_cast<const float4*>(&Ks[kg*68 + dq*4]);
                float4 k1 = *reinterpret_cast<const float4*>(&Ks[(kg+8)*68 + dq*4]);
                float4 k2 = *reinterpret_cast<const float4*>(&Ks[(kg+16)*68 + dq*4]);
                float4 k3 = *reinterpret_cast<const float4*>(&Ks[(kg+24)*68 + dq*4]);
                a0 += qv.x*k0.x + qv.y*k0.y + qv.z*k0.z + qv.w*k0.w;
                a1 += qv.x*k1.x + qv.y*k1.y + qv.z*k1.z + qv.w*k1.w;
                a2 += qv.x*k2.x + qv.y*k2.y + qv.z*k2.z + qv.w*k2.w;
                a3 += qv.x*k3.x + qv.y*k3.y + qv.z*k3.z + qv.w*k3.w;
            }
            Ps[q*36 + kg]    = a0 * 0.125f;
            Ps[q*36 + kg+8]  = a1 * 0.125f;
            Ps[q*36 + kg+16] = a2 * 0.125f;
            Ps[q*36 + kg+24] = a3 * 0.125f;
        }
        __syncthreads();

        // parallel online softmax: 8 lanes per q, butterfly reductions
        {
            const int q = (t < 400) ? (t >> 3) : 49;
            const int g = t & 7;
            float4 p4 = *reinterpret_cast<const float4*>(&Ps[q*36 + g*4]);
            float lm = fmaxf(fmaxf(p4.x, p4.y), fmaxf(p4.z, p4.w));
            #pragma unroll
            for (int o = 1; o < 8; o <<= 1)
                lm = fmaxf(lm, __shfl_xor_sync(0xffffffffu, lm, o, 8));
            const float mold = m_s[q];
            const float nm = fmaxf(mold, lm);
            p4.x = __expf(p4.x - nm);
            p4.y = __expf(p4.y - nm);
            p4.z = __expf(p4.z - nm);
            p4.w = __expf(p4.w - nm);
            float lsum = p4.x + p4.y + p4.z + p4.w;
            #pragma unroll
            for (int o = 1; o < 8; o <<= 1)
                lsum += __shfl_xor_sync(0xffffffffu, lsum, o, 8);
            if (t < 400) {
                *reinterpret_cast<float4*>(&Ps[q*36 + g*4]) = p4;
                if (g == 0) {
                    float cc = __expf(mold - nm);
                    c_s[q] = cc;
                    l_s[q] = l_s[q]*cc + lsum;
                    m_s[q] = nm;
                }
            }
        }
        __syncthreads();

        {
            float vreg[TK];
            #pragma unroll
            for (int k = 0; k < TK; ++k) vreg[k] = Vs[k*68 + d];
            #pragma unroll
            for (int j = 0; j < 7; ++j) {
                int q = qb + 8*j;
                if (q < Uv) {
                    float a = ctx[j] * c_s[q];
                    #pragma unroll
                    for (int kq = 0; kq < 8; ++kq) {
                        float4 p = *reinterpret_cast<const float4*>(&Ps[q*36 + kq*4]);
                        a += p.x*vreg[kq*4] + p.y*vreg[kq*4+1]
                           + p.z*vreg[kq*4+2] + p.w*vreg[kq*4+3];
                    }
                    ctx[j] = a;
                }
            }
        }
    }

    __syncthreads();
    #pragma unroll
    for (int j = 0; j < 7; ++j) {
        int q = qb + 8*j;
        if (q < Uv)
            g_pctx[(size_t)((bh*SPLIT + sp)*Uv + q)*DKv + d] = ctx[j];
    }
    if (t < Uv) {
        g_pm[(bh*SPLIT + sp)*Uv + t] = m_s[t];
        g_pl[(bh*SPLIT + sp)*Uv + t] = l_s[t];
    }
}

// ---------------- kernel 6: combine split partials ---------------------------
__global__ __launch_bounds__(64) void attn_combine_kernel(){
    const int i = blockIdx.x;
    const int q = i % Uv, bh = i / Uv;
    __shared__ float w[SPLIT];
    __shared__ float inv;
    if (threadIdx.x == 0) {
        float M = -1e30f;
        for (int s = 0; s < SPLIT; ++s) M = fmaxf(M, g_pm[(bh*SPLIT+s)*Uv + q]);
        float tot = 0.f;
        for (int s = 0; s < SPLIT; ++s) {
            float e = __expf(g_pm[(bh*SPLIT+s)*Uv + q] - M);
            w[s] = e;
            tot += g_pl[(bh*SPLIT+s)*Uv + q] * e;
        }
        inv = 1.0f / tot;
    }
    __syncthreads();
    const int d = threadIdx.x;
    float c = 0.f;
    for (int s = 0; s < SPLIT; ++s)
        c += g_pctx[(size_t)((bh*SPLIT+s)*Uv + q)*DKv + d] * w[s];
    g_ctx[(size_t)i*DKv + d] = c * inv;
}

// ---------------- kernel 7: base output row per batch ------------------------
__global__ __launch_bounds__(256) void base_kernel(const float* __restrict__ Wo,
                                                   const float* __restrict__ bo){
    const int b = blockIdx.y;
    const int warp = threadIdx.x >> 5, lane = threadIdx.x & 31;
    const int j = blockIdx.x*8 + warp;
    float s = 0.f;
    for (int d0 = lane; d0 < Dm; d0 += 32)
        s += g_vsum[b*Dm + d0] * Wo[(size_t)j*Dm + d0];
    #pragma unroll
    for (int o = 16; o; o >>= 1) s += __shfl_down_sync(0xffffffffu, s, o);
    if (lane == 0) g_base[b*Dm + j] = s*(1.0f/Lv) + bo[j];
}

// ---------------- kernel 8: broadcast base rows into output -------------------
__global__ void fill_kernel(float* __restrict__ out){
    const int i = blockIdx.x*blockDim.x + threadIdx.x;
    const int b  = i >> 21;
    const int j4 = i & 255;
    float4 v = *reinterpret_cast<const float4*>(&g_base[b*Dm + j4*4]);
    reinterpret_cast<float4*>(out)[i] = v;
}

// ---------------- kernel 9: rank-64 corrections for top rows ------------------
__global__ __launch_bounds__(256) void corr_kernel(const float* __restrict__ Wo,
                                                   float* __restrict__ out){
    const int i = blockIdx.x;
    const int bh = i / Uv;
    const int b = bh / Hh, h = bh % Hh;
    const int l = g_top[i];
    __shared__ float delta[DKv];
    const int t = threadIdx.x;
    if (t < DKv)
        delta[t] = g_ctx[(size_t)i*DKv + t] - g_vsum[b*Dm + h*DKv + t]*(1.0f/Lv);
    __syncthreads();
    for (int j = t; j < Dm; j += 256) {
        const float4* wr = reinterpret_cast<const float4*>(Wo + (size_t)j*Dm + h*DKv);
        float s = 0.f;
        #pragma unroll
        for (int dd = 0; dd < 16; ++dd) {
            float4 wv = wr[dd];
            s += delta[dd*4+0]*wv.x + delta[dd*4+1]*wv.y
               + delta[dd*4+2]*wv.z + delta[dd*4+3]*wv.w;
        }
        atomicAdd(&out[(size_t)(b*Lv + l)*Dm + j], s);
    }
}

// ---------------- launch ------------------------------------------------------
extern "C" void kernel_launch(void* const* d_in, const int* in_sizes, int n_in,
                              void* d_out, int out_size)
{
    const float* x    = (const float*)d_in[0];
    const float* Wq   = (const float*)d_in[1];
    const float* bq   = (const float*)d_in[2];
    const float* Wk   = (const float*)d_in[3];
    const float* bk   = (const float*)d_in[4];
    const float* Wv   = (const float*)d_in[5];
    const float* bv   = (const float*)d_in[6];
    const float* Wo   = (const float*)d_in[7];
    const float* bo   = (const float*)d_in[8];
    const int*   idxk = (const int*)d_in[9];
    float* out = (float*)d_out;

    cudaFuncSetAttribute(qkv_f16_kernel,
                         cudaFuncAttributeMaxDynamicSharedMemorySize, 65536);
    cudaFuncSetAttribute(attn_partial_kernel,
                         cudaFuncAttributeMaxDynamicSharedMemorySize, 55424);

    split_x_kernel<<<(2048*64*32)/256, 256>>>(x);
    split_w_kernel<<<(3*128*64*32)/256, 256>>>(Wq, Wk, Wv);
    qkv_f16_kernel<<<dim3(Dm/128, BLv/128, 3), 256, 65536>>>(bq, bk, bv);
    m_kernel<<<dim3(Lv/128, Hh, Bv), 128>>>(idxk);
    vsum_kernel<<<dim3(Dm/128, Lv/256, Bv), 128>>>();
    topk_kernel<<<Bv*Hh, 256>>>();
    attn_partial_kernel<<<dim3(Bv*Hh, SPLIT), 512, 55424>>>();
    attn_combine_kernel<<<Bv*Hh*Uv, 64>>>();
    base_kernel<<<dim3(Dm/8, Bv), 256>>>(Wo, bo);
    fill_kernel<<<(BLv*Dm/4)/256, 256>>>(out);
    corr_kernel<<<Bv*Hh*Uv, 256>>>(Wo, out);
}

// round 12
// speedup vs baseline: 3.2483x; 1.0606x over previous
#include <cuda_runtime.h>
#include <cuda_fp16.h>
#include <math.h>
#include <stdint.h>

#define Bv 4
#define Lv 8192
#define Dm 1024
#define Hh 16
#define DKv 64
#define Uv 50
#define BLv (Bv*Lv)            // 32768
#define SPLIT 8
#define LSPL (Lv/SPLIT)        // 1024
#define TK 32

// ---------------- scratch (device globals; no allocations allowed) ----------
#define XS_CELLS ((size_t)2048*64*32)
__device__ float g_Q[BLv*Dm];          // 128 MB
__device__ float g_K[BLv*Dm];          // 128 MB
__device__ float g_V[BLv*Dm];          // 128 MB
__device__ uint32_t g_XS[XS_CELLS*8];             // 128 MB: X limbs, hi plane then lo plane
__device__ uint32_t g_WS[(size_t)3*128*64*32*4];  // 12 MB: W limbs (x32), frag order
__device__ float g_M[Bv*Hh*Lv];
__device__ int   g_top[Bv*Hh*Uv];
__device__ float g_pm[Bv*Hh*SPLIT*Uv];
__device__ float g_pl[Bv*Hh*SPLIT*Uv];
__device__ float g_pctx[Bv*Hh*SPLIT*Uv*DKv];
__device__ float g_ctx[Bv*Hh*Uv*DKv];
__device__ float g_vsum[Bv*Dm];
__device__ float g_base[Bv*Dm];

// ---------------- helpers ----------------------------------------------------
__device__ __forceinline__ uint32_t packsplit(float x, float y, uint32_t &lo){
    __half hx = __float2half_rn(x);
    __half hy = __float2half_rn(y);
    __half lx = __float2half_rn(x - __half2float(hx));
    __half ly = __float2half_rn(y - __half2float(hy));
    __half2 h2 = __halves2half2(hx, hy);
    __half2 l2 = __halves2half2(lx, ly);
    lo = *reinterpret_cast<uint32_t*>(&l2);
    return *reinterpret_cast<uint32_t*>(&h2);
}

__device__ __forceinline__ void mma16(float* c, const uint32_t* a, const uint32_t* b){
    asm volatile(
        "mma.sync.aligned.m16n8k16.row.col.f32.f16.f16.f32 "
        "{%0,%1,%2,%3}, {%4,%5,%6,%7}, {%8,%9}, {%0,%1,%2,%3};"
        : "+f"(c[0]), "+f"(c[1]), "+f"(c[2]), "+f"(c[3])
        : "r"(a[0]), "r"(a[1]), "r"(a[2]), "r"(a[3]), "r"(b[0]), "r"(b[1]));
}

__device__ __forceinline__ uint32_t sm_u32(const void* p){
    uint32_t a;
    asm("{ .reg .u64 t; cvta.to.shared.u64 t, %1; cvt.u32.u64 %0, t; }"
        : "=r"(a) : "l"(p));
    return a;
}

__device__ __forceinline__ void cpasync16(uint32_t dst, const void* src){
    asm volatile("cp.async.cg.shared.global [%0], [%1], 16;"
                 :: "r"(dst), "l"(src) : "memory");
}
#define CP_COMMIT() asm volatile("cp.async.commit_group;" ::: "memory")
#define CP_WAIT1()  asm volatile("cp.async.wait_group 1;" ::: "memory")

// ---------------- kernel A: split X into limb planes (frag order) -----------
__global__ __launch_bounds__(256) void split_x_kernel(const float* __restrict__ X){
    const int id = blockIdx.x*256 + threadIdx.x;
    const int mb   = id >> 11;
    const int c    = (id >> 5) & 63;
    const int lane = id & 31;
    const int r0 = mb*16 + (lane >> 2);
    const int k0 = c*16 + 2*(lane & 3);
    const float* p0 = X + (size_t)r0*Dm + k0;
    float2 a00 = *reinterpret_cast<const float2*>(p0);
    float2 a10 = *reinterpret_cast<const float2*>(p0 + 8*Dm);
    float2 a01 = *reinterpret_cast<const float2*>(p0 + 8);
    float2 a11 = *reinterpret_cast<const float2*>(p0 + 8*Dm + 8);
    uint32_t h0,h1,h2,h3, l0,l1,l2,l3;
    h0 = packsplit(a00.x, a00.y, l0);
    h1 = packsplit(a10.x, a10.y, l1);
    h2 = packsplit(a01.x, a01.y, l2);
    h3 = packsplit(a11.x, a11.y, l3);
    *reinterpret_cast<uint4*>(&g_XS[(size_t)id*4])              = make_uint4(h0,h1,h2,h3);
    *reinterpret_cast<uint4*>(&g_XS[XS_CELLS*4 + (size_t)id*4]) = make_uint4(l0,l1,l2,l3);
}

// ---------------- kernel B: split W (x32) into limbs; also zero vsum ---------
__global__ __launch_bounds__(256) void split_w_kernel(
    const float* __restrict__ Wq, const float* __restrict__ Wk,
    const float* __restrict__ Wv)
{
    if (blockIdx.x < 16) g_vsum[blockIdx.x*256 + threadIdx.x] = 0.0f;

    const int id = blockIdx.x*256 + threadIdx.x;
    const int gemm = id >> 18;
    const int rem  = id & 262143;
    const int nb   = rem >> 11;
    const int c    = (rem >> 5) & 63;
    const int lane = rem & 31;
    const float* W = (gemm == 0) ? Wq : (gemm == 1) ? Wk : Wv;
    const int row = nb*8 + (lane >> 2);
    const int k0  = c*16 + 2*(lane & 3);
    const float* p = W + (size_t)row*Dm + k0;
    float2 b0 = *reinterpret_cast<const float2*>(p);
    float2 b1 = *reinterpret_cast<const float2*>(p + 8);
    uint32_t bh0, bh1, bl0, bl1;
    bh0 = packsplit(b0.x*32.f, b0.y*32.f, bl0);
    bh1 = packsplit(b1.x*32.f, b1.y*32.f, bl1);
    reinterpret_cast<uint4*>(&g_WS[(size_t)id*4])[0] = make_uint4(bh0,bh1,bl0,bl1);
}

// ======================= kernel 1: QKV GEMM (R9-best pipeline) ===============
__global__ __launch_bounds__(256,2) void qkv_f16_kernel(
    const float* __restrict__ bq, const float* __restrict__ bk,
    const float* __restrict__ bv)
{
    const int gemm = blockIdx.z;
    const float* bias = (gemm == 0) ? bq : (gemm == 1) ? bk : bv;
    float* out = (gemm == 0) ? g_Q : (gemm == 1) ? g_K : g_V;

    const int n0 = blockIdx.x * 128;
    const int m0 = blockIdx.y * 128;

    extern __shared__ uint32_t smq[];
    const uint32_t smb = sm_u32(smq);

    const int t = threadIdx.x;
    const int lane = t & 31;
    const int wid  = t >> 5;
    const int warp_m = wid & 3;
    const int warp_n = wid >> 2;

    const int fA = wid, lA = lane;
    const char* srcAh = (const char*)g_XS
        + ((size_t)((blockIdx.y*8 + fA)*64)*32 + lA)*16;
    const char* srcAl = srcAh + XS_CELLS*16;
    const char* srcB1 = (const char*)g_WS
        + ((size_t)((gemm*128 + blockIdx.x*16 + fA)*64)*32 + lA)*16;
    const char* srcB2 = srcB1 + (size_t)8*64*32*16;
    const uint32_t dAh = (fA*32 + lA)*16;
    const uint32_t dAl = dAh + 4096;
    const uint32_t dB1 = 8192 + (fA*32 + lA)*16;
    const uint32_t dB2 = dB1 + 4096;

    float acc[2][8][4];
    #pragma unroll
    for (int i = 0; i < 2; ++i)
        #pragma unroll
        for (int j = 0; j < 8; ++j)
            #pragma unroll
            for (int r = 0; r < 4; ++r) acc[i][j][r] = 0.0f;

    #pragma unroll
    for (int p = 0; p < 2; ++p) {
        const uint32_t b = smb + p*16384;
        cpasync16(b + dAh, srcAh + (size_t)p*512);
        cpasync16(b + dAl, srcAl + (size_t)p*512);
        cpasync16(b + dB1, srcB1 + (size_t)p*512);
        cpasync16(b + dB2, srcB2 + (size_t)p*512);
        CP_COMMIT();
    }

    #pragma unroll 1
    for (int c = 0; c < 64; ++c) {
        CP_WAIT1();
        __syncthreads();

        if (c + 2 < 64) {
            const uint32_t b = smb + ((c+2) & 3)*16384;
            cpasync16(b + dAh, srcAh + (size_t)(c+2)*512);
            cpasync16(b + dAl, srcAl + (size_t)(c+2)*512);
            cpasync16(b + dB1, srcB1 + (size_t)(c+2)*512);
            cpasync16(b + dB2, srcB2 + (size_t)(c+2)*512);
        }
        CP_COMMIT();

        const uint32_t* C = smq + (c & 3)*4096;
        uint32_t ah[2][4], al[2][4];
        #pragma unroll
        for (int im = 0; im < 2; ++im) {
            const int base = ((warp_m*2 + im)*32 + lane)*4;
            *reinterpret_cast<uint4*>(ah[im]) = *reinterpret_cast<const uint4*>(&C[base]);
            *reinterpret_cast<uint4*>(al[im]) = *reinterpret_cast<const uint4*>(&C[base + 1024]);
        }
        #pragma unroll
        for (int in = 0; in < 8; ++in) {
            const int base = 2048 + ((warp_n*8 + in)*32 + lane)*4;
            uint4 q = *reinterpret_cast<const uint4*>(&C[base]);
            uint32_t bh[2] = {q.x, q.y};
            uint32_t bl[2] = {q.z, q.w};
            #pragma unroll
            for (int im = 0; im < 2; ++im) {
                mma16(acc[im][in], al[im], bh);
                mma16(acc[im][in], ah[im], bl);
                mma16(acc[im][in], ah[im], bh);
            }
        }
    }

    const float inv32 = 0.03125f;
    #pragma unroll
    for (int im = 0; im < 2; ++im) {
        const int m = m0 + warp_m*32 + im*16 + (lane >> 2);
        #pragma unroll
        for (int in = 0; in < 8; ++in) {
            const int n = n0 + warp_n*64 + in*8 + (lane & 3)*2;
            const float b0 = __ldg(&bias[n]);
            const float b1 = __ldg(&bias[n+1]);
            float2 v0 = make_float2(acc[im][in][0]*inv32 + b0, acc[im][in][1]*inv32 + b1);
            float2 v1 = make_float2(acc[im][in][2]*inv32 + b0, acc[im][in][3]*inv32 + b1);
            *reinterpret_cast<float2*>(&out[(size_t)m*Dm + n])     = v0;
            *reinterpret_cast<float2*>(&out[(size_t)(m+8)*Dm + n]) = v1;
        }
    }
}

// ---------------- kernel 2: sparsity measure M via tensor cores --------------
// Per block: scores[128 x 56] = Q_tile[128 x 64] @ K_samp[56 x 64]^T (3-limb f16),
// then M[row] = max_u - mean_u over the 50 valid cols.
__global__ __launch_bounds__(256) void m_tc_kernel(const int* __restrict__ idx_k){
    const int b = blockIdx.z, h = blockIdx.y;
    const int l0 = blockIdx.x * 128;

    __shared__ uint32_t Ah[8][4][32][4];   // 16 KB  A hi limbs [frag][chunk][lane][4]
    __shared__ uint32_t Al[8][4][32][4];   // 16 KB  A lo limbs
    __shared__ uint32_t Bs[7][4][32][4];   // 14 KB  B {bh0,bh1,bl0,bl1}

    const int t = threadIdx.x;
    const int lane = t & 31;
    const int w = t >> 5;

    // ---- A producer: 1024 cells (frag, lane, chunk), 4 per thread ----
    #pragma unroll
    for (int i = 0; i < 4; ++i) {
        const int id = t + i*256;
        const int frag = id >> 7, ln = (id >> 2) & 31, ch = id & 3;
        const int r0 = l0 + frag*16 + (ln >> 2);
        const int c0 = ch*16 + 2*(ln & 3);
        const float* q0 = &g_Q[(size_t)(b*Lv + r0)*Dm + h*DKv + c0];
        const float* q1 = q0 + 8*Dm;
        float2 x00 = *reinterpret_cast<const float2*>(q0);
        float2 x10 = *reinterpret_cast<const float2*>(q1);
        float2 x01 = *reinterpret_cast<const float2*>(q0 + 8);
        float2 x11 = *reinterpret_cast<const float2*>(q1 + 8);
        uint32_t h0,h1,h2,h3, e0,e1,e2,e3;
        h0 = packsplit(x00.x, x00.y, e0);
        h1 = packsplit(x10.x, x10.y, e1);
        h2 = packsplit(x01.x, x01.y, e2);
        h3 = packsplit(x11.x, x11.y, e3);
        *reinterpret_cast<uint4*>(&Ah[frag][ch][ln][0]) = make_uint4(h0,h1,h2,h3);
        *reinterpret_cast<uint4*>(&Al[frag][ch][ln][0]) = make_uint4(e0,e1,e2,e3);
    }
    // ---- B producer: 896 cells (gathered K_samp rows; n>=50 zero) ----
    #pragma unroll
    for (int i = 0; i < 4; ++i) {
        const int id = t + i*256;
        if (id < 896) {
            const int frag = id >> 7, ln = (id >> 2) & 31, ch = id & 3;
            const int n = frag*8 + (ln >> 2);
            uint32_t bh0=0, bh1=0, bl0=0, bl1=0;
            if (n < Uv) {
                const int row = __ldg(&idx_k[n]);
                const int c0 = ch*16 + 2*(ln & 3);
                const float* kp = &g_K[(size_t)(b*Lv + row)*Dm + h*DKv + c0];
                float2 y0 = *reinterpret_cast<const float2*>(kp);
                float2 y1 = *reinterpret_cast<const float2*>(kp + 8);
                bh0 = packsplit(y0.x, y0.y, bl0);
                bh1 = packsplit(y1.x, y1.y, bl1);
            }
            *reinterpret_cast<uint4*>(&Bs[frag][ch][ln][0]) = make_uint4(bh0,bh1,bl0,bl1);
        }
    }
    __syncthreads();

    // ---- MMA phase: warp w = A frag w (rows w*16..w*16+15) ----
    float acc[7][4];
    #pragma unroll
    for (int in = 0; in < 7; ++in)
        #pragma unroll
        for (int r = 0; r < 4; ++r) acc[in][r] = 0.0f;

    #pragma unroll
    for (int ch = 0; ch < 4; ++ch) {
        uint32_t ahr[4], alr[4];
        *reinterpret_cast<uint4*>(ahr) = *reinterpret_cast<const uint4*>(&Ah[w][ch][lane][0]);
        *reinterpret_cast<uint4*>(alr) = *reinterpret_cast<const uint4*>(&Al[w][ch][lane][0]);
        #pragma unroll
        for (int in = 0; in < 7; ++in) {
            uint4 q = *reinterpret_cast<const uint4*>(&Bs[in][ch][lane][0]);
            uint32_t bh[2] = {q.x, q.y};
            uint32_t bl[2] = {q.z, q.w};
            mma16(acc[in], alr, bh);
            mma16(acc[in], ahr, bl);
            mma16(acc[in], ahr, bh);
        }
    }

    // ---- epilogue: masked max/sum over 50 cols, 4-lane butterfly ----
    const int colbase = (lane & 3)*2;
    float mx0 = -1e30f, sm0 = 0.f, mx1 = -1e30f, sm1 = 0.f;
    #pragma unroll
    for (int in = 0; in < 7; ++in) {
        const int c0 = in*8 + colbase;
        if (c0 < Uv) {
            mx0 = fmaxf(mx0, acc[in][0]); sm0 += acc[in][0];
            mx1 = fmaxf(mx1, acc[in][2]); sm1 += acc[in][2];
        }
        if (c0 + 1 < Uv) {
            mx0 = fmaxf(mx0, acc[in][1]); sm0 += acc[in][1];
            mx1 = fmaxf(mx1, acc[in][3]); sm1 += acc[in][3];
        }
    }
    #pragma unroll
    for (int o = 1; o < 4; o <<= 1) {
        mx0 = fmaxf(mx0, __shfl_xor_sync(0xffffffffu, mx0, o));
        sm0 += __shfl_xor_sync(0xffffffffu, sm0, o);
        mx1 = fmaxf(mx1, __shfl_xor_sync(0xffffffffu, mx1, o));
        sm1 += __shfl_xor_sync(0xffffffffu, sm1, o);
    }
    if ((lane & 3) == 0) {
        const int r = l0 + w*16 + (lane >> 2);
        float* Mrow = &g_M[(size_t)(b*Hh + h)*Lv + r];
        Mrow[0] = mx0 - sm0*(1.0f/Uv);
        Mrow[8] = mx1 - sm1*(1.0f/Uv);
    }
}

// ---------------- kernel 3: top-k (k=50 of 8192) per (b,h) -------------------
__global__ __launch_bounds__(256) void topk_kernel(){
    const int bh = blockIdx.x;
    __shared__ float vals[Lv];
    __shared__ float rv[256];
    __shared__ int   ri[256];
    const int t = threadIdx.x;

    for (int i = t; i < Lv; i += 256) vals[i] = g_M[(size_t)bh*Lv + i];
    __syncthreads();

    for (int it = 0; it < Uv; ++it) {
        float best = -1e30f; int bi = Lv;
        for (int i = t; i < Lv; i += 256) {
            float v = vals[i];
            if (v > best || (v == best && i < bi)) { best = v; bi = i; }
        }
        rv[t] = best; ri[t] = bi;
        __syncthreads();
        for (int s = 128; s > 0; s >>= 1) {
            if (t < s) {
                if (rv[t+s] > rv[t] || (rv[t+s] == rv[t] && ri[t+s] < ri[t])) {
                    rv[t] = rv[t+s]; ri[t] = ri[t+s];
                }
            }
            __syncthreads();
        }
        if (t == 0) { g_top[bh*Uv + it] = ri[0]; vals[ri[0]] = -1e30f; }
        __syncthreads();
    }
}

// ---------------- kernel 4: V column sums (for mean) -------------------------
__global__ void vsum_kernel(){
    const int b = blockIdx.z;
    const int d = blockIdx.x*128 + threadIdx.x;
    const int c = blockIdx.y;
    float s = 0.0f;
    const int lbeg = c*256, lend = lbeg + 256;
    for (int l = lbeg; l < lend; ++l) s += g_V[(size_t)(b*Lv + l)*Dm + d];
    atomicAdd(&g_vsum[b*Dm + d], s);
}

// ---------------- kernel 5: flash attention (cp.async + parallel softmax) ----
__global__ __launch_bounds__(512) void attn_partial_kernel(){
    extern __shared__ float sma[];
    const int bh = blockIdx.x;
    const int sp = blockIdx.y;
    const int b = bh / Hh, h = bh % Hh;
    const int t = threadIdx.x;

    float* Qs  = sma;
    float* Ps  = sma + 11904;
    float* m_s = sma + 13704;
    float* l_s = sma + 13754;
    float* c_s = sma + 13804;
    const uint32_t smab = sm_u32(sma);

    for (int i = t; i < Uv*DKv; i += 512) {
        int q = i >> 6, d = i & 63;
        int l = g_top[bh*Uv + q];
        Qs[q*64 + d] = g_Q[(size_t)(b*Lv + l)*Dm + h*DKv + d];
    }
    if (t < Uv) { m_s[t] = -1e30f; l_s[t] = 0.0f; }

    float ctx[7];
    #pragma unroll
    for (int j = 0; j < 7; ++j) ctx[j] = 0.0f;
    const int d = t & 63;
    const int qb = t >> 6;

    const int ldrow = t >> 4;
    const int lddq  = t & 15;
    const uint32_t kdst = smab + (3200 + ldrow*68 + lddq*4)*4;
    const uint32_t vdst = kdst + 2176*4;

    {
        size_t g = (size_t)(b*Lv + sp*LSPL + ldrow)*Dm + h*DKv + lddq*4;
        cpasync16(kdst, &g_K[g]);
        cpasync16(vdst, &g_V[g]);
    }
    CP_COMMIT();

    const int NT = LSPL/TK;   // 32
    #pragma unroll 1
    for (int i = 0; i < NT; ++i) {
        __syncthreads();
        if (i + 1 < NT) {
            const uint32_t off = ((i+1) & 1)*4352*4;
            size_t g = (size_t)(b*Lv + sp*LSPL + (i+1)*TK + ldrow)*Dm + h*DKv + lddq*4;
            cpasync16(kdst + off, &g_K[g]);
            cpasync16(vdst + off, &g_V[g]);
        }
        CP_COMMIT();
        CP_WAIT1();
        __syncthreads();

        const float* Ks = sma + 3200 + (i & 1)*4352;
        const float* Vs = Ks + 2176;

        if (t < 400) {
            const int q = t >> 3, kg = t & 7;
            float a0 = 0.f, a1 = 0.f, a2 = 0.f, a3 = 0.f;
            #pragma unroll
            for (int dq = 0; dq < 16; ++dq) {
                float4 qv = *reinterpret_cast<const float4*>(&Qs[q*64 + dq*4]);
                float4 k0 = *reinterpret_cast<const float4*>(&Ks[kg*68 + dq*4]);
                float4 k1 = *reinterpret_cast<const float4*>(&Ks[(kg+8)*68 + dq*4]);
                float4 k2 = *reinterpret_cast<const float4*>(&Ks[(kg+16)*68 + dq*4]);
                float4 k3 = *reinterpret_cast<const float4*>(&Ks[(kg+24)*68 + dq*4]);
                a0 += qv.x*k0.x + qv.y*k0.y + qv.z*k0.z + qv.w*k0.w;
                a1 += qv.x*k1.x + qv.y*k1.y + qv.z*k1.z + qv.w*k1.w;
                a2 += qv.x*k2.x + qv.y*k2.y + qv.z*k2.z + qv.w*k2.w;
                a3 += qv.x*k3.x + qv.y*k3.y + qv.z*k3.z + qv.w*k3.w;
            }
            Ps[q*36 + kg]    = a0 * 0.125f;
            Ps[q*36 + kg+8]  = a1 * 0.125f;
            Ps[q*36 + kg+16] = a2 * 0.125f;
            Ps[q*36 + kg+24] = a3 * 0.125f;
        }
        __syncthreads();

        {
            const int q = (t < 400) ? (t >> 3) : 49;
            const int g = t & 7;
            float4 p4 = *reinterpret_cast<const float4*>(&Ps[q*36 + g*4]);
            float lm = fmaxf(fmaxf(p4.x, p4.y), fmaxf(p4.z, p4.w));
            #pragma unroll
            for (int o = 1; o < 8; o <<= 1)
                lm = fmaxf(lm, __shfl_xor_sync(0xffffffffu, lm, o, 8));
            const float mold = m_s[q];
            const float nm = fmaxf(mold, lm);
            p4.x = __expf(p4.x - nm);
            p4.y = __expf(p4.y - nm);
            p4.z = __expf(p4.z - nm);
            p4.w = __expf(p4.w - nm);
            float lsum = p4.x + p4.y + p4.z + p4.w;
            #pragma unroll
            for (int o = 1; o < 8; o <<= 1)
                lsum += __shfl_xor_sync(0xffffffffu, lsum, o, 8);
            if (t < 400) {
                *reinterpret_cast<float4*>(&Ps[q*36 + g*4]) = p4;
                if (g == 0) {
                    float cc = __expf(mold - nm);
                    c_s[q] = cc;
                    l_s[q] = l_s[q]*cc + lsum;
                    m_s[q] = nm;
                }
            }
        }
        __syncthreads();

        {
            float vreg[TK];
            #pragma unroll
            for (int k = 0; k < TK; ++k) vreg[k] = Vs[k*68 + d];
            #pragma unroll
            for (int j = 0; j < 7; ++j) {
                int q = qb + 8*j;
                if (q < Uv) {
                    float a = ctx[j] * c_s[q];
                    #pragma unroll
                    for (int kq = 0; kq < 8; ++kq) {
                        float4 p = *reinterpret_cast<const float4*>(&Ps[q*36 + kq*4]);
                        a += p.x*vreg[kq*4] + p.y*vreg[kq*4+1]
                           + p.z*vreg[kq*4+2] + p.w*vreg[kq*4+3];
                    }
                    ctx[j] = a;
                }
            }
        }
    }

    __syncthreads();
    #pragma unroll
    for (int j = 0; j < 7; ++j) {
        int q = qb + 8*j;
        if (q < Uv)
            g_pctx[(size_t)((bh*SPLIT + sp)*Uv + q)*DKv + d] = ctx[j];
    }
    if (t < Uv) {
        g_pm[(bh*SPLIT + sp)*Uv + t] = m_s[t];
        g_pl[(bh*SPLIT + sp)*Uv + t] = l_s[t];
    }
}

// ---------------- kernel 6: combine split partials ---------------------------
__global__ __launch_bounds__(64) void attn_combine_kernel(){
    const int i = blockIdx.x;
    const int q = i % Uv, bh = i / Uv;
    __shared__ float w[SPLIT];
    __shared__ float inv;
    if (threadIdx.x == 0) {
        float M = -1e30f;
        for (int s = 0; s < SPLIT; ++s) M = fmaxf(M, g_pm[(bh*SPLIT+s)*Uv + q]);
        float tot = 0.f;
        for (int s = 0; s < SPLIT; ++s) {
            float e = __expf(g_pm[(bh*SPLIT+s)*Uv + q] - M);
            w[s] = e;
            tot += g_pl[(bh*SPLIT+s)*Uv + q] * e;
        }
        inv = 1.0f / tot;
    }
    __syncthreads();
    const int d = threadIdx.x;
    float c = 0.f;
    for (int s = 0; s < SPLIT; ++s)
        c += g_pctx[(size_t)((bh*SPLIT+s)*Uv + q)*DKv + d] * w[s];
    g_ctx[(size_t)i*DKv + d] = c * inv;
}

// ---------------- kernel 7: base output row per batch ------------------------
__global__ __launch_bounds__(256) void base_kernel(const float* __restrict__ Wo,
                                                   const float* __restrict__ bo){
    const int b = blockIdx.y;
    const int warp = threadIdx.x >> 5, lane = threadIdx.x & 31;
    const int j = blockIdx.x*8 + warp;
    float s = 0.f;
    for (int d0 = lane; d0 < Dm; d0 += 32)
        s += g_vsum[b*Dm + d0] * Wo[(size_t)j*Dm + d0];
    #pragma unroll
    for (int o = 16; o; o >>= 1) s += __shfl_down_sync(0xffffffffu, s, o);
    if (lane == 0) g_base[b*Dm + j] = s*(1.0f/Lv) + bo[j];
}

// ---------------- kernel 8: broadcast base rows into output -------------------
__global__ void fill_kernel(float* __restrict__ out){
    const int i = blockIdx.x*blockDim.x + threadIdx.x;
    const int b  = i >> 21;
    const int j4 = i & 255;
    float4 v = *reinterpret_cast<const float4*>(&g_base[b*Dm + j4*4]);
    reinterpret_cast<float4*>(out)[i] = v;
}

// ---------------- kernel 9: rank-64 corrections for top rows ------------------
__global__ __launch_bounds__(256) void corr_kernel(const float* __restrict__ Wo,
                                                   float* __restrict__ out){
    const int i = blockIdx.x;
    const int bh = i / Uv;
    const int b = bh / Hh, h = bh % Hh;
    const int l = g_top[i];
    __shared__ float delta[DKv];
    const int t = threadIdx.x;
    if (t < DKv)
        delta[t] = g_ctx[(size_t)i*DKv + t] - g_vsum[b*Dm + h*DKv + t]*(1.0f/Lv);
    __syncthreads();
    for (int j = t; j < Dm; j += 256) {
        const float4* wr = reinterpret_cast<const float4*>(Wo + (size_t)j*Dm + h*DKv);
        float s = 0.f;
        #pragma unroll
        for (int dd = 0; dd < 16; ++dd) {
            float4 wv = wr[dd];
            s += delta[dd*4+0]*wv.x + delta[dd*4+1]*wv.y
               + delta[dd*4+2]*wv.z + delta[dd*4+3]*wv.w;
        }
        atomicAdd(&out[(size_t)(b*Lv + l)*Dm + j], s);
    }
}

// ---------------- launch ------------------------------------------------------
extern "C" void kernel_launch(void* const* d_in, const int* in_sizes, int n_in,
                              void* d_out, int out_size)
{
    const float* x    = (const float*)d_in[0];
    const float* Wq   = (const float*)d_in[1];
    const float* bq   = (const float*)d_in[2];
    const float* Wk   = (const float*)d_in[3];
    const float* bk   = (const float*)d_in[4];
    const float* Wv   = (const float*)d_in[5];
    const float* bv   = (const float*)d_in[6];
    const float* Wo   = (const float*)d_in[7];
    const float* bo   = (const float*)d_in[8];
    const int*   idxk = (const int*)d_in[9];
    float* out = (float*)d_out;

    cudaFuncSetAttribute(qkv_f16_kernel,
                         cudaFuncAttributeMaxDynamicSharedMemorySize, 65536);
    cudaFuncSetAttribute(attn_partial_kernel,
                         cudaFuncAttributeMaxDynamicSharedMemorySize, 55424);

    split_x_kernel<<<(2048*64*32)/256, 256>>>(x);
    split_w_kernel<<<(3*128*64*32)/256, 256>>>(Wq, Wk, Wv);
    qkv_f16_kernel<<<dim3(Dm/128, BLv/128, 3), 256, 65536>>>(bq, bk, bv);
    m_tc_kernel<<<dim3(Lv/128, Hh, Bv), 256>>>(idxk);
    vsum_kernel<<<dim3(Dm/128, Lv/256, Bv), 128>>>();
    topk_kernel<<<Bv*Hh, 256>>>();
    attn_partial_kernel<<<dim3(Bv*Hh, SPLIT), 512, 55424>>>();
    attn_combine_kernel<<<Bv*Hh*Uv, 64>>>();
    base_kernel<<<dim3(Dm/8, Bv), 256>>>(Wo, bo);
    fill_kernel<<<(BLv*Dm/4)/256, 256>>>(out);
    corr_kernel<<<Bv*Hh*Uv, 256>>>(Wo, out);
}

// round 13
// speedup vs baseline: 3.5259x; 1.0855x over previous
#include <cuda_runtime.h>
#include <cuda_fp16.h>
#include <math.h>
#include <stdint.h>

#define Bv 4
#define Lv 8192
#define Dm 1024
#define Hh 16
#define DKv 64
#define Uv 50
#define BLv (Bv*Lv)            // 32768
#define SPLIT 8
#define LSPL (Lv/SPLIT)        // 1024
#define TK 32

// ---------------- scratch (device globals; no allocations allowed) ----------
#define XS_CELLS ((size_t)2048*64*32)
__device__ float g_Q[BLv*Dm];          // 128 MB
__device__ float g_K[BLv*Dm];          // 128 MB
__device__ float g_V[BLv*Dm];          // 128 MB
__device__ uint32_t g_XS[XS_CELLS*8];             // 128 MB: X limbs, hi plane then lo plane
__device__ uint32_t g_WS[(size_t)3*128*64*32*4];  // 12 MB: W limbs (x32), frag order
__device__ float g_M[Bv*Hh*Lv];
__device__ int   g_top[Bv*Hh*Uv];
__device__ float g_pm[Bv*Hh*SPLIT*Uv];
__device__ float g_pl[Bv*Hh*SPLIT*Uv];
__device__ float g_pctx[Bv*Hh*SPLIT*Uv*DKv];
__device__ float g_ctx[Bv*Hh*Uv*DKv];
__device__ float g_vsum[Bv*Dm];
__device__ float g_base[Bv*Dm];

// ---------------- helpers ----------------------------------------------------
__device__ __forceinline__ uint32_t packsplit(float x, float y, uint32_t &lo){
    __half hx = __float2half_rn(x);
    __half hy = __float2half_rn(y);
    __half lx = __float2half_rn(x - __half2float(hx));
    __half ly = __float2half_rn(y - __half2float(hy));
    __half2 h2 = __halves2half2(hx, hy);
    __half2 l2 = __halves2half2(lx, ly);
    lo = *reinterpret_cast<uint32_t*>(&l2);
    return *reinterpret_cast<uint32_t*>(&h2);
}

__device__ __forceinline__ void mma16(float* c, const uint32_t* a, const uint32_t* b){
    asm volatile(
        "mma.sync.aligned.m16n8k16.row.col.f32.f16.f16.f32 "
        "{%0,%1,%2,%3}, {%4,%5,%6,%7}, {%8,%9}, {%0,%1,%2,%3};"
        : "+f"(c[0]), "+f"(c[1]), "+f"(c[2]), "+f"(c[3])
        : "r"(a[0]), "r"(a[1]), "r"(a[2]), "r"(a[3]), "r"(b[0]), "r"(b[1]));
}

__device__ __forceinline__ uint32_t sm_u32(const void* p){
    uint32_t a;
    asm("{ .reg .u64 t; cvta.to.shared.u64 t, %1; cvt.u32.u64 %0, t; }"
        : "=r"(a) : "l"(p));
    return a;
}

__device__ __forceinline__ void cpasync16(uint32_t dst, const void* src){
    asm volatile("cp.async.cg.shared.global [%0], [%1], 16;"
                 :: "r"(dst), "l"(src) : "memory");
}
#define CP_COMMIT() asm volatile("cp.async.commit_group;" ::: "memory")
#define CP_WAIT1()  asm volatile("cp.async.wait_group 1;" ::: "memory")

// ---------------- kernel A: split X into limb planes (frag order) -----------
__global__ __launch_bounds__(256) void split_x_kernel(const float* __restrict__ X){
    const int id = blockIdx.x*256 + threadIdx.x;
    const int mb   = id >> 11;
    const int c    = (id >> 5) & 63;
    const int lane = id & 31;
    const int r0 = mb*16 + (lane >> 2);
    const int k0 = c*16 + 2*(lane & 3);
    const float* p0 = X + (size_t)r0*Dm + k0;
    float2 a00 = *reinterpret_cast<const float2*>(p0);
    float2 a10 = *reinterpret_cast<const float2*>(p0 + 8*Dm);
    float2 a01 = *reinterpret_cast<const float2*>(p0 + 8);
    float2 a11 = *reinterpret_cast<const float2*>(p0 + 8*Dm + 8);
    uint32_t h0,h1,h2,h3, l0,l1,l2,l3;
    h0 = packsplit(a00.x, a00.y, l0);
    h1 = packsplit(a10.x, a10.y, l1);
    h2 = packsplit(a01.x, a01.y, l2);
    h3 = packsplit(a11.x, a11.y, l3);
    *reinterpret_cast<uint4*>(&g_XS[(size_t)id*4])              = make_uint4(h0,h1,h2,h3);
    *reinterpret_cast<uint4*>(&g_XS[XS_CELLS*4 + (size_t)id*4]) = make_uint4(l0,l1,l2,l3);
}

// ---------------- kernel B: split W (x32) into limbs; also zero vsum ---------
__global__ __launch_bounds__(256) void split_w_kernel(
    const float* __restrict__ Wq, const float* __restrict__ Wk,
    const float* __restrict__ Wv)
{
    if (blockIdx.x < 16) g_vsum[blockIdx.x*256 + threadIdx.x] = 0.0f;

    const int id = blockIdx.x*256 + threadIdx.x;
    const int gemm = id >> 18;
    const int rem  = id & 262143;
    const int nb   = rem >> 11;
    const int c    = (rem >> 5) & 63;
    const int lane = rem & 31;
    const float* W = (gemm == 0) ? Wq : (gemm == 1) ? Wk : Wv;
    const int row = nb*8 + (lane >> 2);
    const int k0  = c*16 + 2*(lane & 3);
    const float* p = W + (size_t)row*Dm + k0;
    float2 b0 = *reinterpret_cast<const float2*>(p);
    float2 b1 = *reinterpret_cast<const float2*>(p + 8);
    uint32_t bh0, bh1, bl0, bl1;
    bh0 = packsplit(b0.x*32.f, b0.y*32.f, bl0);
    bh1 = packsplit(b1.x*32.f, b1.y*32.f, bl1);
    reinterpret_cast<uint4*>(&g_WS[(size_t)id*4])[0] = make_uint4(bh0,bh1,bl0,bl1);
}

// ======================= kernel 1: QKV GEMM (R9-best pipeline) ===============
__global__ __launch_bounds__(256,2) void qkv_f16_kernel(
    const float* __restrict__ bq, const float* __restrict__ bk,
    const float* __restrict__ bv)
{
    const int gemm = blockIdx.z;
    const float* bias = (gemm == 0) ? bq : (gemm == 1) ? bk : bv;
    float* out = (gemm == 0) ? g_Q : (gemm == 1) ? g_K : g_V;

    const int n0 = blockIdx.x * 128;
    const int m0 = blockIdx.y * 128;

    extern __shared__ uint32_t smq[];
    const uint32_t smb = sm_u32(smq);

    const int t = threadIdx.x;
    const int lane = t & 31;
    const int wid  = t >> 5;
    const int warp_m = wid & 3;
    const int warp_n = wid >> 2;

    const int fA = wid, lA = lane;
    const char* srcAh = (const char*)g_XS
        + ((size_t)((blockIdx.y*8 + fA)*64)*32 + lA)*16;
    const char* srcAl = srcAh + XS_CELLS*16;
    const char* srcB1 = (const char*)g_WS
        + ((size_t)((gemm*128 + blockIdx.x*16 + fA)*64)*32 + lA)*16;
    const char* srcB2 = srcB1 + (size_t)8*64*32*16;
    const uint32_t dAh = (fA*32 + lA)*16;
    const uint32_t dAl = dAh + 4096;
    const uint32_t dB1 = 8192 + (fA*32 + lA)*16;
    const uint32_t dB2 = dB1 + 4096;

    float acc[2][8][4];
    #pragma unroll
    for (int i = 0; i < 2; ++i)
        #pragma unroll
        for (int j = 0; j < 8; ++j)
            #pragma unroll
            for (int r = 0; r < 4; ++r) acc[i][j][r] = 0.0f;

    #pragma unroll
    for (int p = 0; p < 2; ++p) {
        const uint32_t b = smb + p*16384;
        cpasync16(b + dAh, srcAh + (size_t)p*512);
        cpasync16(b + dAl, srcAl + (size_t)p*512);
        cpasync16(b + dB1, srcB1 + (size_t)p*512);
        cpasync16(b + dB2, srcB2 + (size_t)p*512);
        CP_COMMIT();
    }

    #pragma unroll 1
    for (int c = 0; c < 64; ++c) {
        CP_WAIT1();
        __syncthreads();

        if (c + 2 < 64) {
            const uint32_t b = smb + ((c+2) & 3)*16384;
            cpasync16(b + dAh, srcAh + (size_t)(c+2)*512);
            cpasync16(b + dAl, srcAl + (size_t)(c+2)*512);
            cpasync16(b + dB1, srcB1 + (size_t)(c+2)*512);
            cpasync16(b + dB2, srcB2 + (size_t)(c+2)*512);
        }
        CP_COMMIT();

        const uint32_t* C = smq + (c & 3)*4096;
        uint32_t ah[2][4], al[2][4];
        #pragma unroll
        for (int im = 0; im < 2; ++im) {
            const int base = ((warp_m*2 + im)*32 + lane)*4;
            *reinterpret_cast<uint4*>(ah[im]) = *reinterpret_cast<const uint4*>(&C[base]);
            *reinterpret_cast<uint4*>(al[im]) = *reinterpret_cast<const uint4*>(&C[base + 1024]);
        }
        #pragma unroll
        for (int in = 0; in < 8; ++in) {
            const int base = 2048 + ((warp_n*8 + in)*32 + lane)*4;
            uint4 q = *reinterpret_cast<const uint4*>(&C[base]);
            uint32_t bh[2] = {q.x, q.y};
            uint32_t bl[2] = {q.z, q.w};
            #pragma unroll
            for (int im = 0; im < 2; ++im) {
                mma16(acc[im][in], al[im], bh);
                mma16(acc[im][in], ah[im], bl);
                mma16(acc[im][in], ah[im], bh);
            }
        }
    }

    const float inv32 = 0.03125f;
    #pragma unroll
    for (int im = 0; im < 2; ++im) {
        const int m = m0 + warp_m*32 + im*16 + (lane >> 2);
        #pragma unroll
        for (int in = 0; in < 8; ++in) {
            const int n = n0 + warp_n*64 + in*8 + (lane & 3)*2;
            const float b0 = __ldg(&bias[n]);
            const float b1 = __ldg(&bias[n+1]);
            float2 v0 = make_float2(acc[im][in][0]*inv32 + b0, acc[im][in][1]*inv32 + b1);
            float2 v1 = make_float2(acc[im][in][2]*inv32 + b0, acc[im][in][3]*inv32 + b1);
            *reinterpret_cast<float2*>(&out[(size_t)m*Dm + n])     = v0;
            *reinterpret_cast<float2*>(&out[(size_t)(m+8)*Dm + n]) = v1;
        }
    }
}

// ---------------- kernel 2: sparsity measure M via tensor cores --------------
__global__ __launch_bounds__(256) void m_tc_kernel(const int* __restrict__ idx_k){
    const int b = blockIdx.z, h = blockIdx.y;
    const int l0 = blockIdx.x * 128;

    __shared__ uint32_t Ah[8][4][32][4];
    __shared__ uint32_t Al[8][4][32][4];
    __shared__ uint32_t Bs[7][4][32][4];

    const int t = threadIdx.x;
    const int lane = t & 31;
    const int w = t >> 5;

    #pragma unroll
    for (int i = 0; i < 4; ++i) {
        const int id = t + i*256;
        const int frag = id >> 7, ln = (id >> 2) & 31, ch = id & 3;
        const int r0 = l0 + frag*16 + (ln >> 2);
        const int c0 = ch*16 + 2*(ln & 3);
        const float* q0 = &g_Q[(size_t)(b*Lv + r0)*Dm + h*DKv + c0];
        const float* q1 = q0 + 8*Dm;
        float2 x00 = *reinterpret_cast<const float2*>(q0);
        float2 x10 = *reinterpret_cast<const float2*>(q1);
        float2 x01 = *reinterpret_cast<const float2*>(q0 + 8);
        float2 x11 = *reinterpret_cast<const float2*>(q1 + 8);
        uint32_t h0,h1,h2,h3, e0,e1,e2,e3;
        h0 = packsplit(x00.x, x00.y, e0);
        h1 = packsplit(x10.x, x10.y, e1);
        h2 = packsplit(x01.x, x01.y, e2);
        h3 = packsplit(x11.x, x11.y, e3);
        *reinterpret_cast<uint4*>(&Ah[frag][ch][ln][0]) = make_uint4(h0,h1,h2,h3);
        *reinterpret_cast<uint4*>(&Al[frag][ch][ln][0]) = make_uint4(e0,e1,e2,e3);
    }
    #pragma unroll
    for (int i = 0; i < 4; ++i) {
        const int id = t + i*256;
        if (id < 896) {
            const int frag = id >> 7, ln = (id >> 2) & 31, ch = id & 3;
            const int n = frag*8 + (ln >> 2);
            uint32_t bh0=0, bh1=0, bl0=0, bl1=0;
            if (n < Uv) {
                const int row = __ldg(&idx_k[n]);
                const int c0 = ch*16 + 2*(ln & 3);
                const float* kp = &g_K[(size_t)(b*Lv + row)*Dm + h*DKv + c0];
                float2 y0 = *reinterpret_cast<const float2*>(kp);
                float2 y1 = *reinterpret_cast<const float2*>(kp + 8);
                bh0 = packsplit(y0.x, y0.y, bl0);
                bh1 = packsplit(y1.x, y1.y, bl1);
            }
            *reinterpret_cast<uint4*>(&Bs[frag][ch][ln][0]) = make_uint4(bh0,bh1,bl0,bl1);
        }
    }
    __syncthreads();

    float acc[7][4];
    #pragma unroll
    for (int in = 0; in < 7; ++in)
        #pragma unroll
        for (int r = 0; r < 4; ++r) acc[in][r] = 0.0f;

    #pragma unroll
    for (int ch = 0; ch < 4; ++ch) {
        uint32_t ahr[4], alr[4];
        *reinterpret_cast<uint4*>(ahr) = *reinterpret_cast<const uint4*>(&Ah[w][ch][lane][0]);
        *reinterpret_cast<uint4*>(alr) = *reinterpret_cast<const uint4*>(&Al[w][ch][lane][0]);
        #pragma unroll
        for (int in = 0; in < 7; ++in) {
            uint4 q = *reinterpret_cast<const uint4*>(&Bs[in][ch][lane][0]);
            uint32_t bh[2] = {q.x, q.y};
            uint32_t bl[2] = {q.z, q.w};
            mma16(acc[in], alr, bh);
            mma16(acc[in], ahr, bl);
            mma16(acc[in], ahr, bh);
        }
    }

    const int colbase = (lane & 3)*2;
    float mx0 = -1e30f, sm0 = 0.f, mx1 = -1e30f, sm1 = 0.f;
    #pragma unroll
    for (int in = 0; in < 7; ++in) {
        const int c0 = in*8 + colbase;
        if (c0 < Uv) {
            mx0 = fmaxf(mx0, acc[in][0]); sm0 += acc[in][0];
            mx1 = fmaxf(mx1, acc[in][2]); sm1 += acc[in][2];
        }
        if (c0 + 1 < Uv) {
            mx0 = fmaxf(mx0, acc[in][1]); sm0 += acc[in][1];
            mx1 = fmaxf(mx1, acc[in][3]); sm1 += acc[in][3];
        }
    }
    #pragma unroll
    for (int o = 1; o < 4; o <<= 1) {
        mx0 = fmaxf(mx0, __shfl_xor_sync(0xffffffffu, mx0, o));
        sm0 += __shfl_xor_sync(0xffffffffu, sm0, o);
        mx1 = fmaxf(mx1, __shfl_xor_sync(0xffffffffu, mx1, o));
        sm1 += __shfl_xor_sync(0xffffffffu, sm1, o);
    }
    if ((lane & 3) == 0) {
        const int r = l0 + w*16 + (lane >> 2);
        float* Mrow = &g_M[(size_t)(b*Hh + h)*Lv + r];
        Mrow[0] = mx0 - sm0*(1.0f/Uv);
        Mrow[8] = mx1 - sm1*(1.0f/Uv);
    }
}

// ---------------- kernel 3: top-k (k=50 of 8192) per (b,h) -------------------
__global__ __launch_bounds__(256) void topk_kernel(){
    const int bh = blockIdx.x;
    __shared__ float vals[Lv];
    __shared__ float rv[256];
    __shared__ int   ri[256];
    const int t = threadIdx.x;

    for (int i = t; i < Lv; i += 256) vals[i] = g_M[(size_t)bh*Lv + i];
    __syncthreads();

    for (int it = 0; it < Uv; ++it) {
        float best = -1e30f; int bi = Lv;
        for (int i = t; i < Lv; i += 256) {
            float v = vals[i];
            if (v > best || (v == best && i < bi)) { best = v; bi = i; }
        }
        rv[t] = best; ri[t] = bi;
        __syncthreads();
        for (int s = 128; s > 0; s >>= 1) {
            if (t < s) {
                if (rv[t+s] > rv[t] || (rv[t+s] == rv[t] && ri[t+s] < ri[t])) {
                    rv[t] = rv[t+s]; ri[t] = ri[t+s];
                }
            }
            __syncthreads();
        }
        if (t == 0) { g_top[bh*Uv + it] = ri[0]; vals[ri[0]] = -1e30f; }
        __syncthreads();
    }
}

// ---------------- kernel 4: V column sums (for mean) -------------------------
__global__ void vsum_kernel(){
    const int b = blockIdx.z;
    const int d = blockIdx.x*128 + threadIdx.x;
    const int c = blockIdx.y;
    float s = 0.0f;
    const int lbeg = c*256, lend = lbeg + 256;
    for (int l = lbeg; l < lend; ++l) s += g_V[(size_t)(b*Lv + l)*Dm + d];
    atomicAdd(&g_vsum[b*Dm + d], s);
}

// ---------------- kernel 5: flash attention (cp.async + parallel softmax) ----
__global__ __launch_bounds__(512) void attn_partial_kernel(){
    extern __shared__ float sma[];
    const int bh = blockIdx.x;
    const int sp = blockIdx.y;
    const int b = bh / Hh, h = bh % Hh;
    const int t = threadIdx.x;

    float* Qs  = sma;
    float* Ps  = sma + 11904;
    float* m_s = sma + 13704;
    float* l_s = sma + 13754;
    float* c_s = sma + 13804;
    const uint32_t smab = sm_u32(sma);

    for (int i = t; i < Uv*DKv; i += 512) {
        int q = i >> 6, d = i & 63;
        int l = g_top[bh*Uv + q];
        Qs[q*64 + d] = g_Q[(size_t)(b*Lv + l)*Dm + h*DKv + d];
    }
    if (t < Uv) { m_s[t] = -1e30f; l_s[t] = 0.0f; }

    float ctx[7];
    #pragma unroll
    for (int j = 0; j < 7; ++j) ctx[j] = 0.0f;
    const int d = t & 63;
    const int qb = t >> 6;

    const int ldrow = t >> 4;
    const int lddq  = t & 15;
    const uint32_t kdst = smab + (3200 + ldrow*68 + lddq*4)*4;
    const uint32_t vdst = kdst + 2176*4;

    {
        size_t g = (size_t)(b*Lv + sp*LSPL + ldrow)*Dm + h*DKv + lddq*4;
        cpasync16(kdst, &g_K[g]);
        cpasync16(vdst, &g_V[g]);
    }
    CP_COMMIT();

    const int NT = LSPL/TK;   // 32
    #pragma unroll 1
    for (int i = 0; i < NT; ++i) {
        __syncthreads();
        if (i + 1 < NT) {
            const uint32_t off = ((i+1) & 1)*4352*4;
            size_t g = (size_t)(b*Lv + sp*LSPL + (i+1)*TK + ldrow)*Dm + h*DKv + lddq*4;
            cpasync16(kdst + off, &g_K[g]);
            cpasync16(vdst + off, &g_V[g]);
        }
        CP_COMMIT();
        CP_WAIT1();
        __syncthreads();

        const float* Ks = sma + 3200 + (i & 1)*4352;
        const float* Vs = Ks + 2176;

        if (t < 400) {
            const int q = t >> 3, kg = t & 7;
            float a0 = 0.f, a1 = 0.f, a2 = 0.f, a3 = 0.f;
            #pragma unroll
            for (int dq = 0; dq < 16; ++dq) {
                float4 qv = *reinterpret_cast<const float4*>(&Qs[q*64 + dq*4]);
                float4 k0 = *reinterpret_cast<const float4*>(&Ks[kg*68 + dq*4]);
                float4 k1 = *reinterpret_cast<const float4*>(&Ks[(kg+8)*68 + dq*4]);
                float4 k2 = *reinterpret_cast<const float4*>(&Ks[(kg+16)*68 + dq*4]);
                float4 k3 = *reinterpret_cast<const float4*>(&Ks[(kg+24)*68 + dq*4]);
                a0 += qv.x*k0.x + qv.y*k0.y + qv.z*k0.z + qv.w*k0.w;
                a1 += qv.x*k1.x + qv.y*k1.y + qv.z*k1.z + qv.w*k1.w;
                a2 += qv.x*k2.x + qv.y*k2.y + qv.z*k2.z + qv.w*k2.w;
                a3 += qv.x*k3.x + qv.y*k3.y + qv.z*k3.z + qv.w*k3.w;
            }
            Ps[q*36 + kg]    = a0 * 0.125f;
            Ps[q*36 + kg+8]  = a1 * 0.125f;
            Ps[q*36 + kg+16] = a2 * 0.125f;
            Ps[q*36 + kg+24] = a3 * 0.125f;
        }
        __syncthreads();

        {
            const int q = (t < 400) ? (t >> 3) : 49;
            const int g = t & 7;
            float4 p4 = *reinterpret_cast<const float4*>(&Ps[q*36 + g*4]);
            float lm = fmaxf(fmaxf(p4.x, p4.y), fmaxf(p4.z, p4.w));
            #pragma unroll
            for (int o = 1; o < 8; o <<= 1)
                lm = fmaxf(lm, __shfl_xor_sync(0xffffffffu, lm, o, 8));
            const float mold = m_s[q];
            const float nm = fmaxf(mold, lm);
            p4.x = __expf(p4.x - nm);
            p4.y = __expf(p4.y - nm);
            p4.z = __expf(p4.z - nm);
            p4.w = __expf(p4.w - nm);
            float lsum = p4.x + p4.y + p4.z + p4.w;
            #pragma unroll
            for (int o = 1; o < 8; o <<= 1)
                lsum += __shfl_xor_sync(0xffffffffu, lsum, o, 8);
            if (t < 400) {
                *reinterpret_cast<float4*>(&Ps[q*36 + g*4]) = p4;
                if (g == 0) {
                    float cc = __expf(mold - nm);
                    c_s[q] = cc;
                    l_s[q] = l_s[q]*cc + lsum;
                    m_s[q] = nm;
                }
            }
        }
        __syncthreads();

        {
            float vreg[TK];
            #pragma unroll
            for (int k = 0; k < TK; ++k) vreg[k] = Vs[k*68 + d];
            #pragma unroll
            for (int j = 0; j < 7; ++j) {
                int q = qb + 8*j;
                if (q < Uv) {
                    float a = ctx[j] * c_s[q];
                    #pragma unroll
                    for (int kq = 0; kq < 8; ++kq) {
                        float4 p = *reinterpret_cast<const float4*>(&Ps[q*36 + kq*4]);
                        a += p.x*vreg[kq*4] + p.y*vreg[kq*4+1]
                           + p.z*vreg[kq*4+2] + p.w*vreg[kq*4+3];
                    }
                    ctx[j] = a;
                }
            }
        }
    }

    __syncthreads();
    #pragma unroll
    for (int j = 0; j < 7; ++j) {
        int q = qb + 8*j;
        if (q < Uv)
            g_pctx[(size_t)((bh*SPLIT + sp)*Uv + q)*DKv + d] = ctx[j];
    }
    if (t < Uv) {
        g_pm[(bh*SPLIT + sp)*Uv + t] = m_s[t];
        g_pl[(bh*SPLIT + sp)*Uv + t] = l_s[t];
    }
}

// ---------------- kernel 6: combine split partials ---------------------------
__global__ __launch_bounds__(64) void attn_combine_kernel(){
    const int i = blockIdx.x;
    const int q = i % Uv, bh = i / Uv;
    __shared__ float w[SPLIT];
    __shared__ float inv;
    if (threadIdx.x == 0) {
        float M = -1e30f;
        for (int s = 0; s < SPLIT; ++s) M = fmaxf(M, g_pm[(bh*SPLIT+s)*Uv + q]);
        float tot = 0.f;
        for (int s = 0; s < SPLIT; ++s) {
            float e = __expf(g_pm[(bh*SPLIT+s)*Uv + q] - M);
            w[s] = e;
            tot += g_pl[(bh*SPLIT+s)*Uv + q] * e;
        }
        inv = 1.0f / tot;
    }
    __syncthreads();
    const int d = threadIdx.x;
    float c = 0.f;
    for (int s = 0; s < SPLIT; ++s)
        c += g_pctx[(size_t)((bh*SPLIT+s)*Uv + q)*DKv + d] * w[s];
    g_ctx[(size_t)i*DKv + d] = c * inv;
}

// ---------------- kernel 7: base output row per batch ------------------------
__global__ __launch_bounds__(256) void base_kernel(const float* __restrict__ Wo,
                                                   const float* __restrict__ bo){
    const int b = blockIdx.y;
    const int warp = threadIdx.x >> 5, lane = threadIdx.x & 31;
    const int j = blockIdx.x*8 + warp;
    float s = 0.f;
    for (int d0 = lane; d0 < Dm; d0 += 32)
        s += g_vsum[b*Dm + d0] * Wo[(size_t)j*Dm + d0];
    #pragma unroll
    for (int o = 16; o; o >>= 1) s += __shfl_down_sync(0xffffffffu, s, o);
    if (lane == 0) g_base[b*Dm + j] = s*(1.0f/Lv) + bo[j];
}

// ---------------- kernel 8: broadcast base rows into output -------------------
__global__ void fill_kernel(float* __restrict__ out){
    const int i = blockIdx.x*blockDim.x + threadIdx.x;
    const int b  = i >> 21;
    const int j4 = i & 255;
    float4 v = *reinterpret_cast<const float4*>(&g_base[b*Dm + j4*4]);
    reinterpret_cast<float4*>(out)[i] = v;
}

// ---------------- kernel 9: rank-64 corrections (Wo read once per block) -----
// grid (4, Bv*Hh): block owns 256 j-columns for one (b,h); delta[50] in smem.
__global__ __launch_bounds__(256) void corr_kernel(const float* __restrict__ Wo,
                                                   float* __restrict__ out){
    const int bh = blockIdx.y;
    const int b = bh / Hh, h = bh % Hh;
    const int j = blockIdx.x*256 + threadIdx.x;
    const int t = threadIdx.x;

    __shared__ float delta[Uv][DKv];
    __shared__ int   ls[Uv];

    if (t < Uv) ls[t] = g_top[bh*Uv + t];
    for (int i = t; i < Uv*DKv; i += 256) {
        const int u = i >> 6, dd = i & 63;
        delta[u][dd] = g_ctx[(size_t)(bh*Uv + u)*DKv + dd]
                     - g_vsum[b*Dm + h*DKv + dd]*(1.0f/Lv);
    }
    __syncthreads();

    // Wo row slice in registers (64 floats)
    float4 w[16];
    const float4* wr = reinterpret_cast<const float4*>(Wo + (size_t)j*Dm + h*DKv);
    #pragma unroll
    for (int dd = 0; dd < 16; ++dd) w[dd] = wr[dd];

    #pragma unroll 2
    for (int u = 0; u < Uv; ++u) {
        float s = 0.f;
        #pragma unroll
        for (int dd = 0; dd < 16; ++dd) {
            s += delta[u][dd*4+0]*w[dd].x + delta[u][dd*4+1]*w[dd].y
               + delta[u][dd*4+2]*w[dd].z + delta[u][dd*4+3]*w[dd].w;
        }
        atomicAdd(&out[(size_t)(b*Lv + ls[u])*Dm + j], s);
    }
}

// ---------------- launch ------------------------------------------------------
extern "C" void kernel_launch(void* const* d_in, const int* in_sizes, int n_in,
                              void* d_out, int out_size)
{
    const float* x    = (const float*)d_in[0];
    const float* Wq   = (const float*)d_in[1];
    const float* bq   = (const float*)d_in[2];
    const float* Wk   = (const float*)d_in[3];
    const float* bk   = (const float*)d_in[4];
    const float* Wv   = (const float*)d_in[5];
    const float* bv   = (const float*)d_in[6];
    const float* Wo   = (const float*)d_in[7];
    const float* bo   = (const float*)d_in[8];
    const int*   idxk = (const int*)d_in[9];
    float* out = (float*)d_out;

    cudaFuncSetAttribute(qkv_f16_kernel,
                         cudaFuncAttributeMaxDynamicSharedMemorySize, 65536);
    cudaFuncSetAttribute(attn_partial_kernel,
                         cudaFuncAttributeMaxDynamicSharedMemorySize, 55424);

    split_x_kernel<<<(2048*64*32)/256, 256>>>(x);
    split_w_kernel<<<(3*128*64*32)/256, 256>>>(Wq, Wk, Wv);
    qkv_f16_kernel<<<dim3(Dm/128, BLv/128, 3), 256, 65536>>>(bq, bk, bv);
    m_tc_kernel<<<dim3(Lv/128, Hh, Bv), 256>>>(idxk);
    vsum_kernel<<<dim3(Dm/128, Lv/256, Bv), 128>>>();
    topk_kernel<<<Bv*Hh, 256>>>();
    attn_partial_kernel<<<dim3(Bv*Hh, SPLIT), 512, 55424>>>();
    attn_combine_kernel<<<Bv*Hh*Uv, 64>>>();
    base_kernel<<<dim3(Dm/8, Bv), 256>>>(Wo, bo);
    fill_kernel<<<(BLv*Dm/4)/256, 256>>>(out);
    corr_kernel<<<dim3(4, Bv*Hh), 256>>>(Wo, out);
}

// round 14
// speedup vs baseline: 4.1998x; 1.1911x over previous
#include <cuda_runtime.h>
#include <cuda_fp16.h>
#include <math.h>
#include <stdint.h>

#define Bv 4
#define Lv 8192
#define Dm 1024
#define Hh 16
#define DKv 64
#define Uv 50
#define BLv (Bv*Lv)            // 32768
#define SPLIT 8
#define LSPL (Lv/SPLIT)        // 1024
#define TK 32

// ---------------- scratch (device globals; no allocations allowed) ----------
#define XS_CELLS ((size_t)2048*64*32)
__device__ float g_Q[BLv*Dm];          // 128 MB
__device__ float g_K[BLv*Dm];          // 128 MB
__device__ float g_V[BLv*Dm];          // 128 MB
__device__ uint32_t g_XS[XS_CELLS*8];             // 128 MB: X limbs, hi plane then lo plane
__device__ uint32_t g_WS[(size_t)3*128*64*32*4];  // 12 MB: W limbs (x32), frag order
__device__ float g_M[Bv*Hh*Lv];
__device__ int   g_top[Bv*Hh*Uv];
__device__ float g_pm[Bv*Hh*SPLIT*Uv];
__device__ float g_pl[Bv*Hh*SPLIT*Uv];
__device__ float g_pctx[Bv*Hh*SPLIT*Uv*DKv];
__device__ float g_ctx[Bv*Hh*Uv*DKv];
__device__ float g_vsum[Bv*Dm];
__device__ float g_base[Bv*Dm];

// ---------------- helpers ----------------------------------------------------
__device__ __forceinline__ uint32_t packsplit(float x, float y, uint32_t &lo){
    __half hx = __float2half_rn(x);
    __half hy = __float2half_rn(y);
    __half lx = __float2half_rn(x - __half2float(hx));
    __half ly = __float2half_rn(y - __half2float(hy));
    __half2 h2 = __halves2half2(hx, hy);
    __half2 l2 = __halves2half2(lx, ly);
    lo = *reinterpret_cast<uint32_t*>(&l2);
    return *reinterpret_cast<uint32_t*>(&h2);
}

__device__ __forceinline__ void mma16(float* c, const uint32_t* a, const uint32_t* b){
    asm volatile(
        "mma.sync.aligned.m16n8k16.row.col.f32.f16.f16.f32 "
        "{%0,%1,%2,%3}, {%4,%5,%6,%7}, {%8,%9}, {%0,%1,%2,%3};"
        : "+f"(c[0]), "+f"(c[1]), "+f"(c[2]), "+f"(c[3])
        : "r"(a[0]), "r"(a[1]), "r"(a[2]), "r"(a[3]), "r"(b[0]), "r"(b[1]));
}

__device__ __forceinline__ uint32_t sm_u32(const void* p){
    uint32_t a;
    asm("{ .reg .u64 t; cvta.to.shared.u64 t, %1; cvt.u32.u64 %0, t; }"
        : "=r"(a) : "l"(p));
    return a;
}

__device__ __forceinline__ void cpasync16(uint32_t dst, const void* src){
    asm volatile("cp.async.cg.shared.global [%0], [%1], 16;"
                 :: "r"(dst), "l"(src) : "memory");
}
#define CP_COMMIT() asm volatile("cp.async.commit_group;" ::: "memory")
#define CP_WAIT1()  asm volatile("cp.async.wait_group 1;" ::: "memory")

// ---------------- kernel A: split X into limb planes (frag order) -----------
__global__ __launch_bounds__(256) void split_x_kernel(const float* __restrict__ X){
    const int id = blockIdx.x*256 + threadIdx.x;
    const int mb   = id >> 11;
    const int c    = (id >> 5) & 63;
    const int lane = id & 31;
    const int r0 = mb*16 + (lane >> 2);
    const int k0 = c*16 + 2*(lane & 3);
    const float* p0 = X + (size_t)r0*Dm + k0;
    float2 a00 = *reinterpret_cast<const float2*>(p0);
    float2 a10 = *reinterpret_cast<const float2*>(p0 + 8*Dm);
    float2 a01 = *reinterpret_cast<const float2*>(p0 + 8);
    float2 a11 = *reinterpret_cast<const float2*>(p0 + 8*Dm + 8);
    uint32_t h0,h1,h2,h3, l0,l1,l2,l3;
    h0 = packsplit(a00.x, a00.y, l0);
    h1 = packsplit(a10.x, a10.y, l1);
    h2 = packsplit(a01.x, a01.y, l2);
    h3 = packsplit(a11.x, a11.y, l3);
    *reinterpret_cast<uint4*>(&g_XS[(size_t)id*4])              = make_uint4(h0,h1,h2,h3);
    *reinterpret_cast<uint4*>(&g_XS[XS_CELLS*4 + (size_t)id*4]) = make_uint4(l0,l1,l2,l3);
}

// ---------------- kernel B: split W (x32) into limbs; also zero vsum ---------
__global__ __launch_bounds__(256) void split_w_kernel(
    const float* __restrict__ Wq, const float* __restrict__ Wk,
    const float* __restrict__ Wv)
{
    if (blockIdx.x < 16) g_vsum[blockIdx.x*256 + threadIdx.x] = 0.0f;

    const int id = blockIdx.x*256 + threadIdx.x;
    const int gemm = id >> 18;
    const int rem  = id & 262143;
    const int nb   = rem >> 11;
    const int c    = (rem >> 5) & 63;
    const int lane = rem & 31;
    const float* W = (gemm == 0) ? Wq : (gemm == 1) ? Wk : Wv;
    const int row = nb*8 + (lane >> 2);
    const int k0  = c*16 + 2*(lane & 3);
    const float* p = W + (size_t)row*Dm + k0;
    float2 b0 = *reinterpret_cast<const float2*>(p);
    float2 b1 = *reinterpret_cast<const float2*>(p + 8);
    uint32_t bh0, bh1, bl0, bl1;
    bh0 = packsplit(b0.x*32.f, b0.y*32.f, bl0);
    bh1 = packsplit(b1.x*32.f, b1.y*32.f, bl1);
    reinterpret_cast<uint4*>(&g_WS[(size_t)id*4])[0] = make_uint4(bh0,bh1,bl0,bl1);
}

// ======================= kernel 1: QKV GEMM (R9-best pipeline) ===============
__global__ __launch_bounds__(256,2) void qkv_f16_kernel(
    const float* __restrict__ bq, const float* __restrict__ bk,
    const float* __restrict__ bv)
{
    const int gemm = blockIdx.z;
    const float* bias = (gemm == 0) ? bq : (gemm == 1) ? bk : bv;
    float* out = (gemm == 0) ? g_Q : (gemm == 1) ? g_K : g_V;

    const int n0 = blockIdx.x * 128;
    const int m0 = blockIdx.y * 128;

    extern __shared__ uint32_t smq[];
    const uint32_t smb = sm_u32(smq);

    const int t = threadIdx.x;
    const int lane = t & 31;
    const int wid  = t >> 5;
    const int warp_m = wid & 3;
    const int warp_n = wid >> 2;

    const int fA = wid, lA = lane;
    const char* srcAh = (const char*)g_XS
        + ((size_t)((blockIdx.y*8 + fA)*64)*32 + lA)*16;
    const char* srcAl = srcAh + XS_CELLS*16;
    const char* srcB1 = (const char*)g_WS
        + ((size_t)((gemm*128 + blockIdx.x*16 + fA)*64)*32 + lA)*16;
    const char* srcB2 = srcB1 + (size_t)8*64*32*16;
    const uint32_t dAh = (fA*32 + lA)*16;
    const uint32_t dAl = dAh + 4096;
    const uint32_t dB1 = 8192 + (fA*32 + lA)*16;
    const uint32_t dB2 = dB1 + 4096;

    float acc[2][8][4];
    #pragma unroll
    for (int i = 0; i < 2; ++i)
        #pragma unroll
        for (int j = 0; j < 8; ++j)
            #pragma unroll
            for (int r = 0; r < 4; ++r) acc[i][j][r] = 0.0f;

    #pragma unroll
    for (int p = 0; p < 2; ++p) {
        const uint32_t b = smb + p*16384;
        cpasync16(b + dAh, srcAh + (size_t)p*512);
        cpasync16(b + dAl, srcAl + (size_t)p*512);
        cpasync16(b + dB1, srcB1 + (size_t)p*512);
        cpasync16(b + dB2, srcB2 + (size_t)p*512);
        CP_COMMIT();
    }

    #pragma unroll 1
    for (int c = 0; c < 64; ++c) {
        CP_WAIT1();
        __syncthreads();

        if (c + 2 < 64) {
            const uint32_t b = smb + ((c+2) & 3)*16384;
            cpasync16(b + dAh, srcAh + (size_t)(c+2)*512);
            cpasync16(b + dAl, srcAl + (size_t)(c+2)*512);
            cpasync16(b + dB1, srcB1 + (size_t)(c+2)*512);
            cpasync16(b + dB2, srcB2 + (size_t)(c+2)*512);
        }
        CP_COMMIT();

        const uint32_t* C = smq + (c & 3)*4096;
        uint32_t ah[2][4], al[2][4];
        #pragma unroll
        for (int im = 0; im < 2; ++im) {
            const int base = ((warp_m*2 + im)*32 + lane)*4;
            *reinterpret_cast<uint4*>(ah[im]) = *reinterpret_cast<const uint4*>(&C[base]);
            *reinterpret_cast<uint4*>(al[im]) = *reinterpret_cast<const uint4*>(&C[base + 1024]);
        }
        #pragma unroll
        for (int in = 0; in < 8; ++in) {
            const int base = 2048 + ((warp_n*8 + in)*32 + lane)*4;
            uint4 q = *reinterpret_cast<const uint4*>(&C[base]);
            uint32_t bh[2] = {q.x, q.y};
            uint32_t bl[2] = {q.z, q.w};
            #pragma unroll
            for (int im = 0; im < 2; ++im) {
                mma16(acc[im][in], al[im], bh);
                mma16(acc[im][in], ah[im], bl);
                mma16(acc[im][in], ah[im], bh);
            }
        }
    }

    const float inv32 = 0.03125f;
    #pragma unroll
    for (int im = 0; im < 2; ++im) {
        const int m = m0 + warp_m*32 + im*16 + (lane >> 2);
        #pragma unroll
        for (int in = 0; in < 8; ++in) {
            const int n = n0 + warp_n*64 + in*8 + (lane & 3)*2;
            const float b0 = __ldg(&bias[n]);
            const float b1 = __ldg(&bias[n+1]);
            float2 v0 = make_float2(acc[im][in][0]*inv32 + b0, acc[im][in][1]*inv32 + b1);
            float2 v1 = make_float2(acc[im][in][2]*inv32 + b0, acc[im][in][3]*inv32 + b1);
            *reinterpret_cast<float2*>(&out[(size_t)m*Dm + n])     = v0;
            *reinterpret_cast<float2*>(&out[(size_t)(m+8)*Dm + n]) = v1;
        }
    }
}

// ---------------- kernel 2: sparsity measure M via tensor cores --------------
__global__ __launch_bounds__(256) void m_tc_kernel(const int* __restrict__ idx_k){
    const int b = blockIdx.z, h = blockIdx.y;
    const int l0 = blockIdx.x * 128;

    __shared__ uint32_t Ah[8][4][32][4];
    __shared__ uint32_t Al[8][4][32][4];
    __shared__ uint32_t Bs[7][4][32][4];

    const int t = threadIdx.x;
    const int lane = t & 31;
    const int w = t >> 5;

    #pragma unroll
    for (int i = 0; i < 4; ++i) {
        const int id = t + i*256;
        const int frag = id >> 7, ln = (id >> 2) & 31, ch = id & 3;
        const int r0 = l0 + frag*16 + (ln >> 2);
        const int c0 = ch*16 + 2*(ln & 3);
        const float* q0 = &g_Q[(size_t)(b*Lv + r0)*Dm + h*DKv + c0];
        const float* q1 = q0 + 8*Dm;
        float2 x00 = *reinterpret_cast<const float2*>(q0);
        float2 x10 = *reinterpret_cast<const float2*>(q1);
        float2 x01 = *reinterpret_cast<const float2*>(q0 + 8);
        float2 x11 = *reinterpret_cast<const float2*>(q1 + 8);
        uint32_t h0,h1,h2,h3, e0,e1,e2,e3;
        h0 = packsplit(x00.x, x00.y, e0);
        h1 = packsplit(x10.x, x10.y, e1);
        h2 = packsplit(x01.x, x01.y, e2);
        h3 = packsplit(x11.x, x11.y, e3);
        *reinterpret_cast<uint4*>(&Ah[frag][ch][ln][0]) = make_uint4(h0,h1,h2,h3);
        *reinterpret_cast<uint4*>(&Al[frag][ch][ln][0]) = make_uint4(e0,e1,e2,e3);
    }
    #pragma unroll
    for (int i = 0; i < 4; ++i) {
        const int id = t + i*256;
        if (id < 896) {
            const int frag = id >> 7, ln = (id >> 2) & 31, ch = id & 3;
            const int n = frag*8 + (ln >> 2);
            uint32_t bh0=0, bh1=0, bl0=0, bl1=0;
            if (n < Uv) {
                const int row = __ldg(&idx_k[n]);
                const int c0 = ch*16 + 2*(ln & 3);
                const float* kp = &g_K[(size_t)(b*Lv + row)*Dm + h*DKv + c0];
                float2 y0 = *reinterpret_cast<const float2*>(kp);
                float2 y1 = *reinterpret_cast<const float2*>(kp + 8);
                bh0 = packsplit(y0.x, y0.y, bl0);
                bh1 = packsplit(y1.x, y1.y, bl1);
            }
            *reinterpret_cast<uint4*>(&Bs[frag][ch][ln][0]) = make_uint4(bh0,bh1,bl0,bl1);
        }
    }
    __syncthreads();

    float acc[7][4];
    #pragma unroll
    for (int in = 0; in < 7; ++in)
        #pragma unroll
        for (int r = 0; r < 4; ++r) acc[in][r] = 0.0f;

    #pragma unroll
    for (int ch = 0; ch < 4; ++ch) {
        uint32_t ahr[4], alr[4];
        *reinterpret_cast<uint4*>(ahr) = *reinterpret_cast<const uint4*>(&Ah[w][ch][lane][0]);
        *reinterpret_cast<uint4*>(alr) = *reinterpret_cast<const uint4*>(&Al[w][ch][lane][0]);
        #pragma unroll
        for (int in = 0; in < 7; ++in) {
            uint4 q = *reinterpret_cast<const uint4*>(&Bs[in][ch][lane][0]);
            uint32_t bh[2] = {q.x, q.y};
            uint32_t bl[2] = {q.z, q.w};
            mma16(acc[in], alr, bh);
            mma16(acc[in], ahr, bl);
            mma16(acc[in], ahr, bh);
        }
    }

    const int colbase = (lane & 3)*2;
    float mx0 = -1e30f, sm0 = 0.f, mx1 = -1e30f, sm1 = 0.f;
    #pragma unroll
    for (int in = 0; in < 7; ++in) {
        const int c0 = in*8 + colbase;
        if (c0 < Uv) {
            mx0 = fmaxf(mx0, acc[in][0]); sm0 += acc[in][0];
            mx1 = fmaxf(mx1, acc[in][2]); sm1 += acc[in][2];
        }
        if (c0 + 1 < Uv) {
            mx0 = fmaxf(mx0, acc[in][1]); sm0 += acc[in][1];
            mx1 = fmaxf(mx1, acc[in][3]); sm1 += acc[in][3];
        }
    }
    #pragma unroll
    for (int o = 1; o < 4; o <<= 1) {
        mx0 = fmaxf(mx0, __shfl_xor_sync(0xffffffffu, mx0, o));
        sm0 += __shfl_xor_sync(0xffffffffu, sm0, o);
        mx1 = fmaxf(mx1, __shfl_xor_sync(0xffffffffu, mx1, o));
        sm1 += __shfl_xor_sync(0xffffffffu, sm1, o);
    }
    if ((lane & 3) == 0) {
        const int r = l0 + w*16 + (lane >> 2);
        float* Mrow = &g_M[(size_t)(b*Hh + h)*Lv + r];
        Mrow[0] = mx0 - sm0*(1.0f/Uv);
        Mrow[8] = mx1 - sm1*(1.0f/Uv);
    }
}

// ---------------- kernel 3: top-k (k=50 of 8192) per (b,h) -------------------
__global__ __launch_bounds__(256) void topk_kernel(){
    const int bh = blockIdx.x;
    __shared__ float vals[Lv];
    __shared__ float rv[256];
    __shared__ int   ri[256];
    const int t = threadIdx.x;

    for (int i = t; i < Lv; i += 256) vals[i] = g_M[(size_t)bh*Lv + i];
    __syncthreads();

    for (int it = 0; it < Uv; ++it) {
        float best = -1e30f; int bi = Lv;
        for (int i = t; i < Lv; i += 256) {
            float v = vals[i];
            if (v > best || (v == best && i < bi)) { best = v; bi = i; }
        }
        rv[t] = best; ri[t] = bi;
        __syncthreads();
        for (int s = 128; s > 0; s >>= 1) {
            if (t < s) {
                if (rv[t+s] > rv[t] || (rv[t+s] == rv[t] && ri[t+s] < ri[t])) {
                    rv[t] = rv[t+s]; ri[t] = ri[t+s];
                }
            }
            __syncthreads();
        }
        if (t == 0) { g_top[bh*Uv + it] = ri[0]; vals[ri[0]] = -1e30f; }
        __syncthreads();
    }
}

// ---------------- kernel 4: V column sums (for mean) -------------------------
__global__ void vsum_kernel(){
    const int b = blockIdx.z;
    const int d = blockIdx.x*128 + threadIdx.x;
    const int c = blockIdx.y;
    float s = 0.0f;
    const int lbeg = c*256, lend = lbeg + 256;
    for (int l = lbeg; l < lend; ++l) s += g_V[(size_t)(b*Lv + l)*Dm + d];
    atomicAdd(&g_vsum[b*Dm + d], s);
}

// ---------------- kernel 5: flash attention (tensor-core QK^T and PV) --------
// smem (floats): Qraw@0 (64x64), Ps@4096 (64x36), m@6400, l@6464, c@6528,
// raw stages @6592 (2 x 4352: K 32x68 + V 32x68),
// Qh@15296 (2048 u32), Ql@17344, Kl@19392 ([4][4][32][4]), Vl@21440 ([8][2][32][4])
// total 23488 floats = 93952 B
__global__ __launch_bounds__(512) void attn_partial_kernel(){
    extern __shared__ float sma[];
    const int bh = blockIdx.x;
    const int sp = blockIdx.y;
    const int b = bh / Hh, h = bh % Hh;
    const int t = threadIdx.x;
    const int lane = t & 31;
    const int w = t >> 5;

    float* Qraw = sma;
    float* Ps   = sma + 4096;
    float* m_s  = sma + 6400;
    float* l_s  = sma + 6464;
    float* c_s  = sma + 6528;
    uint32_t* Qh = reinterpret_cast<uint32_t*>(sma + 15296);
    uint32_t* Ql = Qh + 2048;
    uint32_t* Kl = Ql + 2048;
    uint32_t* Vl = Kl + 2048;
    const uint32_t smab = sm_u32(sma);

    // load Q_top (rows >= 50 zeroed)
    for (int i = t; i < 64*64; i += 512) {
        const int q = i >> 6, d = i & 63;
        float v = 0.0f;
        if (q < Uv) {
            const int l = g_top[bh*Uv + q];
            v = g_Q[(size_t)(b*Lv + l)*Dm + h*DKv + d];
        }
        Qraw[i] = v;
    }
    if (t < Uv) { m_s[t] = -1e30f; l_s[t] = 0.0f; }
    if (t < 64) c_s[t] = 1.0f;
    __syncthreads();

    // convert Q to A-limb fragments (512 cells, 1/thread)
    {
        const int mf = t >> 7, ch = (t >> 5) & 3, ln = t & 31;
        const int r0 = mf*16 + (ln >> 2), k0 = ch*16 + 2*(ln & 3);
        float2 x00 = *reinterpret_cast<const float2*>(&Qraw[r0*64 + k0]);
        float2 x10 = *reinterpret_cast<const float2*>(&Qraw[(r0+8)*64 + k0]);
        float2 x01 = *reinterpret_cast<const float2*>(&Qraw[r0*64 + k0 + 8]);
        float2 x11 = *reinterpret_cast<const float2*>(&Qraw[(r0+8)*64 + k0 + 8]);
        uint32_t h0,h1,h2,h3, e0,e1,e2,e3;
        h0 = packsplit(x00.x, x00.y, e0);
        h1 = packsplit(x10.x, x10.y, e1);
        h2 = packsplit(x01.x, x01.y, e2);
        h3 = packsplit(x11.x, x11.y, e3);
        const int cell = ((mf*4 + ch)*32 + ln)*4;
        *reinterpret_cast<uint4*>(&Qh[cell]) = make_uint4(h0,h1,h2,h3);
        *reinterpret_cast<uint4*>(&Ql[cell]) = make_uint4(e0,e1,e2,e3);
    }

    const int ldrow = t >> 4;
    const int lddq  = t & 15;
    const uint32_t kdst = smab + (6592 + ldrow*68 + lddq*4)*4;
    const uint32_t vdst = kdst + 2176*4;

    {
        size_t g = (size_t)(b*Lv + sp*LSPL + ldrow)*Dm + h*DKv + lddq*4;
        cpasync16(kdst, &g_K[g]);
        cpasync16(vdst, &g_V[g]);
    }
    CP_COMMIT();

    float o[2][4];
    #pragma unroll
    for (int j = 0; j < 2; ++j)
        #pragma unroll
        for (int r = 0; r < 4; ++r) o[j][r] = 0.0f;

    const int mf  = w >> 2;       // A-frag (rows)
    const int nfS = w & 3;        // scores B-frag
    const int nf0 = (w & 3)*2;    // PV B-frag base

    const int NT = LSPL/TK;   // 32
    #pragma unroll 1
    for (int i = 0; i < NT; ++i) {
        __syncthreads();      // prev PV done; Q limbs visible (i=0)
        if (i + 1 < NT) {
            const uint32_t off = ((i+1) & 1)*4352*4;
            size_t g = (size_t)(b*Lv + sp*LSPL + (i+1)*TK + ldrow)*Dm + h*DKv + lddq*4;
            cpasync16(kdst + off, &g_K[g]);
            cpasync16(vdst + off, &g_V[g]);
        }
        CP_COMMIT();
        CP_WAIT1();           // tile i raw data arrived
        __syncthreads();

        const float* Kr = sma + 6592 + (i & 1)*4352;
        const float* Vr = Kr + 2176;

        // convert K tile to B-limb fragments (scores): cell t -> [nf][ch][ln]
        {
            const int nf = t >> 7, ch = (t >> 5) & 3, ln = t & 31;
            const int n = nf*8 + (ln >> 2), k0 = ch*16 + 2*(ln & 3);
            float2 y0 = *reinterpret_cast<const float2*>(&Kr[n*68 + k0]);
            float2 y1 = *reinterpret_cast<const float2*>(&Kr[n*68 + k0 + 8]);
            uint32_t bh0, bh1, bl0, bl1;
            bh0 = packsplit(y0.x, y0.y, bl0);
            bh1 = packsplit(y1.x, y1.y, bl1);
            *reinterpret_cast<uint4*>(&Kl[((nf*4+ch)*32+ln)*4]) = make_uint4(bh0,bh1,bl0,bl1);
        }
        // convert V tile to B-limb fragments (PV): cell t -> [nf][ch][ln]
        {
            const int nf = t >> 6, ch = (t >> 5) & 1, ln = t & 31;
            const int n = nf*8 + (ln >> 2), k0 = ch*16 + 2*(ln & 3);
            float v00 = Vr[k0*68 + n],     v01 = Vr[(k0+1)*68 + n];
            float v10 = Vr[(k0+8)*68 + n], v11 = Vr[(k0+9)*68 + n];
            uint32_t bh0, bh1, bl0, bl1;
            bh0 = packsplit(v00, v01, bl0);
            bh1 = packsplit(v10, v11, bl1);
            *reinterpret_cast<uint4*>(&Vl[((nf*2+ch)*32+ln)*4]) = make_uint4(bh0,bh1,bl0,bl1);
        }
        __syncthreads();

        // scores: S(64x32) = Q(64x64) . K^T, 3-limb MMA; store scaled to Ps
        {
            float s[4] = {0.f, 0.f, 0.f, 0.f};
            #pragma unroll
            for (int ch = 0; ch < 4; ++ch) {
                uint32_t ah[4], al[4];
                *reinterpret_cast<uint4*>(ah) = *reinterpret_cast<const uint4*>(&Qh[((mf*4+ch)*32+lane)*4]);
                *reinterpret_cast<uint4*>(al) = *reinterpret_cast<const uint4*>(&Ql[((mf*4+ch)*32+lane)*4]);
                uint4 q4 = *reinterpret_cast<const uint4*>(&Kl[((nfS*4+ch)*32+lane)*4]);
                uint32_t bh2[2] = {q4.x, q4.y};
                uint32_t bl2[2] = {q4.z, q4.w};
                mma16(s, al, bh2);
                mma16(s, ah, bl2);
                mma16(s, ah, bh2);
            }
            const int q0 = mf*16 + (lane >> 2);
            const int col = nfS*8 + (lane & 3)*2;
            *reinterpret_cast<float2*>(&Ps[q0*36 + col])     = make_float2(s[0]*0.125f, s[1]*0.125f);
            *reinterpret_cast<float2*>(&Ps[(q0+8)*36 + col]) = make_float2(s[2]*0.125f, s[3]*0.125f);
        }
        __syncthreads();

        // parallel online softmax (8 lanes per q, q < 50)
        {
            const int q = (t < 400) ? (t >> 3) : 49;
            const int g = t & 7;
            float4 p4 = *reinterpret_cast<const float4*>(&Ps[q*36 + g*4]);
            float lm = fmaxf(fmaxf(p4.x, p4.y), fmaxf(p4.z, p4.w));
            #pragma unroll
            for (int oo = 1; oo < 8; oo <<= 1)
                lm = fmaxf(lm, __shfl_xor_sync(0xffffffffu, lm, oo, 8));
            const float mold = m_s[q];
            const float nm = fmaxf(mold, lm);
            p4.x = __expf(p4.x - nm);
            p4.y = __expf(p4.y - nm);
            p4.z = __expf(p4.z - nm);
            p4.w = __expf(p4.w - nm);
            float lsum = p4.x + p4.y + p4.z + p4.w;
            #pragma unroll
            for (int oo = 1; oo < 8; oo <<= 1)
                lsum += __shfl_xor_sync(0xffffffffu, lsum, oo, 8);
            if (t < 400) {
                *reinterpret_cast<float4*>(&Ps[q*36 + g*4]) = p4;
                if (g == 0) {
                    float cc = __expf(mold - nm);
                    c_s[q] = cc;
                    l_s[q] = l_s[q]*cc + lsum;
                    m_s[q] = nm;
                }
            }
        }
        __syncthreads();

        // PV: ctx(64x64) += P(64x32) . V(32x64), 3-limb, acc in fragments
        {
            const int ro = mf*16 + (lane >> 2);
            const float c0 = c_s[ro], c1 = c_s[ro + 8];
            #pragma unroll
            for (int j = 0; j < 2; ++j) {
                o[j][0] *= c0; o[j][1] *= c0;
                o[j][2] *= c1; o[j][3] *= c1;
            }
            #pragma unroll
            for (int ch = 0; ch < 2; ++ch) {
                const int k0 = ch*16 + 2*(lane & 3);
                float2 p00 = *reinterpret_cast<const float2*>(&Ps[ro*36 + k0]);
                float2 p10 = *reinterpret_cast<const float2*>(&Ps[(ro+8)*36 + k0]);
                float2 p01 = *reinterpret_cast<const float2*>(&Ps[ro*36 + k0 + 8]);
                float2 p11 = *reinterpret_cast<const float2*>(&Ps[(ro+8)*36 + k0 + 8]);
                uint32_t ah[4], al[4];
                ah[0] = packsplit(p00.x, p00.y, al[0]);
                ah[1] = packsplit(p10.x, p10.y, al[1]);
                ah[2] = packsplit(p01.x, p01.y, al[2]);
                ah[3] = packsplit(p11.x, p11.y, al[3]);
                #pragma unroll
                for (int j = 0; j < 2; ++j) {
                    uint4 q4 = *reinterpret_cast<const uint4*>(&Vl[(((nf0+j)*2+ch)*32+lane)*4]);
                    uint32_t bh2[2] = {q4.x, q4.y};
                    uint32_t bl2[2] = {q4.z, q4.w};
                    mma16(o[j], al, bh2);
                    mma16(o[j], ah, bl2);
                    mma16(o[j], ah, bh2);
                }
            }
        }
    }

    // epilogue: write ctx fragments + softmax stats
    {
        const int ro = mf*16 + (lane >> 2);
        #pragma unroll
        for (int j = 0; j < 2; ++j) {
            const int d = (nf0+j)*8 + (lane & 3)*2;
            if (ro < Uv)
                *reinterpret_cast<float2*>(&g_pctx[(size_t)((bh*SPLIT+sp)*Uv + ro)*DKv + d])
                    = make_float2(o[j][0], o[j][1]);
            if (ro + 8 < Uv)
                *reinterpret_cast<float2*>(&g_pctx[(size_t)((bh*SPLIT+sp)*Uv + ro + 8)*DKv + d])
                    = make_float2(o[j][2], o[j][3]);
        }
    }
    if (t < Uv) {
        g_pm[(bh*SPLIT + sp)*Uv + t] = m_s[t];
        g_pl[(bh*SPLIT + sp)*Uv + t] = l_s[t];
    }
}

// ---------------- kernel 6: combine split partials ---------------------------
__global__ __launch_bounds__(64) void attn_combine_kernel(){
    const int i = blockIdx.x;
    const int q = i % Uv, bh = i / Uv;
    __shared__ float w[SPLIT];
    __shared__ float inv;
    if (threadIdx.x == 0) {
        float M = -1e30f;
        for (int s = 0; s < SPLIT; ++s) M = fmaxf(M, g_pm[(bh*SPLIT+s)*Uv + q]);
        float tot = 0.f;
        for (int s = 0; s < SPLIT; ++s) {
            float e = __expf(g_pm[(bh*SPLIT+s)*Uv + q] - M);
            w[s] = e;
            tot += g_pl[(bh*SPLIT+s)*Uv + q] * e;
        }
        inv = 1.0f / tot;
    }
    __syncthreads();
    const int d = threadIdx.x;
    float c = 0.f;
    for (int s = 0; s < SPLIT; ++s)
        c += g_pctx[(size_t)((bh*SPLIT+s)*Uv + q)*DKv + d] * w[s];
    g_ctx[(size_t)i*DKv + d] = c * inv;
}

// ---------------- kernel 7: base output row per batch ------------------------
__global__ __launch_bounds__(256) void base_kernel(const float* __restrict__ Wo,
                                                   const float* __restrict__ bo){
    const int b = blockIdx.y;
    const int warp = threadIdx.x >> 5, lane = threadIdx.x & 31;
    const int j = blockIdx.x*8 + warp;
    float s = 0.f;
    for (int d0 = lane; d0 < Dm; d0 += 32)
        s += g_vsum[b*Dm + d0] * Wo[(size_t)j*Dm + d0];
    #pragma unroll
    for (int o = 16; o; o >>= 1) s += __shfl_down_sync(0xffffffffu, s, o);
    if (lane == 0) g_base[b*Dm + j] = s*(1.0f/Lv) + bo[j];
}

// ---------------- kernel 8: broadcast base rows into output -------------------
__global__ void fill_kernel(float* __restrict__ out){
    const int i = blockIdx.x*blockDim.x + threadIdx.x;
    const int b  = i >> 21;
    const int j4 = i & 255;
    float4 v = *reinterpret_cast<const float4*>(&g_base[b*Dm + j4*4]);
    reinterpret_cast<float4*>(out)[i] = v;
}

// ---------------- kernel 9: rank-64 corrections (Wo read once per block) -----
__global__ __launch_bounds__(256) void corr_kernel(const float* __restrict__ Wo,
                                                   float* __restrict__ out){
    const int bh = blockIdx.y;
    const int b = bh / Hh, h = bh % Hh;
    const int j = blockIdx.x*256 + threadIdx.x;
    const int t = threadIdx.x;

    __shared__ float delta[Uv][DKv];
    __shared__ int   ls[Uv];

    if (t < Uv) ls[t] = g_top[bh*Uv + t];
    for (int i = t; i < Uv*DKv; i += 256) {
        const int u = i >> 6, dd = i & 63;
        delta[u][dd] = g_ctx[(size_t)(bh*Uv + u)*DKv + dd]
                     - g_vsum[b*Dm + h*DKv + dd]*(1.0f/Lv);
    }
    __syncthreads();

    float4 w[16];
    const float4* wr = reinterpret_cast<const float4*>(Wo + (size_t)j*Dm + h*DKv);
    #pragma unroll
    for (int dd = 0; dd < 16; ++dd) w[dd] = wr[dd];

    #pragma unroll 2
    for (int u = 0; u < Uv; ++u) {
        float s = 0.f;
        #pragma unroll
        for (int dd = 0; dd < 16; ++dd) {
            s += delta[u][dd*4+0]*w[dd].x + delta[u][dd*4+1]*w[dd].y
               + delta[u][dd*4+2]*w[dd].z + delta[u][dd*4+3]*w[dd].w;
        }
        atomicAdd(&out[(size_t)(b*Lv + ls[u])*Dm + j], s);
    }
}

// ---------------- launch ------------------------------------------------------
extern "C" void kernel_launch(void* const* d_in, const int* in_sizes, int n_in,
                              void* d_out, int out_size)
{
    const float* x    = (const float*)d_in[0];
    const float* Wq   = (const float*)d_in[1];
    const float* bq   = (const float*)d_in[2];
    const float* Wk   = (const float*)d_in[3];
    const float* bk   = (const float*)d_in[4];
    const float* Wv   = (const float*)d_in[5];
    const float* bv   = (const float*)d_in[6];
    const float* Wo   = (const float*)d_in[7];
    const float* bo   = (const float*)d_in[8];
    const int*   idxk = (const int*)d_in[9];
    float* out = (float*)d_out;

    cudaFuncSetAttribute(qkv_f16_kernel,
                         cudaFuncAttributeMaxDynamicSharedMemorySize, 65536);
    cudaFuncSetAttribute(attn_partial_kernel,
                         cudaFuncAttributeMaxDynamicSharedMemorySize, 94208);

    split_x_kernel<<<(2048*64*32)/256, 256>>>(x);
    split_w_kernel<<<(3*128*64*32)/256, 256>>>(Wq, Wk, Wv);
    qkv_f16_kernel<<<dim3(Dm/128, BLv/128, 3), 256, 65536>>>(bq, bk, bv);
    m_tc_kernel<<<dim3(Lv/128, Hh, Bv), 256>>>(idxk);
    vsum_kernel<<<dim3(Dm/128, Lv/256, Bv), 128>>>();
    topk_kernel<<<Bv*Hh, 256>>>();
    attn_partial_kernel<<<dim3(Bv*Hh, SPLIT), 512, 94208>>>();
    attn_combine_kernel<<<Bv*Hh*Uv, 64>>>();
    base_kernel<<<dim3(Dm/8, Bv), 256>>>(Wo, bo);
    fill_kernel<<<(BLv*Dm/4)/256, 256>>>(out);
    corr_kernel<<<dim3(4, Bv*Hh), 256>>>(Wo, out);
}